// round 1
// baseline (speedup 1.0000x reference)
#include <cuda_runtime.h>
#include <cuda_bf16.h>

// Problem constants
#define BB 32
#define TT 400
#define EE 1024
#define DD 1024
#define VV 5000
#define LL 100
#define L1 101
#define SOS_ID 4999
#define NEGBIG -1e30f

// ----------------------------------------------------------------------------
// Scratch (device globals — no dynamic allocation allowed)
// ----------------------------------------------------------------------------
__device__ __align__(16) float g_pre[BB * TT * DD];        // tanh(hs @ Wenc^T)  52.4MB
__device__ __align__(16) float g_Wc0[4096 * 3072];         // [W_ih0 | W_hh0]    50.3MB
__device__ __align__(16) float g_Wc1[4096 * 2048];         // [W_ih1 | W_hh1]    33.6MB
__device__ __align__(16) float g_bs0[4096];
__device__ __align__(16) float g_bs1[4096];
__device__ __align__(16) float g_xz0[BB * 3072];           // [ey | att_c | z0]
__device__ __align__(16) float g_in01[BB * 2048];          // [z0_new | z1_prev]
__device__ __align__(16) float g_gates[BB * 4096];
__device__ __align__(16) float g_z0[BB * DD];
__device__ __align__(16) float g_c0[BB * DD];
__device__ __align__(16) float g_z1[BB * DD];
__device__ __align__(16) float g_c1[BB * DD];
__device__ __align__(16) float g_dq[BB * DD];
__device__ __align__(16) float g_e[BB * TT];
__device__ __align__(16) float g_zall[L1 * BB * 2048];     // [z1 | att_c] per step, 26.5MB
__device__ __align__(16) float g_yall[L1 * BB * VV];       // logits 64.6MB
__device__ float g_loss;
__device__ int g_i64;

__device__ __forceinline__ float sigm(float x) { return 1.0f / (1.0f + expf(-x)); }

__device__ __forceinline__ int read_ys(const void* ys, int i) {
    return g_i64 ? (int)((const long long*)ys)[i] : ((const int*)ys)[i];
}

// ----------------------------------------------------------------------------
// Init: zero state, sum biases, detect int64 ys, zero loss
// ----------------------------------------------------------------------------
__global__ void k_init(const float* __restrict__ bih0, const float* __restrict__ bhh0,
                       const float* __restrict__ bih1, const float* __restrict__ bhh1,
                       const void* __restrict__ ys) {
    int i = blockIdx.x * blockDim.x + threadIdx.x;
    int n = blockDim.x * gridDim.x;
    for (int j = i; j < BB * DD; j += n) {
        g_z0[j] = 0.f; g_c0[j] = 0.f; g_z1[j] = 0.f; g_c1[j] = 0.f;
    }
    for (int j = i; j < 4096; j += n) {
        g_bs0[j] = bih0[j] + bhh0[j];
        g_bs1[j] = bih1[j] + bhh1[j];
    }
    if (i == 0) {
        g_loss = 0.f;
        // int64 detection: if data is int64 (values < 2^31), every odd 32-bit
        // word of the first 32 values is 0. If int32, odd words are random
        // token ids in [0,4999) — all-zero probability ~0.
        const int* w = (const int*)ys;
        int f = 1;
        for (int j = 1; j < 64; j += 2) if (w[j] != 0) f = 0;
        g_i64 = f;
    }
}

// Concatenate LSTM weights: Wc0[r] = [W_ih0[r](2048) | W_hh0[r](1024)]
//                           Wc1[r] = [W_ih1[r](1024) | W_hh1[r](1024)]
__global__ void k_concat(const float* __restrict__ Wih0, const float* __restrict__ Whh0,
                         const float* __restrict__ Wih1, const float* __restrict__ Whh1) {
    long long i = (long long)blockIdx.x * blockDim.x + threadIdx.x;
    long long n = (long long)blockDim.x * gridDim.x;
    const long long N0 = 4096LL * 3072, N1 = 4096LL * 2048;
    for (long long j = i; j < N0; j += n) {
        int r = (int)(j / 3072), c = (int)(j % 3072);
        g_Wc0[j] = (c < 2048) ? Wih0[(long long)r * 2048 + c]
                              : Whh0[(long long)r * 1024 + (c - 2048)];
    }
    for (long long j = i; j < N1; j += n) {
        int r = (int)(j / 2048), c = (int)(j % 2048);
        g_Wc1[j] = (c < 1024) ? Wih1[(long long)r * 1024 + c]
                              : Whh1[(long long)r * 1024 + (c - 1024)];
    }
}

// ----------------------------------------------------------------------------
// Generic NT GEMM: C[M,N] = act(A[M,K] @ B[N,K]^T + bias[n])
// A,B row-major, K-contiguous. ACT: 0 = none, 1 = tanh.
// Requires K % BK == 0, 16B-aligned rows (K % 4 == 0).
// ----------------------------------------------------------------------------
template <int BM, int BN, int BK, int TM, int TN, int ACT>
__global__ void gemm_nt(const float* __restrict__ A, const float* __restrict__ B,
                        const float* __restrict__ bias, float* __restrict__ C,
                        int M, int N, int K) {
    constexpr int TX = BN / TN, TY = BM / TM, THREADS = TX * TY;
    __shared__ float As[BK][BM];
    __shared__ float Bs[BK][BN];
    const int tid = threadIdx.x;
    const int m0 = blockIdx.y * BM, n0 = blockIdx.x * BN;
    const int trow = (tid / TX) * TM, tcol = (tid % TX) * TN;

    float acc[TM][TN];
#pragma unroll
    for (int i = 0; i < TM; i++)
#pragma unroll
        for (int j = 0; j < TN; j++) acc[i][j] = 0.f;

    constexpr int AV = BM * BK / (4 * THREADS);
    constexpr int BV = BN * BK / (4 * THREADS);

    for (int k0 = 0; k0 < K; k0 += BK) {
#pragma unroll
        for (int v = 0; v < AV; v++) {
            int idx = (tid + v * THREADS) * 4;
            int r = idx / BK, kk = idx % BK;
            float4 val = make_float4(0.f, 0.f, 0.f, 0.f);
            if (m0 + r < M)
                val = *(const float4*)(A + (long long)(m0 + r) * K + k0 + kk);
            As[kk + 0][r] = val.x; As[kk + 1][r] = val.y;
            As[kk + 2][r] = val.z; As[kk + 3][r] = val.w;
        }
#pragma unroll
        for (int v = 0; v < BV; v++) {
            int idx = (tid + v * THREADS) * 4;
            int r = idx / BK, kk = idx % BK;
            float4 val = make_float4(0.f, 0.f, 0.f, 0.f);
            if (n0 + r < N)
                val = *(const float4*)(B + (long long)(n0 + r) * K + k0 + kk);
            Bs[kk + 0][r] = val.x; Bs[kk + 1][r] = val.y;
            Bs[kk + 2][r] = val.z; Bs[kk + 3][r] = val.w;
        }
        __syncthreads();
#pragma unroll
        for (int kk = 0; kk < BK; kk++) {
            float a[TM], b[TN];
#pragma unroll
            for (int i = 0; i < TM; i++) a[i] = As[kk][trow + i];
#pragma unroll
            for (int j = 0; j < TN; j++) b[j] = Bs[kk][tcol + j];
#pragma unroll
            for (int i = 0; i < TM; i++)
#pragma unroll
                for (int j = 0; j < TN; j++) acc[i][j] = fmaf(a[i], b[j], acc[i][j]);
        }
        __syncthreads();
    }

#pragma unroll
    for (int i = 0; i < TM; i++) {
        int m = m0 + trow + i;
        if (m >= M) continue;
#pragma unroll
        for (int j = 0; j < TN; j++) {
            int n = n0 + tcol + j;
            if (n >= N) continue;
            float v = acc[i][j] + bias[n];
            if (ACT == 1) v = tanhf(v);
            C[(long long)m * N + n] = v;
        }
    }
}

// ----------------------------------------------------------------------------
// Per-step: embedding gather + z0 copy into xz0
// ----------------------------------------------------------------------------
__global__ void k_misc(const float* __restrict__ embed, const void* __restrict__ ys, int step) {
    int b = blockIdx.x;
    int idx = SOS_ID;
    if (step != 0) idx = read_ys(ys, b * LL + step - 1);
    const float* erow = embed + (long long)idx * DD;
    for (int j = threadIdx.x; j < DD; j += blockDim.x) {
        g_xz0[b * 3072 + j] = erow[j];
        g_xz0[b * 3072 + 2048 + j] = g_z0[b * DD + j];
    }
}

// e[b,t] = masked(2 * dot(pre_enc[b,t,:], dq[b,:]))
__global__ void k_attn_e(const int* __restrict__ hlens) {
    __shared__ float dqs[DD];
    int b = blockIdx.y;
    for (int j = threadIdx.x; j < DD; j += blockDim.x) dqs[j] = g_dq[b * DD + j];
    __syncthreads();
    int warp = threadIdx.x / 32, lane = threadIdx.x % 32;
    int hl = hlens[b];
#pragma unroll
    for (int r = 0; r < 2; r++) {
        int t = blockIdx.x * 16 + warp * 2 + r;
        const float* p = g_pre + (long long)(b * TT + t) * DD;
        float s = 0.f;
#pragma unroll
        for (int i = 0; i < 32; i++) s = fmaf(p[lane + 32 * i], dqs[lane + 32 * i], s);
#pragma unroll
        for (int off = 16; off > 0; off >>= 1) s += __shfl_xor_sync(0xffffffffu, s, off);
        if (lane == 0) g_e[b * TT + t] = (t < hl) ? 2.f * s : NEGBIG;
    }
}

// softmax(e) then att_c[b,:] = sum_t w[t] * hs[b,t,:]; writes xz0 and z_all slots
__global__ void k_attn_c(const float* __restrict__ hs, int step) {
    __shared__ float ws[TT];
    __shared__ float red[128];
    int b = blockIdx.y;
    int tid = threadIdx.x;
    // max
    float lm = NEGBIG;
    for (int i = tid; i < TT; i += 128) lm = fmaxf(lm, g_e[b * TT + i]);
    red[tid] = lm; __syncthreads();
    for (int s = 64; s > 0; s >>= 1) { if (tid < s) red[tid] = fmaxf(red[tid], red[tid + s]); __syncthreads(); }
    float m = red[0]; __syncthreads();
    // exp + sum
    float ls = 0.f;
    for (int i = tid; i < TT; i += 128) { float w = expf(g_e[b * TT + i] - m); ws[i] = w; ls += w; }
    red[tid] = ls; __syncthreads();
    for (int s = 64; s > 0; s >>= 1) { if (tid < s) red[tid] += red[tid + s]; __syncthreads(); }
    float S = red[0];
    // weighted sum over t
    int col = blockIdx.x * 128 + tid;
    const float* hp = hs + (long long)b * TT * EE + col;
    float acc = 0.f;
#pragma unroll 4
    for (int t = 0; t < TT; t++) acc = fmaf(ws[t], hp[(long long)t * EE], acc);
    float v = acc / S;
    g_xz0[b * 3072 + 1024 + col] = v;
    g_zall[(long long)(step * BB + b) * 2048 + 1024 + col] = v;
}

__global__ void k_lstm0() {
    int id = blockIdx.x * blockDim.x + threadIdx.x;   // BB*DD
    int b = id >> 10, d = id & 1023;
    const float* g = g_gates + b * 4096;
    float gi = sigm(g[d]);
    float gf = sigm(g[1024 + d]);
    float gg = tanhf(g[2048 + d]);
    float go = sigm(g[3072 + d]);
    float c = gf * g_c0[id] + gi * gg;
    float h = go * tanhf(c);
    g_c0[id] = c; g_z0[id] = h;
    g_in01[b * 2048 + d] = h;
    g_in01[b * 2048 + 1024 + d] = g_z1[id];
}

__global__ void k_lstm1(int step) {
    int id = blockIdx.x * blockDim.x + threadIdx.x;
    int b = id >> 10, d = id & 1023;
    const float* g = g_gates + b * 4096;
    float gi = sigm(g[d]);
    float gf = sigm(g[1024 + d]);
    float gg = tanhf(g[2048 + d]);
    float go = sigm(g[3072 + d]);
    float c = gf * g_c1[id] + gi * gg;
    float h = go * tanhf(c);
    g_c1[id] = c; g_z1[id] = h;
    g_zall[(long long)(step * BB + b) * 2048 + d] = h;
}

// CE over each of the 3232 logit rows: logsumexp - logit[target]
__global__ void k_ce(const void* __restrict__ ys) {
    int r = blockIdx.x;
    int l = r / BB, b = r % BB;
    const float* y = g_yall + (long long)r * VV;
    __shared__ float red[256];
    int tid = threadIdx.x;
    float lm = NEGBIG;
    for (int v = tid; v < VV; v += 256) lm = fmaxf(lm, y[v]);
    red[tid] = lm; __syncthreads();
    for (int s = 128; s > 0; s >>= 1) { if (tid < s) red[tid] = fmaxf(red[tid], red[tid + s]); __syncthreads(); }
    float m = red[0]; __syncthreads();
    float ls = 0.f;
    for (int v = tid; v < VV; v += 256) ls += expf(y[v] - m);
    red[tid] = ls; __syncthreads();
    for (int s = 128; s > 0; s >>= 1) { if (tid < s) red[tid] += red[tid + s]; __syncthreads(); }
    if (tid == 0) {
        int tgt = (l < LL) ? read_ys(ys, b * LL + l) : SOS_ID;  // EOS == SOS == 4999
        float ce = logf(red[0]) + m - y[tgt];
        atomicAdd(&g_loss, ce);
    }
}

__global__ void k_fin(float* out) {
    out[0] = g_loss * (100.0f / (float)(L1 * BB));
}

// ----------------------------------------------------------------------------
// Launch
// ----------------------------------------------------------------------------
extern "C" void kernel_launch(void* const* d_in, const int* in_sizes, int n_in,
                              void* d_out, int out_size) {
    const float* hs    = (const float*)d_in[0];
    const float* embed = (const float*)d_in[1];
    const float* Wenc  = (const float*)d_in[2];
    const float* benc  = (const float*)d_in[3];
    const float* Wdec  = (const float*)d_in[4];
    const float* bdec  = (const float*)d_in[5];
    const float* Wih0  = (const float*)d_in[6];
    const float* Whh0  = (const float*)d_in[7];
    const float* bih0  = (const float*)d_in[8];
    const float* bhh0  = (const float*)d_in[9];
    const float* Wih1  = (const float*)d_in[10];
    const float* Whh1  = (const float*)d_in[11];
    const float* bih1  = (const float*)d_in[12];
    const float* bhh1  = (const float*)d_in[13];
    const float* Wout  = (const float*)d_in[14];
    const float* bout  = (const float*)d_in[15];
    const int*   hlens = (const int*)d_in[16];
    const void*  ys    = (const void*)d_in[17];

    float *pre, *Wc0, *Wc1, *bs0, *bs1, *xz0, *in01, *gates, *z0, *dq, *zall, *yall;
    cudaGetSymbolAddress((void**)&pre,   g_pre);
    cudaGetSymbolAddress((void**)&Wc0,   g_Wc0);
    cudaGetSymbolAddress((void**)&Wc1,   g_Wc1);
    cudaGetSymbolAddress((void**)&bs0,   g_bs0);
    cudaGetSymbolAddress((void**)&bs1,   g_bs1);
    cudaGetSymbolAddress((void**)&xz0,   g_xz0);
    cudaGetSymbolAddress((void**)&in01,  g_in01);
    cudaGetSymbolAddress((void**)&gates, g_gates);
    cudaGetSymbolAddress((void**)&z0,    g_z0);
    cudaGetSymbolAddress((void**)&dq,    g_dq);
    cudaGetSymbolAddress((void**)&zall,  g_zall);
    cudaGetSymbolAddress((void**)&yall,  g_yall);

    k_init<<<128, 256>>>(bih0, bhh0, bih1, bhh1, ys);
    k_concat<<<512, 256>>>(Wih0, Whh0, Wih1, Whh1);

    // pre_enc = tanh(hs @ Wenc^T + benc)  [12800 x 1024], K=1024
    {
        dim3 grid(DD / 128, (BB * TT) / 128);
        gemm_nt<128, 128, 16, 8, 8, 1><<<grid, 256>>>(hs, Wenc, benc, pre, BB * TT, DD, EE);
    }

    for (int s = 0; s < L1; s++) {
        k_misc<<<BB, 256>>>(embed, ys, s);
        // dq = tanh(z0 @ Wdec^T + bdec)  [32 x 1024], K=1024
        gemm_nt<32, 32, 32, 2, 2, 1><<<dim3(DD / 32, 1), 256>>>(z0, Wdec, bdec, dq, BB, DD, DD);
        k_attn_e<<<dim3(TT / 16, BB), 256>>>(hlens);
        k_attn_c<<<dim3(EE / 128, BB), 128>>>(hs, s);
        // gates = xz0 @ Wc0^T + bs0  [32 x 4096], K=3072
        gemm_nt<32, 32, 32, 2, 2, 0><<<dim3(4096 / 32, 1), 256>>>(xz0, Wc0, bs0, gates, BB, 4096, 3072);
        k_lstm0<<<BB * DD / 256, 256>>>();
        // gates = in01 @ Wc1^T + bs1  [32 x 4096], K=2048
        gemm_nt<32, 32, 32, 2, 2, 0><<<dim3(4096 / 32, 1), 256>>>(in01, Wc1, bs1, gates, BB, 4096, 2048);
        k_lstm1<<<BB * DD / 256, 256>>>(s);
    }

    // y_all = z_all @ Wout^T + bout  [3232 x 5000], K=2048
    {
        dim3 grid((VV + 127) / 128, (L1 * BB + 127) / 128);
        gemm_nt<128, 128, 16, 8, 8, 0><<<grid, 256>>>(zall, Wout, bout, yall, L1 * BB, VV, 2048);
    }
    k_ce<<<L1 * BB, 256>>>(ys);
    k_fin<<<1, 1>>>((float*)d_out);
}

// round 2
// speedup vs baseline: 2.0740x; 2.0740x over previous
#include <cuda_runtime.h>
#include <cuda_bf16.h>

#define BB 32
#define TT 400
#define DD 1024
#define VV 5000
#define LL 100
#define L1 101
#define NEGBIG -1e30f

// ----------------------------------------------------------------------------
// Device-global scratch (no dynamic allocation allowed)
// ----------------------------------------------------------------------------
__device__ __align__(16) __nv_bfloat16 g_hsb [BB * TT * DD];      // 26MB
__device__ __align__(16) __nv_bfloat16 g_preb[BB * TT * DD];      // 26MB
__device__ __align__(16) __nv_bfloat16 g_embb[5000 * DD];         // 10MB
__device__ __align__(16) __nv_bfloat16 g_Wencb[DD * DD];
__device__ __align__(16) __nv_bfloat16 g_Wdecb[DD * DD];
__device__ __align__(16) __nv_bfloat16 g_Woutb[VV * 2048];        // 20MB
__device__ __align__(16) __nv_bfloat16 g_Wc0r[4096 * 3072];       // 25MB (gate-interleaved)
__device__ __align__(16) __nv_bfloat16 g_Wc1r[4096 * 2048];       // 17MB
__device__ __align__(16) float g_bs0r[4096];
__device__ __align__(16) float g_bs1r[4096];
__device__ __align__(16) __nv_bfloat16 g_dqb[BB * DD];
__device__ __align__(16) __nv_bfloat16 g_attb[BB * DD];
__device__ __align__(16) __nv_bfloat16 g_z0b[BB * DD];
__device__ __align__(16) __nv_bfloat16 g_z1b[BB * DD];
__device__ __align__(16) float g_c0[BB * DD];
__device__ __align__(16) float g_c1[BB * DD];
__device__ __align__(16) float g_e[BB * TT];
__device__ __align__(16) __nv_bfloat16 g_zallb[L1 * BB * 2048];   // 13MB
__device__ __align__(16) float g_yall[(long long)L1 * BB * VV];   // 65MB
__device__ float g_loss;
__device__ int g_i64;

__device__ __forceinline__ float sigm(float x) { return 1.0f / (1.0f + expf(-x)); }

// ----------------------------------------------------------------------------
// Prep: zero states, reorder+sum biases (gate-interleaved), detect int64 ys
// ----------------------------------------------------------------------------
__global__ void k_prep0(const float* __restrict__ bih0, const float* __restrict__ bhh0,
                        const float* __restrict__ bih1, const float* __restrict__ bhh1,
                        const void* __restrict__ ys) {
    int i = blockIdx.x * blockDim.x + threadIdx.x;
    int n = gridDim.x * blockDim.x;
    __nv_bfloat16 z = __float2bfloat16(0.f);
    for (int j = i; j < BB * DD; j += n) {
        g_c0[j] = 0.f; g_c1[j] = 0.f; g_z0b[j] = z; g_z1b[j] = z;
    }
    for (int j = i; j < 4096; j += n) {
        int u = j >> 2, gate = j & 3;
        int orow = gate * 1024 + u;
        g_bs0r[j] = bih0[orow] + bhh0[orow];
        g_bs1r[j] = bih1[orow] + bhh1[orow];
    }
    if (i == 0) {
        g_loss = 0.f;
        const int* w = (const int*)ys;
        int f = 1;
        for (int j = 1; j < 64; j += 2) if (w[j] != 0) f = 0;
        g_i64 = f;
    }
}

__device__ __forceinline__ int read_ys(const void* ys, int i) {
    return g_i64 ? (int)((const long long*)ys)[i] : ((const int*)ys)[i];
}

// fp32 -> bf16 convert (vectorized by 2)
__global__ void k_cvt(const float* __restrict__ s, __nv_bfloat16* __restrict__ d, long long n2) {
    long long i = (long long)blockIdx.x * blockDim.x + threadIdx.x;
    long long stride = (long long)gridDim.x * blockDim.x;
    const float2* s2 = (const float2*)s;
    __nv_bfloat162* d2 = (__nv_bfloat162*)d;
    for (long long j = i; j < n2; j += stride) {
        float2 v = s2[j];
        d2[j] = __floats2bfloat162_rn(v.x, v.y);
    }
}

// Gate-interleaved LSTM weight reorder + bf16 convert.
// New row r = 4u+gate <- [W_ih[gate*1024+u] | W_hh[gate*1024+u]]
__global__ void k_reo0(const float* __restrict__ Wih, const float* __restrict__ Whh) {
    long long N = 4096LL * 3072;
    long long i = (long long)blockIdx.x * blockDim.x + threadIdx.x;
    long long stride = (long long)gridDim.x * blockDim.x;
    for (long long j = i; j < N; j += stride) {
        int r = (int)(j / 3072), c = (int)(j % 3072);
        int u = r >> 2, gate = r & 3;
        long long orow = gate * 1024 + u;
        float v = (c < 2048) ? Wih[orow * 2048 + c] : Whh[orow * 1024 + (c - 2048)];
        g_Wc0r[j] = __float2bfloat16(v);
    }
}
__global__ void k_reo1(const float* __restrict__ Wih, const float* __restrict__ Whh) {
    long long N = 4096LL * 2048;
    long long i = (long long)blockIdx.x * blockDim.x + threadIdx.x;
    long long stride = (long long)gridDim.x * blockDim.x;
    for (long long j = i; j < N; j += stride) {
        int r = (int)(j / 2048), c = (int)(j % 2048);
        int u = r >> 2, gate = r & 3;
        long long orow = gate * 1024 + u;
        float v = (c < 1024) ? Wih[orow * 1024 + c] : Whh[orow * 1024 + (c - 1024)];
        g_Wc1r[j] = __float2bfloat16(v);
    }
}

// ----------------------------------------------------------------------------
// HMMA building block: m16n8k16 bf16 -> f32
// ----------------------------------------------------------------------------
__device__ __forceinline__ void mma_bf16(float* d, const unsigned* a, const unsigned* b) {
    asm volatile(
        "mma.sync.aligned.m16n8k16.row.col.f32.bf16.bf16.f32 "
        "{%0,%1,%2,%3}, {%4,%5,%6,%7}, {%8,%9}, {%0,%1,%2,%3};\n"
        : "+f"(d[0]), "+f"(d[1]), "+f"(d[2]), "+f"(d[3])
        : "r"(a[0]), "r"(a[1]), "r"(a[2]), "r"(a[3]), "r"(b[0]), "r"(b[1]));
}

// ----------------------------------------------------------------------------
// Big GEMM: C[M,N] = A[M,K] @ B[N,K]^T (+bias), bf16 in, fp32 acc.
// BM=BN=128, BK=32; 8 warps (4m x 2n), warp tile 32x64.
// EPI 0: fp32 out + bias. EPI 1: tanh -> bf16 out + bias.
// ----------------------------------------------------------------------------
template <int EPI>
__global__ __launch_bounds__(256) void mma_big(
    const __nv_bfloat16* __restrict__ A, const __nv_bfloat16* __restrict__ B,
    const float* __restrict__ bias, float* __restrict__ Cf,
    __nv_bfloat16* __restrict__ Cb, int M, int N, int K)
{
    constexpr int BKP = 40;
    __shared__ __nv_bfloat16 As[128][BKP];
    __shared__ __nv_bfloat16 Bs[128][BKP];
    const int tid = threadIdx.x, lane = tid & 31, wid = tid >> 5;
    const int wm = wid >> 1, wn = wid & 1;
    const int m0 = blockIdx.y * 128, n0 = blockIdx.x * 128;
    const int g = lane >> 2, tg = lane & 3;

    float acc[2][8][4];
#pragma unroll
    for (int a = 0; a < 2; a++)
#pragma unroll
        for (int b = 0; b < 8; b++)
#pragma unroll
            for (int c = 0; c < 4; c++) acc[a][b][c] = 0.f;

    int ar[2], ac[2];
#pragma unroll
    for (int t = 0; t < 2; t++) { int s = tid + t * 256; ar[t] = s >> 2; ac[t] = (s & 3) * 8; }

    uint4 pa[2], pb[2];
#pragma unroll
    for (int t = 0; t < 2; t++) {
        int m = m0 + ar[t];
        pa[t] = (m < M) ? *(const uint4*)(A + (long long)m * K + ac[t]) : make_uint4(0, 0, 0, 0);
        int n = n0 + ar[t];
        pb[t] = (n < N) ? *(const uint4*)(B + (long long)n * K + ac[t]) : make_uint4(0, 0, 0, 0);
    }
#pragma unroll
    for (int t = 0; t < 2; t++) {
        *(uint2*)&As[ar[t]][ac[t]]     = make_uint2(pa[t].x, pa[t].y);
        *(uint2*)&As[ar[t]][ac[t] + 4] = make_uint2(pa[t].z, pa[t].w);
        *(uint2*)&Bs[ar[t]][ac[t]]     = make_uint2(pb[t].x, pb[t].y);
        *(uint2*)&Bs[ar[t]][ac[t] + 4] = make_uint2(pb[t].z, pb[t].w);
    }
    __syncthreads();

    const int niter = K >> 5;
    for (int it = 0; it < niter; it++) {
        if (it + 1 < niter) {
            int k0 = (it + 1) << 5;
#pragma unroll
            for (int t = 0; t < 2; t++) {
                int m = m0 + ar[t];
                pa[t] = (m < M) ? *(const uint4*)(A + (long long)m * K + k0 + ac[t]) : make_uint4(0, 0, 0, 0);
                int n = n0 + ar[t];
                pb[t] = (n < N) ? *(const uint4*)(B + (long long)n * K + k0 + ac[t]) : make_uint4(0, 0, 0, 0);
            }
        }
#pragma unroll
        for (int kt = 0; kt < 2; kt++) {
            const int c0 = kt * 16 + tg * 2;
            unsigned af[2][4];
#pragma unroll
            for (int mt = 0; mt < 2; mt++) {
                int r = wm * 32 + mt * 16 + g;
                af[mt][0] = *(const unsigned*)&As[r][c0];
                af[mt][1] = *(const unsigned*)&As[r + 8][c0];
                af[mt][2] = *(const unsigned*)&As[r][c0 + 8];
                af[mt][3] = *(const unsigned*)&As[r + 8][c0 + 8];
            }
#pragma unroll
            for (int nt = 0; nt < 8; nt++) {
                int n = wn * 64 + nt * 8 + g;
                unsigned bf[2];
                bf[0] = *(const unsigned*)&Bs[n][c0];
                bf[1] = *(const unsigned*)&Bs[n][c0 + 8];
                mma_bf16(acc[0][nt], af[0], bf);
                mma_bf16(acc[1][nt], af[1], bf);
            }
        }
        __syncthreads();
        if (it + 1 < niter) {
#pragma unroll
            for (int t = 0; t < 2; t++) {
                *(uint2*)&As[ar[t]][ac[t]]     = make_uint2(pa[t].x, pa[t].y);
                *(uint2*)&As[ar[t]][ac[t] + 4] = make_uint2(pa[t].z, pa[t].w);
                *(uint2*)&Bs[ar[t]][ac[t]]     = make_uint2(pb[t].x, pb[t].y);
                *(uint2*)&Bs[ar[t]][ac[t] + 4] = make_uint2(pb[t].z, pb[t].w);
            }
            __syncthreads();
        }
    }

#pragma unroll
    for (int mt = 0; mt < 2; mt++) {
#pragma unroll
        for (int nt = 0; nt < 8; nt++) {
            int r = m0 + wm * 32 + mt * 16 + g;
            int c = n0 + wn * 64 + nt * 8 + tg * 2;
            float* a = acc[mt][nt];
            if (EPI == 0) {
                float b0 = (c < N) ? bias[c] : 0.f;
                float b1 = (c + 1 < N) ? bias[c + 1] : 0.f;
                if (r < M) {
                    if (c < N)     Cf[(long long)r * N + c]     = a[0] + b0;
                    if (c + 1 < N) Cf[(long long)r * N + c + 1] = a[1] + b1;
                }
                if (r + 8 < M) {
                    if (c < N)     Cf[(long long)(r + 8) * N + c]     = a[2] + b0;
                    if (c + 1 < N) Cf[(long long)(r + 8) * N + c + 1] = a[3] + b1;
                }
            } else {
                float b0 = bias[c], b1 = bias[c + 1];
                __nv_bfloat162 v0 = __floats2bfloat162_rn(tanhf(a[0] + b0), tanhf(a[1] + b1));
                __nv_bfloat162 v1 = __floats2bfloat162_rn(tanhf(a[2] + b0), tanhf(a[3] + b1));
                *(__nv_bfloat162*)(Cb + (long long)r * N + c) = v0;
                *(__nv_bfloat162*)(Cb + (long long)(r + 8) * N + c) = v1;
            }
        }
    }
}

// ----------------------------------------------------------------------------
// Small GEMM: M=32, BN=64, BK=64; 8 warps, warp tile 32x8.
// ASRC: 0 = A0[M,K] plain; 1 = [embed-gather | attb | z0b]; 2 = [z0b | z1b]
// EPI:  1 = tanh -> bf16 out (stride 1024, dq)
//       2 = LSTM pointwise (gate-interleaved): cstate/hb/zall updates
// ----------------------------------------------------------------------------
template <int ASRC, int EPI>
__global__ __launch_bounds__(256) void mma_small(
    const __nv_bfloat16* __restrict__ A0, const __nv_bfloat16* __restrict__ A1,
    const __nv_bfloat16* __restrict__ A2, const __nv_bfloat16* __restrict__ B,
    const float* __restrict__ bias, __nv_bfloat16* __restrict__ outb,
    float* __restrict__ cstate, __nv_bfloat16* __restrict__ hb,
    __nv_bfloat16* __restrict__ zall, int K, int step, const void* __restrict__ ys)
{
    constexpr int BKP = 72;
    __shared__ __align__(16) char sraw[(32 + 64) * BKP * 2];
    __nv_bfloat16 (*As)[BKP] = (__nv_bfloat16(*)[BKP])sraw;
    __nv_bfloat16 (*Bs)[BKP] = (__nv_bfloat16(*)[BKP])(sraw + 32 * BKP * 2);

    const int tid = threadIdx.x, lane = tid & 31, wid = tid >> 5;
    const int n0 = blockIdx.x * 64;
    const int g = lane >> 2, tg = lane & 3;

    const int arow = tid >> 3, acol = (tid & 7) * 8;
    int br[2], bc[2];
#pragma unroll
    for (int t = 0; t < 2; t++) { int s = tid + t * 256; br[t] = s >> 3; bc[t] = (s & 7) * 8; }

    int tok = 4999;
    if (ASRC == 1 && step > 0) tok = read_ys(ys, arow * LL + step - 1);

    float acc[2][4];
#pragma unroll
    for (int a = 0; a < 2; a++)
#pragma unroll
        for (int c = 0; c < 4; c++) acc[a][c] = 0.f;

#define FETCH_A(kk)                                                                  \
    (ASRC == 0 ? *(const uint4*)(A0 + (long long)arow * K + (kk))                    \
     : ASRC == 1                                                                     \
         ? ((kk) < 1024 ? *(const uint4*)(A0 + (long long)tok * 1024 + (kk))         \
            : (kk) < 2048 ? *(const uint4*)(A1 + arow * 1024 + (kk) - 1024)          \
                          : *(const uint4*)(A2 + arow * 1024 + (kk) - 2048))         \
         : ((kk) < 1024 ? *(const uint4*)(A0 + arow * 1024 + (kk))                   \
                        : *(const uint4*)(A1 + arow * 1024 + (kk) - 1024)))

    uint4 pa = FETCH_A(acol);
    uint4 pb0 = *(const uint4*)(B + (long long)(n0 + br[0]) * K + bc[0]);
    uint4 pb1 = *(const uint4*)(B + (long long)(n0 + br[1]) * K + bc[1]);
    *(uint2*)&As[arow][acol]     = make_uint2(pa.x, pa.y);
    *(uint2*)&As[arow][acol + 4] = make_uint2(pa.z, pa.w);
    *(uint2*)&Bs[br[0]][bc[0]]     = make_uint2(pb0.x, pb0.y);
    *(uint2*)&Bs[br[0]][bc[0] + 4] = make_uint2(pb0.z, pb0.w);
    *(uint2*)&Bs[br[1]][bc[1]]     = make_uint2(pb1.x, pb1.y);
    *(uint2*)&Bs[br[1]][bc[1] + 4] = make_uint2(pb1.z, pb1.w);
    __syncthreads();

    const int niter = K >> 6;
    for (int it = 0; it < niter; it++) {
        if (it + 1 < niter) {
            int k0 = (it + 1) << 6;
            pa = FETCH_A(k0 + acol);
            pb0 = *(const uint4*)(B + (long long)(n0 + br[0]) * K + k0 + bc[0]);
            pb1 = *(const uint4*)(B + (long long)(n0 + br[1]) * K + k0 + bc[1]);
        }
#pragma unroll
        for (int kt = 0; kt < 4; kt++) {
            const int c0 = kt * 16 + tg * 2;
            unsigned af[2][4];
#pragma unroll
            for (int mt = 0; mt < 2; mt++) {
                int r = mt * 16 + g;
                af[mt][0] = *(const unsigned*)&As[r][c0];
                af[mt][1] = *(const unsigned*)&As[r + 8][c0];
                af[mt][2] = *(const unsigned*)&As[r][c0 + 8];
                af[mt][3] = *(const unsigned*)&As[r + 8][c0 + 8];
            }
            int n = wid * 8 + g;
            unsigned bf[2];
            bf[0] = *(const unsigned*)&Bs[n][c0];
            bf[1] = *(const unsigned*)&Bs[n][c0 + 8];
            mma_bf16(acc[0], af[0], bf);
            mma_bf16(acc[1], af[1], bf);
        }
        __syncthreads();
        if (it + 1 < niter) {
            *(uint2*)&As[arow][acol]     = make_uint2(pa.x, pa.y);
            *(uint2*)&As[arow][acol + 4] = make_uint2(pa.z, pa.w);
            *(uint2*)&Bs[br[0]][bc[0]]     = make_uint2(pb0.x, pb0.y);
            *(uint2*)&Bs[br[0]][bc[0] + 4] = make_uint2(pb0.z, pb0.w);
            *(uint2*)&Bs[br[1]][bc[1]]     = make_uint2(pb1.x, pb1.y);
            *(uint2*)&Bs[br[1]][bc[1] + 4] = make_uint2(pb1.z, pb1.w);
            __syncthreads();
        }
    }
#undef FETCH_A

    if (EPI == 1) {
#pragma unroll
        for (int mt = 0; mt < 2; mt++) {
            int r = mt * 16 + g;
            int c = n0 + wid * 8 + tg * 2;
            float b0 = bias[c], b1 = bias[c + 1];
            __nv_bfloat162 v0 = __floats2bfloat162_rn(tanhf(acc[mt][0] + b0), tanhf(acc[mt][1] + b1));
            __nv_bfloat162 v1 = __floats2bfloat162_rn(tanhf(acc[mt][2] + b0), tanhf(acc[mt][3] + b1));
            *(__nv_bfloat162*)(outb + r * 1024 + c) = v0;
            *(__nv_bfloat162*)(outb + (r + 8) * 1024 + c) = v1;
        }
    } else {
        float (*Gs)[64] = (float(*)[64])sraw;  // safe: synced after last compute
#pragma unroll
        for (int mt = 0; mt < 2; mt++) {
            int r = mt * 16 + g;
            int cl = wid * 8 + tg * 2;
            Gs[r][cl]         = acc[mt][0] + bias[n0 + cl];
            Gs[r][cl + 1]     = acc[mt][1] + bias[n0 + cl + 1];
            Gs[r + 8][cl]     = acc[mt][2] + bias[n0 + cl];
            Gs[r + 8][cl + 1] = acc[mt][3] + bias[n0 + cl + 1];
        }
        __syncthreads();
        for (int item = tid; item < 512; item += 256) {
            int b = item & 31, ul = item >> 5;
            float gi = Gs[b][4 * ul], gf = Gs[b][4 * ul + 1];
            float gg = Gs[b][4 * ul + 2], go = Gs[b][4 * ul + 3];
            int u = blockIdx.x * 16 + ul;
            int gid = b * 1024 + u;
            float c = sigm(gf) * cstate[gid] + sigm(gi) * tanhf(gg);
            float h = sigm(go) * tanhf(c);
            cstate[gid] = c;
            hb[gid] = __float2bfloat16(h);
            if (zall) zall[(long long)(step * 32 + b) * 2048 + u] = __float2bfloat16(h);
        }
    }
}

// ----------------------------------------------------------------------------
// Attention: e[b,t] = masked(2 * dot(pre[b,t,:], dq[b,:]))
// ----------------------------------------------------------------------------
__global__ void k_attn_e(const int* __restrict__ hlens) {
    __shared__ float2 dqs[512];
    int b = blockIdx.y;
    const __nv_bfloat162* d2 = (const __nv_bfloat162*)(g_dqb + b * DD);
    for (int j = threadIdx.x; j < 512; j += 256) {
        __nv_bfloat162 v = d2[j];
        dqs[j] = make_float2(__bfloat162float(v.x), __bfloat162float(v.y));
    }
    __syncthreads();
    int warp = threadIdx.x >> 5, lane = threadIdx.x & 31;
    int hl = hlens[b];
#pragma unroll
    for (int r = 0; r < 2; r++) {
        int t = blockIdx.x * 16 + warp * 2 + r;
        const __nv_bfloat162* p2 = (const __nv_bfloat162*)(g_preb + (long long)(b * TT + t) * DD);
        float s = 0.f;
#pragma unroll
        for (int i = 0; i < 16; i++) {
            __nv_bfloat162 a = p2[lane + 32 * i];
            float2 d = dqs[lane + 32 * i];
            s = fmaf(__bfloat162float(a.x), d.x, s);
            s = fmaf(__bfloat162float(a.y), d.y, s);
        }
#pragma unroll
        for (int off = 16; off > 0; off >>= 1) s += __shfl_xor_sync(0xffffffffu, s, off);
        if (lane == 0) g_e[b * TT + t] = (t < hl) ? 2.f * s : NEGBIG;
    }
}

// softmax(e) then att_c[b,col] = sum_t w[t]*hs[b,t,col]; writes attb + zallb
__global__ void k_attn_c(int step) {
    __shared__ float ws[TT];
    __shared__ float red[128];
    int b = blockIdx.y;
    int tid = threadIdx.x;
    float lm = NEGBIG;
    for (int i = tid; i < TT; i += 128) lm = fmaxf(lm, g_e[b * TT + i]);
    red[tid] = lm; __syncthreads();
    for (int s = 64; s > 0; s >>= 1) { if (tid < s) red[tid] = fmaxf(red[tid], red[tid + s]); __syncthreads(); }
    float m = red[0]; __syncthreads();
    float ls = 0.f;
    for (int i = tid; i < TT; i += 128) { float w = expf(g_e[b * TT + i] - m); ws[i] = w; ls += w; }
    red[tid] = ls; __syncthreads();
    for (int s = 64; s > 0; s >>= 1) { if (tid < s) red[tid] += red[tid + s]; __syncthreads(); }
    float S = red[0];
    int col = blockIdx.x * 128 + tid;
    const __nv_bfloat16* hp = g_hsb + (long long)b * TT * DD + col;
    float acc = 0.f;
#pragma unroll 4
    for (int t = 0; t < TT; t++) acc = fmaf(ws[t], __bfloat162float(hp[(long long)t * DD]), acc);
    __nv_bfloat16 v = __float2bfloat16(acc / S);
    g_attb[b * DD + col] = v;
    g_zallb[(long long)(step * 32 + b) * 2048 + 1024 + col] = v;
}

// ----------------------------------------------------------------------------
// CE over 3232 logit rows
// ----------------------------------------------------------------------------
__global__ void k_ce(const void* __restrict__ ys) {
    int r = blockIdx.x;
    int l = r / BB, b = r % BB;
    const float* y = g_yall + (long long)r * VV;
    __shared__ float red[256];
    int tid = threadIdx.x;
    float lm = NEGBIG;
    for (int v = tid; v < VV; v += 256) lm = fmaxf(lm, y[v]);
    red[tid] = lm; __syncthreads();
    for (int s = 128; s > 0; s >>= 1) { if (tid < s) red[tid] = fmaxf(red[tid], red[tid + s]); __syncthreads(); }
    float m = red[0]; __syncthreads();
    float ls = 0.f;
    for (int v = tid; v < VV; v += 256) ls += expf(y[v] - m);
    red[tid] = ls; __syncthreads();
    for (int s = 128; s > 0; s >>= 1) { if (tid < s) red[tid] += red[tid + s]; __syncthreads(); }
    if (tid == 0) {
        int tgt = (l < LL) ? read_ys(ys, b * LL + l) : 4999;
        float ce = logf(red[0]) + m - y[tgt];
        atomicAdd(&g_loss, ce);
    }
}

__global__ void k_fin(float* out) {
    out[0] = g_loss * ((float)LL / (float)(L1 * BB));
}

// ----------------------------------------------------------------------------
// Launch
// ----------------------------------------------------------------------------
extern "C" void kernel_launch(void* const* d_in, const int* in_sizes, int n_in,
                              void* d_out, int out_size) {
    const float* hs    = (const float*)d_in[0];
    const float* embed = (const float*)d_in[1];
    const float* Wenc  = (const float*)d_in[2];
    const float* benc  = (const float*)d_in[3];
    const float* Wdec  = (const float*)d_in[4];
    const float* bdec  = (const float*)d_in[5];
    const float* Wih0  = (const float*)d_in[6];
    const float* Whh0  = (const float*)d_in[7];
    const float* bih0  = (const float*)d_in[8];
    const float* bhh0  = (const float*)d_in[9];
    const float* Wih1  = (const float*)d_in[10];
    const float* Whh1  = (const float*)d_in[11];
    const float* bih1  = (const float*)d_in[12];
    const float* bhh1  = (const float*)d_in[13];
    const float* Wout  = (const float*)d_in[14];
    const float* bout  = (const float*)d_in[15];
    const int*   hlens = (const int*)d_in[16];
    const void*  ys    = (const void*)d_in[17];

    __nv_bfloat16 *hsb, *preb, *embb, *Wencb, *Wdecb, *Woutb, *Wc0r, *Wc1r;
    __nv_bfloat16 *dqb, *attb, *z0b, *z1b, *zallb;
    float *bs0r, *bs1r, *c0, *c1, *yall;
    cudaGetSymbolAddress((void**)&hsb,   g_hsb);
    cudaGetSymbolAddress((void**)&preb,  g_preb);
    cudaGetSymbolAddress((void**)&embb,  g_embb);
    cudaGetSymbolAddress((void**)&Wencb, g_Wencb);
    cudaGetSymbolAddress((void**)&Wdecb, g_Wdecb);
    cudaGetSymbolAddress((void**)&Woutb, g_Woutb);
    cudaGetSymbolAddress((void**)&Wc0r,  g_Wc0r);
    cudaGetSymbolAddress((void**)&Wc1r,  g_Wc1r);
    cudaGetSymbolAddress((void**)&bs0r,  g_bs0r);
    cudaGetSymbolAddress((void**)&bs1r,  g_bs1r);
    cudaGetSymbolAddress((void**)&dqb,   g_dqb);
    cudaGetSymbolAddress((void**)&attb,  g_attb);
    cudaGetSymbolAddress((void**)&z0b,   g_z0b);
    cudaGetSymbolAddress((void**)&z1b,   g_z1b);
    cudaGetSymbolAddress((void**)&c0,    g_c0);
    cudaGetSymbolAddress((void**)&c1,    g_c1);
    cudaGetSymbolAddress((void**)&zallb, g_zallb);
    cudaGetSymbolAddress((void**)&yall,  g_yall);

    k_prep0<<<64, 256>>>(bih0, bhh0, bih1, bhh1, ys);
    k_cvt<<<512, 256>>>(hs, hsb, (long long)BB * TT * DD / 2);
    k_cvt<<<256, 256>>>(embed, embb, 5000LL * DD / 2);
    k_cvt<<<128, 256>>>(Wenc, Wencb, (long long)DD * DD / 2);
    k_cvt<<<128, 256>>>(Wdec, Wdecb, (long long)DD * DD / 2);
    k_cvt<<<512, 256>>>(Wout, Woutb, (long long)VV * 2048 / 2);
    k_reo0<<<1024, 256>>>(Wih0, Whh0);
    k_reo1<<<1024, 256>>>(Wih1, Whh1);

    // pre_enc = tanh(hs @ Wenc^T + benc) -> bf16   [12800 x 1024]
    mma_big<1><<<dim3(DD / 128, BB * TT / 128), 256>>>(hsb, Wencb, benc, nullptr, preb,
                                                       BB * TT, DD, DD);

    for (int s = 0; s < L1; s++) {
        // dq = tanh(z0 @ Wdec^T + bdec) -> bf16
        mma_small<0, 1><<<16, 256>>>(z0b, nullptr, nullptr, Wdecb, bdec, dqb,
                                     nullptr, nullptr, nullptr, DD, s, ys);
        k_attn_e<<<dim3(TT / 16, BB), 256>>>(hlens);
        k_attn_c<<<dim3(DD / 128, BB), 128>>>(s);
        // layer 0: gates = [ey|att|z0] @ Wc0r^T + bs0r, fused LSTM pointwise
        mma_small<1, 2><<<64, 256>>>(embb, attb, z0b, Wc0r, bs0r, nullptr,
                                     c0, z0b, nullptr, 3072, s, ys);
        // layer 1: gates = [z0|z1] @ Wc1r^T + bs1r, fused LSTM pointwise + zall
        mma_small<2, 2><<<64, 256>>>(z0b, z1b, nullptr, Wc1r, bs1r, nullptr,
                                     c1, z1b, zallb, 2048, s, ys);
    }

    // y_all = zall @ Wout^T + bout  [3232 x 5000] fp32
    mma_big<0><<<dim3((VV + 127) / 128, (L1 * BB + 127) / 128), 256>>>(
        zallb, Woutb, bout, yall, nullptr, L1 * BB, VV, 2048);

    k_ce<<<L1 * BB, 256>>>(ys);
    k_fin<<<1, 1>>>((float*)d_out);
}

// round 3
// speedup vs baseline: 3.1662x; 1.5266x over previous
#include <cuda_runtime.h>
#include <cuda_bf16.h>

#define BB 32
#define TT 400
#define DD 1024
#define VV 5000
#define LL 100
#define L1 101
#define NEGBIG -1e30f
#define NBLK 148

// ----------------------------------------------------------------------------
// Device-global scratch
// ----------------------------------------------------------------------------
__device__ __align__(16) __nv_bfloat16 g_hsb [BB * TT * DD];
__device__ __align__(16) __nv_bfloat16 g_preb[BB * TT * DD];
__device__ __align__(16) __nv_bfloat16 g_embb[5000 * DD];
__device__ __align__(16) __nv_bfloat16 g_Wencb[DD * DD];
__device__ __align__(16) __nv_bfloat16 g_Wdecb[DD * DD];
__device__ __align__(16) __nv_bfloat16 g_Woutb[VV * 2048];
__device__ __align__(16) __nv_bfloat16 g_Wc0r[4096 * 3072];
__device__ __align__(16) __nv_bfloat16 g_Wc1r[4096 * 2048];
__device__ __align__(16) float g_bs0r[4096];
__device__ __align__(16) float g_bs1r[4096];
__device__ __align__(16) __nv_bfloat16 g_dqb[BB * DD];
__device__ __align__(16) __nv_bfloat16 g_attb[BB * DD];
__device__ __align__(16) __nv_bfloat16 g_z0s[2][BB * DD];
__device__ __align__(16) __nv_bfloat16 g_z1s[2][BB * DD];
__device__ __align__(16) float g_c0[BB * DD];
__device__ __align__(16) float g_c1[BB * DD];
__device__ __align__(16) float g_e[BB * TT];
__device__ __align__(16) __nv_bfloat16 g_zallb[L1 * BB * 2048];
__device__ __align__(16) float g_yall[(long long)L1 * BB * VV];
__device__ float g_loss;
__device__ int g_i64;
__device__ unsigned g_count;

__device__ __forceinline__ float sigm(float x) { return 1.0f / (1.0f + expf(-x)); }
__device__ __forceinline__ int read_ys(const void* ys, int i) {
    return g_i64 ? (int)((const long long*)ys)[i] : ((const int*)ys)[i];
}

// ----------------------------------------------------------------------------
// Prep
// ----------------------------------------------------------------------------
__global__ void k_prep0(const float* __restrict__ bih0, const float* __restrict__ bhh0,
                        const float* __restrict__ bih1, const float* __restrict__ bhh1,
                        const void* __restrict__ ys) {
    int i = blockIdx.x * blockDim.x + threadIdx.x;
    int n = gridDim.x * blockDim.x;
    __nv_bfloat16 z = __float2bfloat16(0.f);
    for (int j = i; j < BB * DD; j += n) {
        g_c0[j] = 0.f; g_c1[j] = 0.f;
        g_z0s[0][j] = z; g_z0s[1][j] = z;
        g_z1s[0][j] = z; g_z1s[1][j] = z;
    }
    for (int j = i; j < 4096; j += n) {
        int u = j >> 2, gate = j & 3;
        int orow = gate * 1024 + u;
        g_bs0r[j] = bih0[orow] + bhh0[orow];
        g_bs1r[j] = bih1[orow] + bhh1[orow];
    }
    if (i == 0) {
        g_loss = 0.f;
        g_count = 0u;
        const int* w = (const int*)ys;
        int f = 1;
        for (int j = 1; j < 64; j += 2) if (w[j] != 0) f = 0;
        g_i64 = f;
    }
}

__global__ void k_cvt(const float* __restrict__ s, __nv_bfloat16* __restrict__ d, long long n2) {
    long long i = (long long)blockIdx.x * blockDim.x + threadIdx.x;
    long long stride = (long long)gridDim.x * blockDim.x;
    const float2* s2 = (const float2*)s;
    __nv_bfloat162* d2 = (__nv_bfloat162*)d;
    for (long long j = i; j < n2; j += stride) {
        float2 v = s2[j];
        d2[j] = __floats2bfloat162_rn(v.x, v.y);
    }
}

// Gate-interleaved LSTM weight reorder (row 4u+gate) + bf16
__global__ void k_reo0(const float* __restrict__ Wih, const float* __restrict__ Whh) {
    long long N = 4096LL * 3072;
    long long i = (long long)blockIdx.x * blockDim.x + threadIdx.x;
    long long stride = (long long)gridDim.x * blockDim.x;
    for (long long j = i; j < N; j += stride) {
        int r = (int)(j / 3072), c = (int)(j % 3072);
        int u = r >> 2, gate = r & 3;
        long long orow = gate * 1024 + u;
        float v = (c < 2048) ? Wih[orow * 2048 + c] : Whh[orow * 1024 + (c - 2048)];
        g_Wc0r[j] = __float2bfloat16(v);
    }
}
__global__ void k_reo1(const float* __restrict__ Wih, const float* __restrict__ Whh) {
    long long N = 4096LL * 2048;
    long long i = (long long)blockIdx.x * blockDim.x + threadIdx.x;
    long long stride = (long long)gridDim.x * blockDim.x;
    for (long long j = i; j < N; j += stride) {
        int r = (int)(j / 2048), c = (int)(j % 2048);
        int u = r >> 2, gate = r & 3;
        long long orow = gate * 1024 + u;
        float v = (c < 1024) ? Wih[orow * 1024 + c] : Whh[orow * 1024 + (c - 1024)];
        g_Wc1r[j] = __float2bfloat16(v);
    }
}

// ----------------------------------------------------------------------------
// HMMA m16n8k16 bf16 -> f32
// ----------------------------------------------------------------------------
__device__ __forceinline__ void mma_bf16(float* d, const unsigned* a, const unsigned* b) {
    asm volatile(
        "mma.sync.aligned.m16n8k16.row.col.f32.bf16.bf16.f32 "
        "{%0,%1,%2,%3}, {%4,%5,%6,%7}, {%8,%9}, {%0,%1,%2,%3};\n"
        : "+f"(d[0]), "+f"(d[1]), "+f"(d[2]), "+f"(d[3])
        : "r"(a[0]), "r"(a[1]), "r"(a[2]), "r"(a[3]), "r"(b[0]), "r"(b[1]));
}

// ----------------------------------------------------------------------------
// Big GEMM (prologue/epilogue): unchanged from round 2
// ----------------------------------------------------------------------------
template <int EPI>
__global__ __launch_bounds__(256) void mma_big(
    const __nv_bfloat16* __restrict__ A, const __nv_bfloat16* __restrict__ B,
    const float* __restrict__ bias, float* __restrict__ Cf,
    __nv_bfloat16* __restrict__ Cb, int M, int N, int K)
{
    constexpr int BKP = 40;
    __shared__ __nv_bfloat16 As[128][BKP];
    __shared__ __nv_bfloat16 Bs[128][BKP];
    const int tid = threadIdx.x, lane = tid & 31, wid = tid >> 5;
    const int wm = wid >> 1, wn = wid & 1;
    const int m0 = blockIdx.y * 128, n0 = blockIdx.x * 128;
    const int g = lane >> 2, tg = lane & 3;

    float acc[2][8][4];
#pragma unroll
    for (int a = 0; a < 2; a++)
#pragma unroll
        for (int b = 0; b < 8; b++)
#pragma unroll
            for (int c = 0; c < 4; c++) acc[a][b][c] = 0.f;

    int ar[2], ac[2];
#pragma unroll
    for (int t = 0; t < 2; t++) { int s = tid + t * 256; ar[t] = s >> 2; ac[t] = (s & 3) * 8; }

    uint4 pa[2], pb[2];
#pragma unroll
    for (int t = 0; t < 2; t++) {
        int m = m0 + ar[t];
        pa[t] = (m < M) ? *(const uint4*)(A + (long long)m * K + ac[t]) : make_uint4(0, 0, 0, 0);
        int n = n0 + ar[t];
        pb[t] = (n < N) ? *(const uint4*)(B + (long long)n * K + ac[t]) : make_uint4(0, 0, 0, 0);
    }
#pragma unroll
    for (int t = 0; t < 2; t++) {
        *(uint2*)&As[ar[t]][ac[t]]     = make_uint2(pa[t].x, pa[t].y);
        *(uint2*)&As[ar[t]][ac[t] + 4] = make_uint2(pa[t].z, pa[t].w);
        *(uint2*)&Bs[ar[t]][ac[t]]     = make_uint2(pb[t].x, pb[t].y);
        *(uint2*)&Bs[ar[t]][ac[t] + 4] = make_uint2(pb[t].z, pb[t].w);
    }
    __syncthreads();

    const int niter = K >> 5;
    for (int it = 0; it < niter; it++) {
        if (it + 1 < niter) {
            int k0 = (it + 1) << 5;
#pragma unroll
            for (int t = 0; t < 2; t++) {
                int m = m0 + ar[t];
                pa[t] = (m < M) ? *(const uint4*)(A + (long long)m * K + k0 + ac[t]) : make_uint4(0, 0, 0, 0);
                int n = n0 + ar[t];
                pb[t] = (n < N) ? *(const uint4*)(B + (long long)n * K + k0 + ac[t]) : make_uint4(0, 0, 0, 0);
            }
        }
#pragma unroll
        for (int kt = 0; kt < 2; kt++) {
            const int c0 = kt * 16 + tg * 2;
            unsigned af[2][4];
#pragma unroll
            for (int mt = 0; mt < 2; mt++) {
                int r = wm * 32 + mt * 16 + g;
                af[mt][0] = *(const unsigned*)&As[r][c0];
                af[mt][1] = *(const unsigned*)&As[r + 8][c0];
                af[mt][2] = *(const unsigned*)&As[r][c0 + 8];
                af[mt][3] = *(const unsigned*)&As[r + 8][c0 + 8];
            }
#pragma unroll
            for (int nt = 0; nt < 8; nt++) {
                int n = wn * 64 + nt * 8 + g;
                unsigned bf[2];
                bf[0] = *(const unsigned*)&Bs[n][c0];
                bf[1] = *(const unsigned*)&Bs[n][c0 + 8];
                mma_bf16(acc[0][nt], af[0], bf);
                mma_bf16(acc[1][nt], af[1], bf);
            }
        }
        __syncthreads();
        if (it + 1 < niter) {
#pragma unroll
            for (int t = 0; t < 2; t++) {
                *(uint2*)&As[ar[t]][ac[t]]     = make_uint2(pa[t].x, pa[t].y);
                *(uint2*)&As[ar[t]][ac[t] + 4] = make_uint2(pa[t].z, pa[t].w);
                *(uint2*)&Bs[ar[t]][ac[t]]     = make_uint2(pb[t].x, pb[t].y);
                *(uint2*)&Bs[ar[t]][ac[t] + 4] = make_uint2(pb[t].z, pb[t].w);
            }
            __syncthreads();
        }
    }

#pragma unroll
    for (int mt = 0; mt < 2; mt++) {
#pragma unroll
        for (int nt = 0; nt < 8; nt++) {
            int r = m0 + wm * 32 + mt * 16 + g;
            int c = n0 + wn * 64 + nt * 8 + tg * 2;
            float* a = acc[mt][nt];
            if (EPI == 0) {
                float b0 = (c < N) ? bias[c] : 0.f;
                float b1 = (c + 1 < N) ? bias[c + 1] : 0.f;
                if (r < M) {
                    if (c < N)     Cf[(long long)r * N + c]     = a[0] + b0;
                    if (c + 1 < N) Cf[(long long)r * N + c + 1] = a[1] + b1;
                }
                if (r + 8 < M) {
                    if (c < N)     Cf[(long long)(r + 8) * N + c]     = a[2] + b0;
                    if (c + 1 < N) Cf[(long long)(r + 8) * N + c + 1] = a[3] + b1;
                }
            } else {
                float b0 = bias[c], b1 = bias[c + 1];
                __nv_bfloat162 v0 = __floats2bfloat162_rn(tanhf(a[0] + b0), tanhf(a[1] + b1));
                __nv_bfloat162 v1 = __floats2bfloat162_rn(tanhf(a[2] + b0), tanhf(a[3] + b1));
                *(__nv_bfloat162*)(Cb + (long long)r * N + c) = v0;
                *(__nv_bfloat162*)(Cb + (long long)(r + 8) * N + c) = v1;
            }
        }
    }
}

// ----------------------------------------------------------------------------
// Persistent loop kernel
// ----------------------------------------------------------------------------
// smem layout (dynamic, 67840B): As stages [2][32][264] bf16 @0 (33792B),
// Bs stages [2][32][264] @33792 (33792B), stok int[32] @67584.
// Pred float[8][32][32] aliases @0 after compute completes.

__device__ __forceinline__ void gsync(unsigned& target) {
    __syncthreads();
    __threadfence();
    if (threadIdx.x == 0) {
        target += NBLK;
        atomicAdd(&g_count, 1u);
        while (atomicAdd(&g_count, 0u) < target) { }
    }
    __syncthreads();
}

// Tile GEMM: C[32 x 32] at cols [n0, n0+32) of N; 8 warps split K.
// AKIND: 0 = A0[32][1024] (ldcg);  1 = [emb(tok)|A0=att|A1=z0prev];  2 = [A0=z0new|A1=z1old]
// EPI:   0 = tanh+bias -> outb (stride 1024);  1 = LSTM pointwise
template <int AKIND, int EPI, bool ZALL>
__device__ void gemm_tile(char* sm, int n0, int K,
                          const __nv_bfloat16* __restrict__ B, const float* __restrict__ bias,
                          const __nv_bfloat16* A0, const __nv_bfloat16* A1,
                          __nv_bfloat16* outb, float* cst, __nv_bfloat16* znew,
                          __nv_bfloat16* zallp, int step, const int* stok)
{
    const int tid = threadIdx.x, lane = tid & 31, wid = tid >> 5;
    const int g = lane >> 2, tg = lane & 3;
    __nv_bfloat16 (*As0)[264] = (__nv_bfloat16(*)[264])(sm);
    __nv_bfloat16 (*As1)[264] = (__nv_bfloat16(*)[264])(sm + 16896);
    __nv_bfloat16 (*Bs0)[264] = (__nv_bfloat16(*)[264])(sm + 33792);
    __nv_bfloat16 (*Bs1)[264] = (__nv_bfloat16(*)[264])(sm + 50688);

    float acc[2][4][4];
#pragma unroll
    for (int a = 0; a < 2; a++)
#pragma unroll
        for (int b = 0; b < 4; b++)
#pragma unroll
            for (int c = 0; c < 4; c++) acc[a][b][c] = 0.f;

    uint4 av[4], bv[4];
    const int S = K >> 8;

#define LOADK(SI)                                                                     \
    {                                                                                 \
        int kbase = (SI) << 8;                                                        \
        _Pragma("unroll")                                                             \
        for (int j = 0; j < 4; j++) {                                                 \
            int idx = tid + j * 256; int r = idx >> 5; int c = (idx & 31) * 8;        \
            int gc = kbase + c;                                                       \
            if (AKIND == 0) {                                                         \
                av[j] = __ldcg((const uint4*)(A0 + r * 1024 + gc));                   \
            } else if (AKIND == 1) {                                                  \
                if (gc < 1024)      av[j] = *(const uint4*)(g_embb + (long long)stok[r] * 1024 + gc); \
                else if (gc < 2048) av[j] = __ldcg((const uint4*)(A0 + r * 1024 + gc - 1024)); \
                else                av[j] = __ldcg((const uint4*)(A1 + r * 1024 + gc - 2048)); \
            } else {                                                                  \
                if (gc < 1024) av[j] = __ldcg((const uint4*)(A0 + r * 1024 + gc));    \
                else           av[j] = __ldcg((const uint4*)(A1 + r * 1024 + gc - 1024)); \
            }                                                                         \
            bv[j] = *(const uint4*)(B + (long long)(n0 + r) * K + gc);                \
        }                                                                             \
    }

#define STOREK(ST)                                                                    \
    {                                                                                 \
        __nv_bfloat16 (*Ad)[264] = (ST) ? As1 : As0;                                  \
        __nv_bfloat16 (*Bd)[264] = (ST) ? Bs1 : Bs0;                                  \
        _Pragma("unroll")                                                             \
        for (int j = 0; j < 4; j++) {                                                 \
            int idx = tid + j * 256; int r = idx >> 5; int c = (idx & 31) * 8;        \
            *(uint4*)&Ad[r][c] = av[j];                                               \
            *(uint4*)&Bd[r][c] = bv[j];                                               \
        }                                                                             \
    }

    LOADK(0); STOREK(0);
    __syncthreads();

    for (int si = 0; si < S; si++) {
        if (si + 1 < S) LOADK(si + 1);
        {
            __nv_bfloat16 (*As)[264] = (si & 1) ? As1 : As0;
            __nv_bfloat16 (*Bs)[264] = (si & 1) ? Bs1 : Bs0;
            const int kw = wid * 32;
#pragma unroll
            for (int ks = 0; ks < 2; ks++) {
                const int c0 = kw + ks * 16 + tg * 2;
                unsigned af[2][4];
#pragma unroll
                for (int mt = 0; mt < 2; mt++) {
                    int r = mt * 16 + g;
                    af[mt][0] = *(const unsigned*)&As[r][c0];
                    af[mt][1] = *(const unsigned*)&As[r + 8][c0];
                    af[mt][2] = *(const unsigned*)&As[r][c0 + 8];
                    af[mt][3] = *(const unsigned*)&As[r + 8][c0 + 8];
                }
#pragma unroll
                for (int nt = 0; nt < 4; nt++) {
                    int n = nt * 8 + g;
                    unsigned bf[2];
                    bf[0] = *(const unsigned*)&Bs[n][c0];
                    bf[1] = *(const unsigned*)&Bs[n][c0 + 8];
                    mma_bf16(acc[0][nt], af[0], bf);
                    mma_bf16(acc[1][nt], af[1], bf);
                }
            }
        }
        if (si + 1 < S) STOREK((si + 1) & 1);
        __syncthreads();
    }
#undef LOADK
#undef STOREK

    // cross-warp K reduce via smem (aliases stage buffers; all dead now)
    float* Pred = (float*)sm;  // [8][32][32]
    {
        int base = wid * 1024;
#pragma unroll
        for (int mt = 0; mt < 2; mt++)
#pragma unroll
            for (int nt = 0; nt < 4; nt++) {
                int r = mt * 16 + g, cl = nt * 8 + tg * 2;
                Pred[base + r * 32 + cl]           = acc[mt][nt][0];
                Pred[base + r * 32 + cl + 1]       = acc[mt][nt][1];
                Pred[base + (r + 8) * 32 + cl]     = acc[mt][nt][2];
                Pred[base + (r + 8) * 32 + cl + 1] = acc[mt][nt][3];
            }
    }
    __syncthreads();

    if (EPI == 0) {
#pragma unroll
        for (int k = 0; k < 4; k++) {
            int o = tid + k * 256;
            int r = o >> 5, c = o & 31;
            float sum = 0.f;
#pragma unroll
            for (int w = 0; w < 8; w++) sum += Pred[w * 1024 + r * 32 + c];
            outb[r * 1024 + n0 + c] = __float2bfloat16(tanhf(sum + bias[n0 + c]));
        }
    } else {
        int b = tid >> 3, ul = tid & 7;
        float gv[4];
#pragma unroll
        for (int gate = 0; gate < 4; gate++) {
            int c = ul * 4 + gate;
            float sum = 0.f;
#pragma unroll
            for (int w = 0; w < 8; w++) sum += Pred[w * 1024 + b * 32 + c];
            gv[gate] = sum + bias[n0 + c];
        }
        int u = (n0 >> 2) + ul;
        float cv = sigm(gv[1]) * cst[b * 1024 + u] + sigm(gv[0]) * tanhf(gv[2]);
        float h = sigm(gv[3]) * tanhf(cv);
        cst[b * 1024 + u] = cv;
        znew[b * 1024 + u] = __float2bfloat16(h);
        if (ZALL) zallp[(long long)(step * 32 + b) * 2048 + u] = __float2bfloat16(h);
    }
    __syncthreads();
}

__device__ void phase_attn_e(const int* __restrict__ hlens) {
    int tid = threadIdx.x, lane = tid & 31, warp = tid >> 5;
    for (int u = blockIdx.x; u < 160; u += NBLK) {
        int b = u / 5, ch = u - b * 5;
        float dqr[32];
        const uint4* dqp = (const uint4*)(g_dqb + b * 1024 + lane * 32);
#pragma unroll
        for (int q = 0; q < 4; q++) {
            uint4 v = __ldcg(dqp + q);
            __nv_bfloat162* h = (__nv_bfloat162*)&v;
#pragma unroll
            for (int k = 0; k < 4; k++) {
                float2 f = __bfloat1622float2(h[k]);
                dqr[q * 8 + k * 2] = f.x; dqr[q * 8 + k * 2 + 1] = f.y;
            }
        }
        int hl = hlens[b];
#pragma unroll 2
        for (int i = 0; i < 10; i++) {
            int t = ch * 80 + warp * 10 + i;
            const __nv_bfloat16* row = g_preb + ((long long)b * 400 + t) * 1024 + lane * 32;
            float s = 0.f;
#pragma unroll
            for (int q = 0; q < 4; q++) {
                uint4 v = *(const uint4*)(row + q * 8);
                __nv_bfloat162* h = (__nv_bfloat162*)&v;
#pragma unroll
                for (int k = 0; k < 4; k++) {
                    float2 f = __bfloat1622float2(h[k]);
                    s = fmaf(f.x, dqr[q * 8 + k * 2], s);
                    s = fmaf(f.y, dqr[q * 8 + k * 2 + 1], s);
                }
            }
#pragma unroll
            for (int off = 16; off; off >>= 1) s += __shfl_xor_sync(0xffffffffu, s, off);
            if (lane == 0) g_e[b * 400 + t] = (t < hl) ? 2.f * s : NEGBIG;
        }
    }
}

__device__ void phase_attn_c(char* sm, int s) {
    if (blockIdx.x >= 128) return;
    int b = blockIdx.x >> 2, cc = blockIdx.x & 3;
    float* ws = (float*)sm;       // 400
    float* red = ws + 400;        // 256
    int tid = threadIdx.x;
    float lm = NEGBIG;
    for (int i = tid; i < 400; i += 256) {
        float v = __ldcg(&g_e[b * 400 + i]);
        ws[i] = v; lm = fmaxf(lm, v);
    }
    red[tid] = lm; __syncthreads();
    for (int st = 128; st; st >>= 1) { if (tid < st) red[tid] = fmaxf(red[tid], red[tid + st]); __syncthreads(); }
    float m = red[0]; __syncthreads();
    float ls = 0.f;
    for (int i = tid; i < 400; i += 256) { float w = expf(ws[i] - m); ws[i] = w; ls += w; }
    red[tid] = ls; __syncthreads();
    for (int st = 128; st; st >>= 1) { if (tid < st) red[tid] += red[tid + st]; __syncthreads(); }
    float Sinv = 1.f / red[0];
    __syncthreads();
    int col = cc * 256 + tid;
    const __nv_bfloat16* hp = g_hsb + (long long)b * 400 * 1024 + col;
    float acc = 0.f;
#pragma unroll 4
    for (int t = 0; t < 400; t++) acc = fmaf(ws[t], __bfloat162float(hp[(long long)t * 1024]), acc);
    __nv_bfloat16 bv = __float2bfloat16(acc * Sinv);
    g_attb[b * 1024 + col] = bv;
    g_zallb[((long long)s * 32 + b) * 2048 + 1024 + col] = bv;
}

__global__ void __launch_bounds__(256, 1) k_loop(const int* __restrict__ hlens,
                                                 const void* __restrict__ ys,
                                                 const float* __restrict__ bdec) {
    extern __shared__ char sm[];
    const int bid = blockIdx.x;
    const int tid = threadIdx.x;
    unsigned target = 0;

    for (int s = 0; s <= 101; s++) {
        const int p = s & 1;
        // Phase A: g1(s-1) on blocks 0..127, dq(s) on blocks 128..147
        if (bid < 128) {
            if (s >= 1) {
                gemm_tile<2, 1, true>(sm, bid * 32, 2048, g_Wc1r, g_bs1r,
                                      g_z0s[p], g_z1s[1 - p],
                                      nullptr, g_c1, g_z1s[p], g_zallb, s - 1, nullptr);
            }
        } else {
            if (s <= 100) {
                for (int u = bid - 128; u < 32; u += 20) {
                    gemm_tile<0, 0, false>(sm, u * 32, 1024, g_Wdecb, bdec,
                                           g_z0s[p], nullptr,
                                           g_dqb, nullptr, nullptr, nullptr, s, nullptr);
                }
            }
        }
        gsync(target);
        if (s == 101) break;

        phase_attn_e(hlens);
        gsync(target);

        phase_attn_c(sm, s);
        gsync(target);

        // Phase D: g0(s) on blocks 0..127
        if (bid < 128) {
            int* stok = (int*)(sm + 67584);
            if (tid < 32) stok[tid] = (s == 0) ? 4999 : read_ys(ys, tid * 100 + s - 1);
            __syncthreads();
            gemm_tile<1, 1, false>(sm, bid * 32, 3072, g_Wc0r, g_bs0r,
                                   g_attb, g_z0s[p],
                                   nullptr, g_c0, g_z0s[1 - p], nullptr, s, stok);
        }
        gsync(target);
    }
}

// ----------------------------------------------------------------------------
// CE
// ----------------------------------------------------------------------------
__global__ void k_ce(const void* __restrict__ ys) {
    int r = blockIdx.x;
    int l = r / BB, b = r % BB;
    const float* y = g_yall + (long long)r * VV;
    __shared__ float red[256];
    int tid = threadIdx.x;
    float lm = NEGBIG;
    for (int v = tid; v < VV; v += 256) lm = fmaxf(lm, y[v]);
    red[tid] = lm; __syncthreads();
    for (int s = 128; s > 0; s >>= 1) { if (tid < s) red[tid] = fmaxf(red[tid], red[tid + s]); __syncthreads(); }
    float m = red[0]; __syncthreads();
    float ls = 0.f;
    for (int v = tid; v < VV; v += 256) ls += expf(y[v] - m);
    red[tid] = ls; __syncthreads();
    for (int s = 128; s > 0; s >>= 1) { if (tid < s) red[tid] += red[tid + s]; __syncthreads(); }
    if (tid == 0) {
        int tgt = (l < LL) ? read_ys(ys, b * LL + l) : 4999;
        float ce = logf(red[0]) + m - y[tgt];
        atomicAdd(&g_loss, ce);
    }
}

__global__ void k_fin(float* out) {
    out[0] = g_loss * ((float)LL / (float)(L1 * BB));
}

// ----------------------------------------------------------------------------
// Launch
// ----------------------------------------------------------------------------
extern "C" void kernel_launch(void* const* d_in, const int* in_sizes, int n_in,
                              void* d_out, int out_size) {
    const float* hs    = (const float*)d_in[0];
    const float* embed = (const float*)d_in[1];
    const float* Wenc  = (const float*)d_in[2];
    const float* benc  = (const float*)d_in[3];
    const float* Wdec  = (const float*)d_in[4];
    const float* bdec  = (const float*)d_in[5];
    const float* Wih0  = (const float*)d_in[6];
    const float* Whh0  = (const float*)d_in[7];
    const float* bih0  = (const float*)d_in[8];
    const float* bhh0  = (const float*)d_in[9];
    const float* Wih1  = (const float*)d_in[10];
    const float* Whh1  = (const float*)d_in[11];
    const float* bih1  = (const float*)d_in[12];
    const float* bhh1  = (const float*)d_in[13];
    const float* Wout  = (const float*)d_in[14];
    const float* bout  = (const float*)d_in[15];
    const int*   hlens = (const int*)d_in[16];
    const void*  ys    = (const void*)d_in[17];

    __nv_bfloat16 *hsb, *preb, *embb, *Wencb, *Wdecb, *Woutb, *zallb;
    float *yall;
    cudaGetSymbolAddress((void**)&hsb,   g_hsb);
    cudaGetSymbolAddress((void**)&preb,  g_preb);
    cudaGetSymbolAddress((void**)&embb,  g_embb);
    cudaGetSymbolAddress((void**)&Wencb, g_Wencb);
    cudaGetSymbolAddress((void**)&Wdecb, g_Wdecb);
    cudaGetSymbolAddress((void**)&Woutb, g_Woutb);
    cudaGetSymbolAddress((void**)&zallb, g_zallb);
    cudaGetSymbolAddress((void**)&yall,  g_yall);

    static int smem_set = 0;
    if (!smem_set) {
        cudaFuncSetAttribute(k_loop, cudaFuncAttributeMaxDynamicSharedMemorySize, 69632);
        smem_set = 1;
    }

    k_prep0<<<64, 256>>>(bih0, bhh0, bih1, bhh1, ys);
    k_cvt<<<512, 256>>>(hs, hsb, (long long)BB * TT * DD / 2);
    k_cvt<<<256, 256>>>(embed, embb, 5000LL * DD / 2);
    k_cvt<<<128, 256>>>(Wenc, Wencb, (long long)DD * DD / 2);
    k_cvt<<<128, 256>>>(Wdec, Wdecb, (long long)DD * DD / 2);
    k_cvt<<<512, 256>>>(Wout, Woutb, (long long)VV * 2048 / 2);
    k_reo0<<<1024, 256>>>(Wih0, Whh0);
    k_reo1<<<1024, 256>>>(Wih1, Whh1);

    // pre_enc = tanh(hs @ Wenc^T + benc) -> bf16
    mma_big<1><<<dim3(DD / 128, BB * TT / 128), 256>>>(hsb, Wencb, benc, nullptr, preb,
                                                       BB * TT, DD, DD);

    // the entire recurrent loop in one persistent kernel
    k_loop<<<NBLK, 256, 69632>>>(hlens, ys, bdec);

    // y_all = zall @ Wout^T + bout
    mma_big<0><<<dim3((VV + 127) / 128, (L1 * BB + 127) / 128), 256>>>(
        zallb, Woutb, bout, yall, nullptr, L1 * BB, VV, 2048);

    k_ce<<<L1 * BB, 256>>>(ys);
    k_fin<<<1, 1>>>((float*)d_out);
}

// round 4
// speedup vs baseline: 3.1890x; 1.0072x over previous
#include <cuda_runtime.h>
#include <cuda_bf16.h>

#define BB 32
#define TT 400
#define DD 1024
#define VV 5000
#define LL 100
#define L1 101
#define NEGBIG -1e30f
#define NBLK 148

// ----------------------------------------------------------------------------
// Device-global scratch
// ----------------------------------------------------------------------------
__device__ __align__(16) __nv_bfloat16 g_hsb [BB * TT * DD];
__device__ __align__(16) __nv_bfloat16 g_preb[BB * TT * DD];
__device__ __align__(16) __nv_bfloat16 g_embb[5000 * DD];
__device__ __align__(16) __nv_bfloat16 g_Wencb[DD * DD];
__device__ __align__(16) __nv_bfloat16 g_Wdecb[DD * DD];
__device__ __align__(16) __nv_bfloat16 g_Woutb[VV * 2048];
__device__ __align__(16) __nv_bfloat16 g_Wc0r[4096 * 3072];
__device__ __align__(16) __nv_bfloat16 g_Wc1r[4096 * 2048];
__device__ __align__(16) float g_bs0r[4096];
__device__ __align__(16) float g_bs1r[4096];
__device__ __align__(16) __nv_bfloat16 g_dqb[BB * DD];
__device__ __align__(16) __nv_bfloat16 g_attb[BB * DD];
__device__ __align__(16) __nv_bfloat16 g_z0s[2][BB * DD];
__device__ __align__(16) __nv_bfloat16 g_z1s[2][BB * DD];
__device__ __align__(16) float g_c0[BB * DD];
__device__ __align__(16) float g_c1[BB * DD];
__device__ __align__(16) float g_e[BB * TT];
__device__ __align__(16) __nv_bfloat16 g_zallb[L1 * BB * 2048];
__device__ __align__(16) float g_yall[(long long)L1 * BB * VV];
__device__ float g_loss;
__device__ int g_i64;
__device__ unsigned g_count;

__device__ __forceinline__ float sigm(float x) { return 1.0f / (1.0f + expf(-x)); }
__device__ __forceinline__ int read_ys(const void* ys, int i) {
    return g_i64 ? (int)((const long long*)ys)[i] : ((const int*)ys)[i];
}

// ----------------------------------------------------------------------------
// Prep
// ----------------------------------------------------------------------------
__global__ void k_prep0(const float* __restrict__ bih0, const float* __restrict__ bhh0,
                        const float* __restrict__ bih1, const float* __restrict__ bhh1,
                        const void* __restrict__ ys) {
    int i = blockIdx.x * blockDim.x + threadIdx.x;
    int n = gridDim.x * blockDim.x;
    __nv_bfloat16 z = __float2bfloat16(0.f);
    for (int j = i; j < BB * DD; j += n) {
        g_c0[j] = 0.f; g_c1[j] = 0.f;
        g_z0s[0][j] = z; g_z0s[1][j] = z;
        g_z1s[0][j] = z; g_z1s[1][j] = z;
    }
    for (int j = i; j < 4096; j += n) {
        int u = j >> 2, gate = j & 3;
        int orow = gate * 1024 + u;
        g_bs0r[j] = bih0[orow] + bhh0[orow];
        g_bs1r[j] = bih1[orow] + bhh1[orow];
    }
    if (i == 0) {
        g_loss = 0.f;
        g_count = 0u;
        const int* w = (const int*)ys;
        int f = 1;
        for (int j = 1; j < 64; j += 2) if (w[j] != 0) f = 0;
        g_i64 = f;
    }
}

__global__ void k_cvt(const float* __restrict__ s, __nv_bfloat16* __restrict__ d, long long n2) {
    long long i = (long long)blockIdx.x * blockDim.x + threadIdx.x;
    long long stride = (long long)gridDim.x * blockDim.x;
    const float2* s2 = (const float2*)s;
    __nv_bfloat162* d2 = (__nv_bfloat162*)d;
    for (long long j = i; j < n2; j += stride) {
        float2 v = s2[j];
        d2[j] = __floats2bfloat162_rn(v.x, v.y);
    }
}

// Gate-interleaved LSTM weight reorder (row 4u+gate) + bf16
__global__ void k_reo0(const float* __restrict__ Wih, const float* __restrict__ Whh) {
    long long N = 4096LL * 3072;
    long long i = (long long)blockIdx.x * blockDim.x + threadIdx.x;
    long long stride = (long long)gridDim.x * blockDim.x;
    for (long long j = i; j < N; j += stride) {
        int r = (int)(j / 3072), c = (int)(j % 3072);
        int u = r >> 2, gate = r & 3;
        long long orow = gate * 1024 + u;
        float v = (c < 2048) ? Wih[orow * 2048 + c] : Whh[orow * 1024 + (c - 2048)];
        g_Wc0r[j] = __float2bfloat16(v);
    }
}
__global__ void k_reo1(const float* __restrict__ Wih, const float* __restrict__ Whh) {
    long long N = 4096LL * 2048;
    long long i = (long long)blockIdx.x * blockDim.x + threadIdx.x;
    long long stride = (long long)gridDim.x * blockDim.x;
    for (long long j = i; j < N; j += stride) {
        int r = (int)(j / 2048), c = (int)(j % 2048);
        int u = r >> 2, gate = r & 3;
        long long orow = gate * 1024 + u;
        float v = (c < 1024) ? Wih[orow * 1024 + c] : Whh[orow * 1024 + (c - 1024)];
        g_Wc1r[j] = __float2bfloat16(v);
    }
}

// ----------------------------------------------------------------------------
// HMMA m16n8k16 bf16 -> f32
// ----------------------------------------------------------------------------
__device__ __forceinline__ void mma_bf16(float* d, const unsigned* a, const unsigned* b) {
    asm volatile(
        "mma.sync.aligned.m16n8k16.row.col.f32.bf16.bf16.f32 "
        "{%0,%1,%2,%3}, {%4,%5,%6,%7}, {%8,%9}, {%0,%1,%2,%3};\n"
        : "+f"(d[0]), "+f"(d[1]), "+f"(d[2]), "+f"(d[3])
        : "r"(a[0]), "r"(a[1]), "r"(a[2]), "r"(a[3]), "r"(b[0]), "r"(b[1]));
}

// ----------------------------------------------------------------------------
// Big GEMM (prologue/epilogue): unchanged from round 2
// ----------------------------------------------------------------------------
template <int EPI>
__global__ __launch_bounds__(256) void mma_big(
    const __nv_bfloat16* __restrict__ A, const __nv_bfloat16* __restrict__ B,
    const float* __restrict__ bias, float* __restrict__ Cf,
    __nv_bfloat16* __restrict__ Cb, int M, int N, int K)
{
    constexpr int BKP = 40;
    __shared__ __nv_bfloat16 As[128][BKP];
    __shared__ __nv_bfloat16 Bs[128][BKP];
    const int tid = threadIdx.x, lane = tid & 31, wid = tid >> 5;
    const int wm = wid >> 1, wn = wid & 1;
    const int m0 = blockIdx.y * 128, n0 = blockIdx.x * 128;
    const int g = lane >> 2, tg = lane & 3;

    float acc[2][8][4];
#pragma unroll
    for (int a = 0; a < 2; a++)
#pragma unroll
        for (int b = 0; b < 8; b++)
#pragma unroll
            for (int c = 0; c < 4; c++) acc[a][b][c] = 0.f;

    int ar[2], ac[2];
#pragma unroll
    for (int t = 0; t < 2; t++) { int s = tid + t * 256; ar[t] = s >> 2; ac[t] = (s & 3) * 8; }

    uint4 pa[2], pb[2];
#pragma unroll
    for (int t = 0; t < 2; t++) {
        int m = m0 + ar[t];
        pa[t] = (m < M) ? *(const uint4*)(A + (long long)m * K + ac[t]) : make_uint4(0, 0, 0, 0);
        int n = n0 + ar[t];
        pb[t] = (n < N) ? *(const uint4*)(B + (long long)n * K + ac[t]) : make_uint4(0, 0, 0, 0);
    }
#pragma unroll
    for (int t = 0; t < 2; t++) {
        *(uint2*)&As[ar[t]][ac[t]]     = make_uint2(pa[t].x, pa[t].y);
        *(uint2*)&As[ar[t]][ac[t] + 4] = make_uint2(pa[t].z, pa[t].w);
        *(uint2*)&Bs[ar[t]][ac[t]]     = make_uint2(pb[t].x, pb[t].y);
        *(uint2*)&Bs[ar[t]][ac[t] + 4] = make_uint2(pb[t].z, pb[t].w);
    }
    __syncthreads();

    const int niter = K >> 5;
    for (int it = 0; it < niter; it++) {
        if (it + 1 < niter) {
            int k0 = (it + 1) << 5;
#pragma unroll
            for (int t = 0; t < 2; t++) {
                int m = m0 + ar[t];
                pa[t] = (m < M) ? *(const uint4*)(A + (long long)m * K + k0 + ac[t]) : make_uint4(0, 0, 0, 0);
                int n = n0 + ar[t];
                pb[t] = (n < N) ? *(const uint4*)(B + (long long)n * K + k0 + ac[t]) : make_uint4(0, 0, 0, 0);
            }
        }
#pragma unroll
        for (int kt = 0; kt < 2; kt++) {
            const int c0 = kt * 16 + tg * 2;
            unsigned af[2][4];
#pragma unroll
            for (int mt = 0; mt < 2; mt++) {
                int r = wm * 32 + mt * 16 + g;
                af[mt][0] = *(const unsigned*)&As[r][c0];
                af[mt][1] = *(const unsigned*)&As[r + 8][c0];
                af[mt][2] = *(const unsigned*)&As[r][c0 + 8];
                af[mt][3] = *(const unsigned*)&As[r + 8][c0 + 8];
            }
#pragma unroll
            for (int nt = 0; nt < 8; nt++) {
                int n = wn * 64 + nt * 8 + g;
                unsigned bf[2];
                bf[0] = *(const unsigned*)&Bs[n][c0];
                bf[1] = *(const unsigned*)&Bs[n][c0 + 8];
                mma_bf16(acc[0][nt], af[0], bf);
                mma_bf16(acc[1][nt], af[1], bf);
            }
        }
        __syncthreads();
        if (it + 1 < niter) {
#pragma unroll
            for (int t = 0; t < 2; t++) {
                *(uint2*)&As[ar[t]][ac[t]]     = make_uint2(pa[t].x, pa[t].y);
                *(uint2*)&As[ar[t]][ac[t] + 4] = make_uint2(pa[t].z, pa[t].w);
                *(uint2*)&Bs[ar[t]][ac[t]]     = make_uint2(pb[t].x, pb[t].y);
                *(uint2*)&Bs[ar[t]][ac[t] + 4] = make_uint2(pb[t].z, pb[t].w);
            }
            __syncthreads();
        }
    }

#pragma unroll
    for (int mt = 0; mt < 2; mt++) {
#pragma unroll
        for (int nt = 0; nt < 8; nt++) {
            int r = m0 + wm * 32 + mt * 16 + g;
            int c = n0 + wn * 64 + nt * 8 + tg * 2;
            float* a = acc[mt][nt];
            if (EPI == 0) {
                float b0 = (c < N) ? bias[c] : 0.f;
                float b1 = (c + 1 < N) ? bias[c + 1] : 0.f;
                if (r < M) {
                    if (c < N)     Cf[(long long)r * N + c]     = a[0] + b0;
                    if (c + 1 < N) Cf[(long long)r * N + c + 1] = a[1] + b1;
                }
                if (r + 8 < M) {
                    if (c < N)     Cf[(long long)(r + 8) * N + c]     = a[2] + b0;
                    if (c + 1 < N) Cf[(long long)(r + 8) * N + c + 1] = a[3] + b1;
                }
            } else {
                float b0 = bias[c], b1 = bias[c + 1];
                __nv_bfloat162 v0 = __floats2bfloat162_rn(tanhf(a[0] + b0), tanhf(a[1] + b1));
                __nv_bfloat162 v1 = __floats2bfloat162_rn(tanhf(a[2] + b0), tanhf(a[3] + b1));
                *(__nv_bfloat162*)(Cb + (long long)r * N + c) = v0;
                *(__nv_bfloat162*)(Cb + (long long)(r + 8) * N + c) = v1;
            }
        }
    }
}

// ----------------------------------------------------------------------------
// Persistent loop kernel
// ----------------------------------------------------------------------------
// smem layout (dynamic, 67840B): As stages [2][32][264] bf16 @0 (33792B),
// Bs stages [2][32][264] @33792 (33792B), stok int[32] @67584.
// Pred float[8][32][32] aliases @0 after compute completes.

__device__ __forceinline__ void gsync(unsigned& target) {
    __syncthreads();
    __threadfence();
    if (threadIdx.x == 0) {
        target += NBLK;
        atomicAdd(&g_count, 1u);
        while (atomicAdd(&g_count, 0u) < target) { }
    }
    __syncthreads();
}

// Tile GEMM: C[32 x 32] at cols [n0, n0+32) of N; 8 warps split K.
// AKIND: 0 = A0[32][1024] (ldcg);  1 = [emb(tok)|A0=att|A1=z0prev];  2 = [A0=z0new|A1=z1old]
// EPI:   0 = tanh+bias -> outb (stride 1024);  1 = LSTM pointwise
template <int AKIND, int EPI, bool ZALL>
__device__ void gemm_tile(char* sm, int n0, int K,
                          const __nv_bfloat16* __restrict__ B, const float* __restrict__ bias,
                          const __nv_bfloat16* A0, const __nv_bfloat16* A1,
                          __nv_bfloat16* outb, float* cst, __nv_bfloat16* znew,
                          __nv_bfloat16* zallp, int step, const int* stok)
{
    const int tid = threadIdx.x, lane = tid & 31, wid = tid >> 5;
    const int g = lane >> 2, tg = lane & 3;
    __nv_bfloat16 (*As0)[264] = (__nv_bfloat16(*)[264])(sm);
    __nv_bfloat16 (*As1)[264] = (__nv_bfloat16(*)[264])(sm + 16896);
    __nv_bfloat16 (*Bs0)[264] = (__nv_bfloat16(*)[264])(sm + 33792);
    __nv_bfloat16 (*Bs1)[264] = (__nv_bfloat16(*)[264])(sm + 50688);

    float acc[2][4][4];
#pragma unroll
    for (int a = 0; a < 2; a++)
#pragma unroll
        for (int b = 0; b < 4; b++)
#pragma unroll
            for (int c = 0; c < 4; c++) acc[a][b][c] = 0.f;

    uint4 av[4], bv[4];
    const int S = K >> 8;

#define LOADK(SI)                                                                     \
    {                                                                                 \
        int kbase = (SI) << 8;                                                        \
        _Pragma("unroll")                                                             \
        for (int j = 0; j < 4; j++) {                                                 \
            int idx = tid + j * 256; int r = idx >> 5; int c = (idx & 31) * 8;        \
            int gc = kbase + c;                                                       \
            if (AKIND == 0) {                                                         \
                av[j] = __ldcg((const uint4*)(A0 + r * 1024 + gc));                   \
            } else if (AKIND == 1) {                                                  \
                if (gc < 1024)      av[j] = *(const uint4*)(g_embb + (long long)stok[r] * 1024 + gc); \
                else if (gc < 2048) av[j] = __ldcg((const uint4*)(A0 + r * 1024 + gc - 1024)); \
                else                av[j] = __ldcg((const uint4*)(A1 + r * 1024 + gc - 2048)); \
            } else {                                                                  \
                if (gc < 1024) av[j] = __ldcg((const uint4*)(A0 + r * 1024 + gc));    \
                else           av[j] = __ldcg((const uint4*)(A1 + r * 1024 + gc - 1024)); \
            }                                                                         \
            bv[j] = *(const uint4*)(B + (long long)(n0 + r) * K + gc);                \
        }                                                                             \
    }

#define STOREK(ST)                                                                    \
    {                                                                                 \
        __nv_bfloat16 (*Ad)[264] = (ST) ? As1 : As0;                                  \
        __nv_bfloat16 (*Bd)[264] = (ST) ? Bs1 : Bs0;                                  \
        _Pragma("unroll")                                                             \
        for (int j = 0; j < 4; j++) {                                                 \
            int idx = tid + j * 256; int r = idx >> 5; int c = (idx & 31) * 8;        \
            *(uint4*)&Ad[r][c] = av[j];                                               \
            *(uint4*)&Bd[r][c] = bv[j];                                               \
        }                                                                             \
    }

    LOADK(0); STOREK(0);
    __syncthreads();

    for (int si = 0; si < S; si++) {
        if (si + 1 < S) LOADK(si + 1);
        {
            __nv_bfloat16 (*As)[264] = (si & 1) ? As1 : As0;
            __nv_bfloat16 (*Bs)[264] = (si & 1) ? Bs1 : Bs0;
            const int kw = wid * 32;
#pragma unroll
            for (int ks = 0; ks < 2; ks++) {
                const int c0 = kw + ks * 16 + tg * 2;
                unsigned af[2][4];
#pragma unroll
                for (int mt = 0; mt < 2; mt++) {
                    int r = mt * 16 + g;
                    af[mt][0] = *(const unsigned*)&As[r][c0];
                    af[mt][1] = *(const unsigned*)&As[r + 8][c0];
                    af[mt][2] = *(const unsigned*)&As[r][c0 + 8];
                    af[mt][3] = *(const unsigned*)&As[r + 8][c0 + 8];
                }
#pragma unroll
                for (int nt = 0; nt < 4; nt++) {
                    int n = nt * 8 + g;
                    unsigned bf[2];
                    bf[0] = *(const unsigned*)&Bs[n][c0];
                    bf[1] = *(const unsigned*)&Bs[n][c0 + 8];
                    mma_bf16(acc[0][nt], af[0], bf);
                    mma_bf16(acc[1][nt], af[1], bf);
                }
            }
        }
        if (si + 1 < S) STOREK((si + 1) & 1);
        __syncthreads();
    }
#undef LOADK
#undef STOREK

    // cross-warp K reduce via smem (aliases stage buffers; all dead now)
    float* Pred = (float*)sm;  // [8][32][32]
    {
        int base = wid * 1024;
#pragma unroll
        for (int mt = 0; mt < 2; mt++)
#pragma unroll
            for (int nt = 0; nt < 4; nt++) {
                int r = mt * 16 + g, cl = nt * 8 + tg * 2;
                Pred[base + r * 32 + cl]           = acc[mt][nt][0];
                Pred[base + r * 32 + cl + 1]       = acc[mt][nt][1];
                Pred[base + (r + 8) * 32 + cl]     = acc[mt][nt][2];
                Pred[base + (r + 8) * 32 + cl + 1] = acc[mt][nt][3];
            }
    }
    __syncthreads();

    if (EPI == 0) {
#pragma unroll
        for (int k = 0; k < 4; k++) {
            int o = tid + k * 256;
            int r = o >> 5, c = o & 31;
            float sum = 0.f;
#pragma unroll
            for (int w = 0; w < 8; w++) sum += Pred[w * 1024 + r * 32 + c];
            outb[r * 1024 + n0 + c] = __float2bfloat16(tanhf(sum + bias[n0 + c]));
        }
    } else {
        int b = tid >> 3, ul = tid & 7;
        float gv[4];
#pragma unroll
        for (int gate = 0; gate < 4; gate++) {
            int c = ul * 4 + gate;
            float sum = 0.f;
#pragma unroll
            for (int w = 0; w < 8; w++) sum += Pred[w * 1024 + b * 32 + c];
            gv[gate] = sum + bias[n0 + c];
        }
        int u = (n0 >> 2) + ul;
        float cv = sigm(gv[1]) * cst[b * 1024 + u] + sigm(gv[0]) * tanhf(gv[2]);
        float h = sigm(gv[3]) * tanhf(cv);
        cst[b * 1024 + u] = cv;
        znew[b * 1024 + u] = __float2bfloat16(h);
        if (ZALL) zallp[(long long)(step * 32 + b) * 2048 + u] = __float2bfloat16(h);
    }
    __syncthreads();
}

__device__ void phase_attn_e(const int* __restrict__ hlens) {
    int tid = threadIdx.x, lane = tid & 31, warp = tid >> 5;
    for (int u = blockIdx.x; u < 160; u += NBLK) {
        int b = u / 5, ch = u - b * 5;
        float dqr[32];
        const uint4* dqp = (const uint4*)(g_dqb + b * 1024 + lane * 32);
#pragma unroll
        for (int q = 0; q < 4; q++) {
            uint4 v = __ldcg(dqp + q);
            __nv_bfloat162* h = (__nv_bfloat162*)&v;
#pragma unroll
            for (int k = 0; k < 4; k++) {
                float2 f = __bfloat1622float2(h[k]);
                dqr[q * 8 + k * 2] = f.x; dqr[q * 8 + k * 2 + 1] = f.y;
            }
        }
        int hl = hlens[b];
#pragma unroll 2
        for (int i = 0; i < 10; i++) {
            int t = ch * 80 + warp * 10 + i;
            const __nv_bfloat16* row = g_preb + ((long long)b * 400 + t) * 1024 + lane * 32;
            float s = 0.f;
#pragma unroll
            for (int q = 0; q < 4; q++) {
                uint4 v = *(const uint4*)(row + q * 8);
                __nv_bfloat162* h = (__nv_bfloat162*)&v;
#pragma unroll
                for (int k = 0; k < 4; k++) {
                    float2 f = __bfloat1622float2(h[k]);
                    s = fmaf(f.x, dqr[q * 8 + k * 2], s);
                    s = fmaf(f.y, dqr[q * 8 + k * 2 + 1], s);
                }
            }
#pragma unroll
            for (int off = 16; off; off >>= 1) s += __shfl_xor_sync(0xffffffffu, s, off);
            if (lane == 0) g_e[b * 400 + t] = (t < hl) ? 2.f * s : NEGBIG;
        }
    }
}

__device__ void phase_attn_c(char* sm, int s) {
    if (blockIdx.x >= 128) return;
    int b = blockIdx.x >> 2, cc = blockIdx.x & 3;
    float* ws = (float*)sm;       // 400
    float* red = ws + 400;        // 256
    int tid = threadIdx.x;
    float lm = NEGBIG;
    for (int i = tid; i < 400; i += 256) {
        float v = __ldcg(&g_e[b * 400 + i]);
        ws[i] = v; lm = fmaxf(lm, v);
    }
    red[tid] = lm; __syncthreads();
    for (int st = 128; st; st >>= 1) { if (tid < st) red[tid] = fmaxf(red[tid], red[tid + st]); __syncthreads(); }
    float m = red[0]; __syncthreads();
    float ls = 0.f;
    for (int i = tid; i < 400; i += 256) { float w = expf(ws[i] - m); ws[i] = w; ls += w; }
    red[tid] = ls; __syncthreads();
    for (int st = 128; st; st >>= 1) { if (tid < st) red[tid] += red[tid + st]; __syncthreads(); }
    float Sinv = 1.f / red[0];
    __syncthreads();
    int col = cc * 256 + tid;
    const __nv_bfloat16* hp = g_hsb + (long long)b * 400 * 1024 + col;
    float acc = 0.f;
#pragma unroll 4
    for (int t = 0; t < 400; t++) acc = fmaf(ws[t], __bfloat162float(hp[(long long)t * 1024]), acc);
    __nv_bfloat16 bv = __float2bfloat16(acc * Sinv);
    g_attb[b * 1024 + col] = bv;
    g_zallb[((long long)s * 32 + b) * 2048 + 1024 + col] = bv;
}

__global__ void __launch_bounds__(256, 1) k_loop(const int* __restrict__ hlens,
                                                 const void* __restrict__ ys,
                                                 const float* __restrict__ bdec) {
    extern __shared__ char sm[];
    const int bid = blockIdx.x;
    const int tid = threadIdx.x;
    unsigned target = 0;

    for (int s = 0; s <= 101; s++) {
        const int p = s & 1;
        // Phase A: g1(s-1) on blocks 0..127, dq(s) on blocks 128..147
        if (bid < 128) {
            if (s >= 1) {
                gemm_tile<2, 1, true>(sm, bid * 32, 2048, g_Wc1r, g_bs1r,
                                      g_z0s[p], g_z1s[1 - p],
                                      nullptr, g_c1, g_z1s[p], g_zallb, s - 1, nullptr);
            }
        } else {
            if (s <= 100) {
                for (int u = bid - 128; u < 32; u += 20) {
                    gemm_tile<0, 0, false>(sm, u * 32, 1024, g_Wdecb, bdec,
                                           g_z0s[p], nullptr,
                                           g_dqb, nullptr, nullptr, nullptr, s, nullptr);
                }
            }
        }
        gsync(target);
        if (s == 101) break;

        phase_attn_e(hlens);
        gsync(target);

        phase_attn_c(sm, s);
        gsync(target);

        // Phase D: g0(s) on blocks 0..127
        if (bid < 128) {
            int* stok = (int*)(sm + 67584);
            if (tid < 32) stok[tid] = (s == 0) ? 4999 : read_ys(ys, tid * 100 + s - 1);
            __syncthreads();
            gemm_tile<1, 1, false>(sm, bid * 32, 3072, g_Wc0r, g_bs0r,
                                   g_attb, g_z0s[p],
                                   nullptr, g_c0, g_z0s[1 - p], nullptr, s, stok);
        }
        gsync(target);
    }
}

// ----------------------------------------------------------------------------
// CE
// ----------------------------------------------------------------------------
__global__ void k_ce(const void* __restrict__ ys) {
    int r = blockIdx.x;
    int l = r / BB, b = r % BB;
    const float* y = g_yall + (long long)r * VV;
    __shared__ float red[256];
    int tid = threadIdx.x;
    float lm = NEGBIG;
    for (int v = tid; v < VV; v += 256) lm = fmaxf(lm, y[v]);
    red[tid] = lm; __syncthreads();
    for (int s = 128; s > 0; s >>= 1) { if (tid < s) red[tid] = fmaxf(red[tid], red[tid + s]); __syncthreads(); }
    float m = red[0]; __syncthreads();
    float ls = 0.f;
    for (int v = tid; v < VV; v += 256) ls += expf(y[v] - m);
    red[tid] = ls; __syncthreads();
    for (int s = 128; s > 0; s >>= 1) { if (tid < s) red[tid] += red[tid + s]; __syncthreads(); }
    if (tid == 0) {
        int tgt = (l < LL) ? read_ys(ys, b * LL + l) : 4999;
        float ce = logf(red[0]) + m - y[tgt];
        atomicAdd(&g_loss, ce);
    }
}

__global__ void k_fin(float* out) {
    out[0] = g_loss * ((float)LL / (float)(L1 * BB));
}

// ----------------------------------------------------------------------------
// Launch
// ----------------------------------------------------------------------------
extern "C" void kernel_launch(void* const* d_in, const int* in_sizes, int n_in,
                              void* d_out, int out_size) {
    const float* hs    = (const float*)d_in[0];
    const float* embed = (const float*)d_in[1];
    const float* Wenc  = (const float*)d_in[2];
    const float* benc  = (const float*)d_in[3];
    const float* Wdec  = (const float*)d_in[4];
    const float* bdec  = (const float*)d_in[5];
    const float* Wih0  = (const float*)d_in[6];
    const float* Whh0  = (const float*)d_in[7];
    const float* bih0  = (const float*)d_in[8];
    const float* bhh0  = (const float*)d_in[9];
    const float* Wih1  = (const float*)d_in[10];
    const float* Whh1  = (const float*)d_in[11];
    const float* bih1  = (const float*)d_in[12];
    const float* bhh1  = (const float*)d_in[13];
    const float* Wout  = (const float*)d_in[14];
    const float* bout  = (const float*)d_in[15];
    const int*   hlens = (const int*)d_in[16];
    const void*  ys    = (const void*)d_in[17];

    __nv_bfloat16 *hsb, *preb, *embb, *Wencb, *Wdecb, *Woutb, *zallb;
    float *yall;
    cudaGetSymbolAddress((void**)&hsb,   g_hsb);
    cudaGetSymbolAddress((void**)&preb,  g_preb);
    cudaGetSymbolAddress((void**)&embb,  g_embb);
    cudaGetSymbolAddress((void**)&Wencb, g_Wencb);
    cudaGetSymbolAddress((void**)&Wdecb, g_Wdecb);
    cudaGetSymbolAddress((void**)&Woutb, g_Woutb);
    cudaGetSymbolAddress((void**)&zallb, g_zallb);
    cudaGetSymbolAddress((void**)&yall,  g_yall);

    static int smem_set = 0;
    if (!smem_set) {
        cudaFuncSetAttribute(k_loop, cudaFuncAttributeMaxDynamicSharedMemorySize, 69632);
        smem_set = 1;
    }

    k_prep0<<<64, 256>>>(bih0, bhh0, bih1, bhh1, ys);
    k_cvt<<<512, 256>>>(hs, hsb, (long long)BB * TT * DD / 2);
    k_cvt<<<256, 256>>>(embed, embb, 5000LL * DD / 2);
    k_cvt<<<128, 256>>>(Wenc, Wencb, (long long)DD * DD / 2);
    k_cvt<<<128, 256>>>(Wdec, Wdecb, (long long)DD * DD / 2);
    k_cvt<<<512, 256>>>(Wout, Woutb, (long long)VV * 2048 / 2);
    k_reo0<<<1024, 256>>>(Wih0, Whh0);
    k_reo1<<<1024, 256>>>(Wih1, Whh1);

    // pre_enc = tanh(hs @ Wenc^T + benc) -> bf16
    mma_big<1><<<dim3(DD / 128, BB * TT / 128), 256>>>(hsb, Wencb, benc, nullptr, preb,
                                                       BB * TT, DD, DD);

    // the entire recurrent loop in one persistent kernel
    k_loop<<<NBLK, 256, 69632>>>(hlens, ys, bdec);

    // y_all = zall @ Wout^T + bout
    mma_big<0><<<dim3((VV + 127) / 128, (L1 * BB + 127) / 128), 256>>>(
        zallb, Woutb, bout, yall, nullptr, L1 * BB, VV, 2048);

    k_ce<<<L1 * BB, 256>>>(ys);
    k_fin<<<1, 1>>>((float*)d_out);
}

// round 5
// speedup vs baseline: 7.8761x; 2.4698x over previous
#include <cuda_runtime.h>
#include <cuda_bf16.h>

#define BB 32
#define TT 400
#define DD 1024
#define VV 5000
#define LL 100
#define L1 101
#define NEGBIG -1e30f
#define NBLK 148
#define SMSZ 104576
#define STOK_OFF 104448

__device__ __align__(16) __nv_bfloat16 g_hsb [BB * TT * DD];
__device__ __align__(16) __nv_bfloat16 g_preb[BB * TT * DD];
__device__ __align__(16) __nv_bfloat16 g_embb[5000 * DD];
__device__ __align__(16) __nv_bfloat16 g_Wencb[DD * DD];
__device__ __align__(16) __nv_bfloat16 g_Wdecb[DD * DD];
__device__ __align__(16) __nv_bfloat16 g_Woutb[VV * 2048];
__device__ __align__(16) __nv_bfloat16 g_Wc0r[4096 * 3072];
__device__ __align__(16) __nv_bfloat16 g_Wc1r[4096 * 2048];
__device__ __align__(16) float g_bs0r[4096];
__device__ __align__(16) float g_bs1r[4096];
__device__ __align__(16) __nv_bfloat16 g_dqb[BB * DD];
__device__ __align__(16) __nv_bfloat16 g_attb[BB * DD];
__device__ __align__(16) __nv_bfloat16 g_z0s[2][BB * DD];
__device__ __align__(16) __nv_bfloat16 g_z1s[2][BB * DD];
__device__ __align__(16) float g_c0[BB * DD];
__device__ __align__(16) float g_c1[BB * DD];
__device__ __align__(16) float g_pc[128 * 1024];
__device__ __align__(16) float g_ms[256];
__device__ unsigned g_cmb[32];
__device__ __align__(16) __nv_bfloat16 g_zallb[L1 * BB * 2048];
__device__ __align__(16) float g_yall[(long long)L1 * BB * VV];
__device__ float g_loss;
__device__ int g_i64;
__device__ unsigned g_arrive;
__device__ unsigned g_release;

__device__ __forceinline__ float sigm(float x) { return 1.0f / (1.0f + expf(-x)); }
__device__ __forceinline__ int read_ys(const void* ys, int i) {
    return g_i64 ? (int)((const long long*)ys)[i] : ((const int*)ys)[i];
}
__device__ __forceinline__ unsigned sptr(const void* p) {
    unsigned r;
    asm("{.reg .u64 t; cvta.to.shared.u64 t, %1; cvt.u32.u64 %0, t;}" : "=r"(r) : "l"(p));
    return r;
}
__device__ __forceinline__ void cpa16(unsigned s, const void* g) {
    asm volatile("cp.async.cg.shared.global [%0], [%1], 16;" :: "r"(s), "l"(g));
}
#define CP_COMMIT asm volatile("cp.async.commit_group;")
#define CP_WAIT2  asm volatile("cp.async.wait_group 2;")

// ---------------------------------------------------------------- prep
__global__ void k_prep0(const float* __restrict__ bih0, const float* __restrict__ bhh0,
                        const float* __restrict__ bih1, const float* __restrict__ bhh1,
                        const void* __restrict__ ys) {
    int i = blockIdx.x * blockDim.x + threadIdx.x;
    int n = gridDim.x * blockDim.x;
    __nv_bfloat16 z = __float2bfloat16(0.f);
    for (int j = i; j < BB * DD; j += n) {
        g_c0[j] = 0.f; g_c1[j] = 0.f;
        g_z0s[0][j] = z; g_z0s[1][j] = z;
        g_z1s[0][j] = z; g_z1s[1][j] = z;
    }
    for (int j = i; j < 4096; j += n) {
        int u = j >> 2, gate = j & 3;
        int orow = gate * 1024 + u;
        g_bs0r[j] = bih0[orow] + bhh0[orow];
        g_bs1r[j] = bih1[orow] + bhh1[orow];
    }
    if (i < 32) g_cmb[i] = 0u;
    if (i == 0) {
        g_loss = 0.f; g_arrive = 0u; g_release = 0u;
        const int* w = (const int*)ys;
        int f = 1;
        for (int j = 1; j < 64; j += 2) if (w[j] != 0) f = 0;
        g_i64 = f;
    }
}

__global__ void k_cvt(const float* __restrict__ s, __nv_bfloat16* __restrict__ d, long long n2) {
    long long i = (long long)blockIdx.x * blockDim.x + threadIdx.x;
    long long st = (long long)gridDim.x * blockDim.x;
    const float2* s2 = (const float2*)s;
    __nv_bfloat162* d2 = (__nv_bfloat162*)d;
    for (long long j = i; j < n2; j += st) {
        float2 v = s2[j];
        d2[j] = __floats2bfloat162_rn(v.x, v.y);
    }
}

__global__ void k_reo0(const float* __restrict__ Wih, const float* __restrict__ Whh) {
    long long N = 4096LL * 3072;
    long long i = (long long)blockIdx.x * blockDim.x + threadIdx.x;
    long long st = (long long)gridDim.x * blockDim.x;
    for (long long j = i; j < N; j += st) {
        int r = (int)(j / 3072), c = (int)(j % 3072);
        long long orow = (r & 3) * 1024 + (r >> 2);
        float v = (c < 2048) ? Wih[orow * 2048 + c] : Whh[orow * 1024 + (c - 2048)];
        g_Wc0r[j] = __float2bfloat16(v);
    }
}
__global__ void k_reo1(const float* __restrict__ Wih, const float* __restrict__ Whh) {
    long long N = 4096LL * 2048;
    long long i = (long long)blockIdx.x * blockDim.x + threadIdx.x;
    long long st = (long long)gridDim.x * blockDim.x;
    for (long long j = i; j < N; j += st) {
        int r = (int)(j / 2048), c = (int)(j % 2048);
        long long orow = (r & 3) * 1024 + (r >> 2);
        float v = (c < 1024) ? Wih[orow * 1024 + c] : Whh[orow * 1024 + (c - 1024)];
        g_Wc1r[j] = __float2bfloat16(v);
    }
}

__device__ __forceinline__ void mma_bf16(float* d, const unsigned* a, const unsigned* b) {
    asm volatile(
        "mma.sync.aligned.m16n8k16.row.col.f32.bf16.bf16.f32 "
        "{%0,%1,%2,%3}, {%4,%5,%6,%7}, {%8,%9}, {%0,%1,%2,%3};\n"
        : "+f"(d[0]), "+f"(d[1]), "+f"(d[2]), "+f"(d[3])
        : "r"(a[0]), "r"(a[1]), "r"(a[2]), "r"(a[3]), "r"(b[0]), "r"(b[1]));
}

// ---------------------------------------------------------------- big GEMM
template <int EPI>
__global__ __launch_bounds__(256) void mma_big(
    const __nv_bfloat16* __restrict__ A, const __nv_bfloat16* __restrict__ B,
    const float* __restrict__ bias, float* __restrict__ Cf,
    __nv_bfloat16* __restrict__ Cb, int M, int N, int K)
{
    constexpr int BKP = 40;
    __shared__ __nv_bfloat16 As[128][BKP];
    __shared__ __nv_bfloat16 Bs[128][BKP];
    const int tid = threadIdx.x, lane = tid & 31, wid = tid >> 5;
    const int wm = wid >> 1, wn = wid & 1;
    const int m0 = blockIdx.y * 128, n0 = blockIdx.x * 128;
    const int g = lane >> 2, tg = lane & 3;

    float acc[2][8][4];
#pragma unroll
    for (int a = 0; a < 2; a++)
#pragma unroll
        for (int b = 0; b < 8; b++)
#pragma unroll
            for (int c = 0; c < 4; c++) acc[a][b][c] = 0.f;

    int ar[2], ac[2];
#pragma unroll
    for (int t = 0; t < 2; t++) { int s = tid + t * 256; ar[t] = s >> 2; ac[t] = (s & 3) * 8; }

    uint4 pa[2], pb[2];
#pragma unroll
    for (int t = 0; t < 2; t++) {
        int m = m0 + ar[t];
        pa[t] = (m < M) ? *(const uint4*)(A + (long long)m * K + ac[t]) : make_uint4(0, 0, 0, 0);
        int n = n0 + ar[t];
        pb[t] = (n < N) ? *(const uint4*)(B + (long long)n * K + ac[t]) : make_uint4(0, 0, 0, 0);
    }
#pragma unroll
    for (int t = 0; t < 2; t++) {
        *(uint2*)&As[ar[t]][ac[t]]     = make_uint2(pa[t].x, pa[t].y);
        *(uint2*)&As[ar[t]][ac[t] + 4] = make_uint2(pa[t].z, pa[t].w);
        *(uint2*)&Bs[ar[t]][ac[t]]     = make_uint2(pb[t].x, pb[t].y);
        *(uint2*)&Bs[ar[t]][ac[t] + 4] = make_uint2(pb[t].z, pb[t].w);
    }
    __syncthreads();

    const int niter = K >> 5;
    for (int it = 0; it < niter; it++) {
        if (it + 1 < niter) {
            int k0 = (it + 1) << 5;
#pragma unroll
            for (int t = 0; t < 2; t++) {
                int m = m0 + ar[t];
                pa[t] = (m < M) ? *(const uint4*)(A + (long long)m * K + k0 + ac[t]) : make_uint4(0, 0, 0, 0);
                int n = n0 + ar[t];
                pb[t] = (n < N) ? *(const uint4*)(B + (long long)n * K + k0 + ac[t]) : make_uint4(0, 0, 0, 0);
            }
        }
#pragma unroll
        for (int kt = 0; kt < 2; kt++) {
            const int c0 = kt * 16 + tg * 2;
            unsigned af[2][4];
#pragma unroll
            for (int mt = 0; mt < 2; mt++) {
                int r = wm * 32 + mt * 16 + g;
                af[mt][0] = *(const unsigned*)&As[r][c0];
                af[mt][1] = *(const unsigned*)&As[r + 8][c0];
                af[mt][2] = *(const unsigned*)&As[r][c0 + 8];
                af[mt][3] = *(const unsigned*)&As[r + 8][c0 + 8];
            }
#pragma unroll
            for (int nt = 0; nt < 8; nt++) {
                int n = wn * 64 + nt * 8 + g;
                unsigned bf[2];
                bf[0] = *(const unsigned*)&Bs[n][c0];
                bf[1] = *(const unsigned*)&Bs[n][c0 + 8];
                mma_bf16(acc[0][nt], af[0], bf);
                mma_bf16(acc[1][nt], af[1], bf);
            }
        }
        __syncthreads();
        if (it + 1 < niter) {
#pragma unroll
            for (int t = 0; t < 2; t++) {
                *(uint2*)&As[ar[t]][ac[t]]     = make_uint2(pa[t].x, pa[t].y);
                *(uint2*)&As[ar[t]][ac[t] + 4] = make_uint2(pa[t].z, pa[t].w);
                *(uint2*)&Bs[ar[t]][ac[t]]     = make_uint2(pb[t].x, pb[t].y);
                *(uint2*)&Bs[ar[t]][ac[t] + 4] = make_uint2(pb[t].z, pb[t].w);
            }
            __syncthreads();
        }
    }

#pragma unroll
    for (int mt = 0; mt < 2; mt++) {
#pragma unroll
        for (int nt = 0; nt < 8; nt++) {
            int r = m0 + wm * 32 + mt * 16 + g;
            int c = n0 + wn * 64 + nt * 8 + tg * 2;
            float* a = acc[mt][nt];
            if (EPI == 0) {
                float b0 = (c < N) ? bias[c] : 0.f;
                float b1 = (c + 1 < N) ? bias[c + 1] : 0.f;
                if (r < M) {
                    if (c < N)     Cf[(long long)r * N + c]     = a[0] + b0;
                    if (c + 1 < N) Cf[(long long)r * N + c + 1] = a[1] + b1;
                }
                if (r + 8 < M) {
                    if (c < N)     Cf[(long long)(r + 8) * N + c]     = a[2] + b0;
                    if (c + 1 < N) Cf[(long long)(r + 8) * N + c + 1] = a[3] + b1;
                }
            } else {
                float b0 = bias[c], b1 = bias[c + 1];
                __nv_bfloat162 v0 = __floats2bfloat162_rn(tanhf(a[0] + b0), tanhf(a[1] + b1));
                __nv_bfloat162 v1 = __floats2bfloat162_rn(tanhf(a[2] + b0), tanhf(a[3] + b1));
                *(__nv_bfloat162*)(Cb + (long long)r * N + c) = v0;
                *(__nv_bfloat162*)(Cb + (long long)(r + 8) * N + c) = v1;
            }
        }
    }
}

// ---------------------------------------------------------------- barrier
__device__ __forceinline__ void gbar(int e) {
    __syncthreads();
    if (threadIdx.x == 0) {
        __threadfence();
        unsigned old = atomicAdd(&g_arrive, 1u);
        if (old == (unsigned)e * NBLK + (NBLK - 1)) {
            atomicExch(&g_release, (unsigned)(e + 1));
        } else {
            unsigned r;
            do { asm volatile("ld.global.cg.u32 %0, [%1];" : "=r"(r) : "l"(&g_release)); }
            while (r < (unsigned)(e + 1));
        }
        __threadfence();
    }
    __syncthreads();
}

// ---------------------------------------------------------------- tile GEMM
// C[32 x NT*8] at cols [n0, ...); 8 warps split K (16 K each per 128-chunk).
// AKIND: 0=A0; 1=[emb(stok)|A0|A1]; 2=[A0|A1]. EPI: 0=tanh->outb; 1=LSTM (NT=4).
template <int AKIND, int NT>
__device__ __forceinline__ void issue_chunk(
    char* smraw, int stage, int kc, int K,
    const __nv_bfloat16* A0, const __nv_bfloat16* A1,
    const __nv_bfloat16* B, int n0, const int* stok)
{
    constexpr int ASZ = 32 * 136;
    constexpr int STE = ASZ + NT * 8 * 136;
    __nv_bfloat16* smA = (__nv_bfloat16*)smraw + stage * STE;
    __nv_bfloat16* smB = smA + ASZ;
    const int tid = threadIdx.x;
    const int kbase = kc << 7;
    const int region = kbase >> 10;
    const int koff = kbase & 1023;
#pragma unroll
    for (int j = 0; j < 2; j++) {
        int u = tid + j * 256;
        int r = u >> 4, c = (u & 15) << 3;
        const __nv_bfloat16* src;
        if (AKIND == 0) src = A0 + r * 1024 + kbase + c;
        else if (AKIND == 1) {
            if (region == 0)      src = g_embb + (long long)stok[r] * 1024 + koff + c;
            else if (region == 1) src = A0 + r * 1024 + koff + c;
            else                  src = A1 + r * 1024 + koff + c;
        } else src = (region == 0 ? A0 : A1) + r * 1024 + koff + c;
        cpa16(sptr(smA + r * 136 + c), src);
    }
#pragma unroll
    for (int j = 0; j < (NT >> 1); j++) {
        int u = tid + j * 256;
        int r = u >> 4, c = (u & 15) << 3;
        cpa16(sptr(smB + r * 136 + c), B + (long long)(n0 + r) * K + kbase + c);
    }
}

template <int AKIND, int EPI, int NT, bool ZALL>
__device__ void gtile(char* smraw, int n0, int K,
                      const __nv_bfloat16* __restrict__ B, const float* __restrict__ bias,
                      const __nv_bfloat16* A0, const __nv_bfloat16* A1,
                      __nv_bfloat16* outb, float* cst, __nv_bfloat16* znew,
                      __nv_bfloat16* zallp, int step, const int* stok)
{
    constexpr int ASZ = 32 * 136;
    constexpr int STE = ASZ + NT * 8 * 136;
    constexpr int NW = 32 * NT * 8;
    const int tid = threadIdx.x, lane = tid & 31, wid = tid >> 5;
    const int g = lane >> 2, tg = lane & 3;
    const int S = K >> 7;

    float acc[2][NT][4];
#pragma unroll
    for (int a = 0; a < 2; a++)
#pragma unroll
        for (int b = 0; b < NT; b++)
#pragma unroll
            for (int c = 0; c < 4; c++) acc[a][b][c] = 0.f;

#pragma unroll
    for (int st = 0; st < 3; st++) {
        if (st < S) issue_chunk<AKIND, NT>(smraw, st, st, K, A0, A1, B, n0, stok);
        CP_COMMIT;
    }

    for (int si = 0; si < S; si++) {
        CP_WAIT2;
        __syncthreads();
        int nx = si + 3;
        if (nx < S) issue_chunk<AKIND, NT>(smraw, nx & 3, nx, K, A0, A1, B, n0, stok);
        CP_COMMIT;
        __nv_bfloat16 (*As)[136] = (__nv_bfloat16(*)[136])((__nv_bfloat16*)smraw + (si & 3) * STE);
        __nv_bfloat16 (*Bs)[136] = (__nv_bfloat16(*)[136])((__nv_bfloat16*)smraw + (si & 3) * STE + ASZ);
        const int c0 = wid * 16 + tg * 2;
        unsigned af[2][4];
#pragma unroll
        for (int mt = 0; mt < 2; mt++) {
            int r = mt * 16 + g;
            af[mt][0] = *(const unsigned*)&As[r][c0];
            af[mt][1] = *(const unsigned*)&As[r + 8][c0];
            af[mt][2] = *(const unsigned*)&As[r][c0 + 8];
            af[mt][3] = *(const unsigned*)&As[r + 8][c0 + 8];
        }
#pragma unroll
        for (int nt = 0; nt < NT; nt++) {
            int n = nt * 8 + g;
            unsigned bf[2];
            bf[0] = *(const unsigned*)&Bs[n][c0];
            bf[1] = *(const unsigned*)&Bs[n][c0 + 8];
            mma_bf16(acc[0][nt], af[0], bf);
            mma_bf16(acc[1][nt], af[1], bf);
        }
    }
    __syncthreads();

    float* Pred = (float*)smraw;
    {
        int base = wid * NW;
#pragma unroll
        for (int mt = 0; mt < 2; mt++)
#pragma unroll
            for (int nt = 0; nt < NT; nt++) {
                int r = mt * 16 + g, cl = nt * 8 + tg * 2;
                Pred[base + r * (NT * 8) + cl]           = acc[mt][nt][0];
                Pred[base + r * (NT * 8) + cl + 1]       = acc[mt][nt][1];
                Pred[base + (r + 8) * (NT * 8) + cl]     = acc[mt][nt][2];
                Pred[base + (r + 8) * (NT * 8) + cl + 1] = acc[mt][nt][3];
            }
    }
    __syncthreads();

    if (EPI == 0) {
        for (int o = tid; o < NW; o += 256) {
            int r = o / (NT * 8), c = o % (NT * 8);
            float sum = 0.f;
#pragma unroll
            for (int w = 0; w < 8; w++) sum += Pred[w * NW + o];
            outb[r * 1024 + n0 + c] = __float2bfloat16(tanhf(sum + bias[n0 + c]));
        }
    } else {
        int b = tid >> 3, ul = tid & 7;
        float gv[4];
#pragma unroll
        for (int gate = 0; gate < 4; gate++) {
            int col = ul * 4 + gate;
            float sum = 0.f;
#pragma unroll
            for (int w = 0; w < 8; w++) sum += Pred[w * 1024 + b * 32 + col];
            gv[gate] = sum + bias[n0 + col];
        }
        int u = (n0 >> 2) + ul;
        int gid = b * 1024 + u;
        float cv = sigm(gv[1]) * cst[gid] + sigm(gv[0]) * tanhf(gv[2]);
        float h = sigm(gv[3]) * tanhf(cv);
        cst[gid] = cv;
        znew[gid] = __float2bfloat16(h);
        if (ZALL) zallp[(long long)(step * 32 + b) * 2048 + u] = __float2bfloat16(h);
    }
    __syncthreads();
}

// ---------------------------------------------------------------- attention
__device__ void phase_epc(char* smraw, int s, const int* __restrict__ hlens) {
    const int bid = blockIdx.x;
    if (bid >= 128) return;
    const int b = bid >> 2, ch = bid & 3;
    const int t0 = ch * 100;
    const int tid = threadIdx.x, lane = tid & 31, wid = tid >> 5;
    float* dqs = (float*)smraw;
    float* ws  = dqs + 1024;
    float* red = ws + 104;
    float* pcr = red + 256;
    int*   flg = (int*)(pcr + 8192);

    const uint4* dqp = (const uint4*)(g_dqb + b * 1024);
    for (int j = tid; j < 128; j += 256) {
        uint4 v = __ldcg(dqp + j);
        const __nv_bfloat162* h = (const __nv_bfloat162*)&v;
#pragma unroll
        for (int k = 0; k < 4; k++) {
            float2 f = __bfloat1622float2(h[k]);
            dqs[j * 8 + k * 2]     = f.x;
            dqs[j * 8 + k * 2 + 1] = f.y;
        }
    }
    __syncthreads();

    const int hl = hlens[b];
    for (int tl = wid; tl < 100; tl += 8) {
        int t = t0 + tl;
        const __nv_bfloat16* row = g_preb + ((long long)b * 400 + t) * 1024 + lane * 8;
        float sa = 0.f;
#pragma unroll
        for (int q = 0; q < 4; q++) {
            uint4 v = *(const uint4*)(row + q * 256);
            const __nv_bfloat162* h = (const __nv_bfloat162*)&v;
#pragma unroll
            for (int k = 0; k < 4; k++) {
                float2 f = __bfloat1622float2(h[k]);
                sa = fmaf(f.x, dqs[q * 256 + lane * 8 + k * 2], sa);
                sa = fmaf(f.y, dqs[q * 256 + lane * 8 + k * 2 + 1], sa);
            }
        }
#pragma unroll
        for (int off = 16; off; off >>= 1) sa += __shfl_xor_sync(0xffffffffu, sa, off);
        if (lane == 0) ws[tl] = (t < hl) ? 2.f * sa : NEGBIG;
    }
    __syncthreads();

    float lm = NEGBIG;
    for (int i = tid; i < 100; i += 256) lm = fmaxf(lm, ws[i]);
    red[tid] = lm; __syncthreads();
    for (int st = 128; st; st >>= 1) { if (tid < st) red[tid] = fmaxf(red[tid], red[tid + st]); __syncthreads(); }
    const float m = red[0]; __syncthreads();
    float ls = 0.f;
    for (int i = tid; i < 100; i += 256) { float w = expf(ws[i] - m); ws[i] = w; ls += w; }
    red[tid] = ls; __syncthreads();
    for (int st = 128; st; st >>= 1) { if (tid < st) red[tid] += red[tid + st]; __syncthreads(); }
    const float sl = red[0];
    __syncthreads();

    float pacc[32];
#pragma unroll
    for (int i = 0; i < 32; i++) pacc[i] = 0.f;
    for (int tl = wid; tl < 100; tl += 8) {
        float w = ws[tl];
        const __nv_bfloat16* row = g_hsb + ((long long)b * 400 + t0 + tl) * 1024 + lane * 8;
#pragma unroll
        for (int q = 0; q < 4; q++) {
            uint4 v = *(const uint4*)(row + q * 256);
            const __nv_bfloat162* h = (const __nv_bfloat162*)&v;
#pragma unroll
            for (int k = 0; k < 4; k++) {
                float2 f = __bfloat1622float2(h[k]);
                pacc[q * 8 + k * 2]     = fmaf(w, f.x, pacc[q * 8 + k * 2]);
                pacc[q * 8 + k * 2 + 1] = fmaf(w, f.y, pacc[q * 8 + k * 2 + 1]);
            }
        }
    }
#pragma unroll
    for (int q = 0; q < 4; q++)
#pragma unroll
        for (int j = 0; j < 8; j++)
            pcr[wid * 1024 + q * 256 + lane * 8 + j] = pacc[q * 8 + j];
    __syncthreads();
    for (int col = tid; col < 1024; col += 256) {
        float a = 0.f;
#pragma unroll
        for (int w = 0; w < 8; w++) a += pcr[w * 1024 + col];
        g_pc[bid * 1024 + col] = a;
    }
    if (tid == 0) { g_ms[bid * 2] = m; g_ms[bid * 2 + 1] = sl; }
    __syncthreads();

    if (tid == 0) {
        __threadfence();
        unsigned old = atomicAdd(&g_cmb[b], 1u);
        *flg = (old == (unsigned)(s * 4 + 3)) ? 1 : 0;
    }
    __syncthreads();
    if (*flg) {
        float mi[4], si[4];
#pragma unroll
        for (int i = 0; i < 4; i++) {
            mi[i] = __ldcg(&g_ms[(b * 4 + i) * 2]);
            si[i] = __ldcg(&g_ms[(b * 4 + i) * 2 + 1]);
        }
        float M = fmaxf(fmaxf(mi[0], mi[1]), fmaxf(mi[2], mi[3]));
        float sc[4], Ssum = 0.f;
#pragma unroll
        for (int i = 0; i < 4; i++) { sc[i] = expf(mi[i] - M); Ssum += sc[i] * si[i]; }
        float inv = 1.f / Ssum;
        for (int col = tid; col < 1024; col += 256) {
            float a = 0.f;
#pragma unroll
            for (int i = 0; i < 4; i++) a += sc[i] * __ldcg(&g_pc[(b * 4 + i) * 1024 + col]);
            __nv_bfloat16 v = __float2bfloat16(a * inv);
            g_attb[b * 1024 + col] = v;
            g_zallb[((long long)s * 32 + b) * 2048 + 1024 + col] = v;
        }
    }
    __syncthreads();
}

// ---------------------------------------------------------------- main loop
__global__ void __launch_bounds__(256, 1) k_loop(const int* __restrict__ hlens,
                                                 const void* __restrict__ ys,
                                                 const float* __restrict__ bdec) {
    extern __shared__ char sm[];
    const int bid = blockIdx.x;
    int ep = 0;

    for (int s = 0; s <= 101; s++) {
        const int p = s & 1;
        if (bid < 128) {
            if (s >= 1)
                gtile<2, 1, 4, true>(sm, bid * 32, 2048, g_Wc1r, g_bs1r,
                                     g_z0s[p], g_z1s[1 - p],
                                     nullptr, g_c1, g_z1s[p], g_zallb, s - 1, nullptr);
        } else if (bid < 144) {
            if (s <= 100)
                gtile<0, 0, 8, false>(sm, (bid - 128) * 64, 1024, g_Wdecb, bdec,
                                      g_z0s[p], nullptr,
                                      g_dqb, nullptr, nullptr, nullptr, s, nullptr);
        }
        gbar(ep); ep++;
        if (s == 101) break;

        phase_epc(sm, s, hlens);
        gbar(ep); ep++;

        if (bid < 128) {
            int* stok = (int*)(sm + STOK_OFF);
            if (threadIdx.x < 32)
                stok[threadIdx.x] = (s == 0) ? 4999 : read_ys(ys, threadIdx.x * 100 + s - 1);
            __syncthreads();
            gtile<1, 1, 4, false>(sm, bid * 32, 3072, g_Wc0r, g_bs0r,
                                  g_attb, g_z0s[p],
                                  nullptr, g_c0, g_z0s[1 - p], nullptr, s, stok);
        }
        gbar(ep); ep++;
    }
}

// ---------------------------------------------------------------- CE
__global__ void k_ce(const void* __restrict__ ys) {
    int r = blockIdx.x;
    int l = r / BB, b = r % BB;
    const float* y = g_yall + (long long)r * VV;
    __shared__ float red[256];
    int tid = threadIdx.x;
    float lm = NEGBIG;
    for (int v = tid; v < VV; v += 256) lm = fmaxf(lm, y[v]);
    red[tid] = lm; __syncthreads();
    for (int s = 128; s > 0; s >>= 1) { if (tid < s) red[tid] = fmaxf(red[tid], red[tid + s]); __syncthreads(); }
    float m = red[0]; __syncthreads();
    float ls = 0.f;
    for (int v = tid; v < VV; v += 256) ls += expf(y[v] - m);
    red[tid] = ls; __syncthreads();
    for (int s = 128; s > 0; s >>= 1) { if (tid < s) red[tid] += red[tid + s]; __syncthreads(); }
    if (tid == 0) {
        int tgt = (l < LL) ? read_ys(ys, b * LL + l) : 4999;
        atomicAdd(&g_loss, logf(red[0]) + m - y[tgt]);
    }
}

__global__ void k_fin(float* out) {
    out[0] = g_loss * ((float)LL / (float)(L1 * BB));
}

// ---------------------------------------------------------------- launch
extern "C" void kernel_launch(void* const* d_in, const int* in_sizes, int n_in,
                              void* d_out, int out_size) {
    const float* hs    = (const float*)d_in[0];
    const float* embed = (const float*)d_in[1];
    const float* Wenc  = (const float*)d_in[2];
    const float* benc  = (const float*)d_in[3];
    const float* Wdec  = (const float*)d_in[4];
    const float* bdec  = (const float*)d_in[5];
    const float* Wih0  = (const float*)d_in[6];
    const float* Whh0  = (const float*)d_in[7];
    const float* bih0  = (const float*)d_in[8];
    const float* bhh0  = (const float*)d_in[9];
    const float* Wih1  = (const float*)d_in[10];
    const float* Whh1  = (const float*)d_in[11];
    const float* bih1  = (const float*)d_in[12];
    const float* bhh1  = (const float*)d_in[13];
    const float* Wout  = (const float*)d_in[14];
    const float* bout  = (const float*)d_in[15];
    const int*   hlens = (const int*)d_in[16];
    const void*  ys    = (const void*)d_in[17];

    __nv_bfloat16 *hsb, *preb, *embb, *Wencb, *Woutb, *zallb;
    float *yall;
    cudaGetSymbolAddress((void**)&hsb,   g_hsb);
    cudaGetSymbolAddress((void**)&preb,  g_preb);
    cudaGetSymbolAddress((void**)&embb,  g_embb);
    cudaGetSymbolAddress((void**)&Wencb, g_Wencb);
    cudaGetSymbolAddress((void**)&Woutb, g_Woutb);
    cudaGetSymbolAddress((void**)&zallb, g_zallb);
    cudaGetSymbolAddress((void**)&yall,  g_yall);
    __nv_bfloat16 *Wdecb;
    cudaGetSymbolAddress((void**)&Wdecb, g_Wdecb);

    static int smem_set = 0;
    if (!smem_set) {
        cudaFuncSetAttribute(k_loop, cudaFuncAttributeMaxDynamicSharedMemorySize, SMSZ);
        smem_set = 1;
    }

    k_prep0<<<64, 256>>>(bih0, bhh0, bih1, bhh1, ys);
    k_cvt<<<512, 256>>>(hs, hsb, (long long)BB * TT * DD / 2);
    k_cvt<<<256, 256>>>(embed, embb, 5000LL * DD / 2);
    k_cvt<<<128, 256>>>(Wenc, Wencb, (long long)DD * DD / 2);
    k_cvt<<<128, 256>>>(Wdec, Wdecb, (long long)DD * DD / 2);
    k_cvt<<<512, 256>>>(Wout, Woutb, (long long)VV * 2048 / 2);
    k_reo0<<<1024, 256>>>(Wih0, Whh0);
    k_reo1<<<1024, 256>>>(Wih1, Whh1);

    mma_big<1><<<dim3(DD / 128, BB * TT / 128), 256>>>(hsb, Wencb, benc, nullptr, preb,
                                                       BB * TT, DD, DD);

    k_loop<<<NBLK, 256, SMSZ>>>(hlens, ys, bdec);

    mma_big<0><<<dim3((VV + 127) / 128, (L1 * BB + 127) / 128), 256>>>(
        zallb, Woutb, bout, yall, nullptr, L1 * BB, VV, 2048);

    k_ce<<<L1 * BB, 256>>>(ys);
    k_fin<<<1, 1>>>((float*)d_out);
}

// round 6
// speedup vs baseline: 8.6121x; 1.0935x over previous
#include <cuda_runtime.h>
#include <cuda_bf16.h>

#define BB 32
#define TT 400
#define DD 1024
#define VV 5000
#define LL 100
#define L1 101
#define NEGBIG -1e30f
#define NBLK 148
// smem: 4 slots x (A 32x264 + B up-to-64x264) bf16 = 202752B, + stok
#define STOK_OFF 202752
#define SMSZ 202880

__device__ __align__(16) __nv_bfloat16 g_hsb [BB * TT * DD];
__device__ __align__(16) __nv_bfloat16 g_preb[BB * TT * DD];
__device__ __align__(16) __nv_bfloat16 g_embb[5000 * DD];
__device__ __align__(16) __nv_bfloat16 g_Wencb[DD * DD];
__device__ __align__(16) __nv_bfloat16 g_Wdecb[DD * DD];
__device__ __align__(16) __nv_bfloat16 g_Woutb[VV * 2048];
__device__ __align__(16) __nv_bfloat16 g_Wc0r[4096 * 3072];
__device__ __align__(16) __nv_bfloat16 g_Wc1r[4096 * 2048];
__device__ __align__(16) float g_bs0r[4096];
__device__ __align__(16) float g_bs1r[4096];
__device__ __align__(16) __nv_bfloat16 g_dqb[BB * DD];
__device__ __align__(16) __nv_bfloat16 g_attb[BB * DD];
__device__ __align__(16) __nv_bfloat16 g_z0s[2][BB * DD];
__device__ __align__(16) __nv_bfloat16 g_z1s[2][BB * DD];
__device__ __align__(16) float g_c0[BB * DD];
__device__ __align__(16) float g_c1[BB * DD];
__device__ __align__(16) float g_pc[128 * 1024];
__device__ __align__(16) float g_ms[256];
__device__ unsigned g_cmb[32];
__device__ __align__(16) __nv_bfloat16 g_zallb[L1 * BB * 2048];
__device__ __align__(16) float g_yall[(long long)L1 * BB * VV];
__device__ float g_loss;
__device__ int g_i64;
__device__ unsigned g_arrive;
__device__ unsigned g_release;

__device__ __forceinline__ float sigm(float x) { return 1.0f / (1.0f + expf(-x)); }
__device__ __forceinline__ int read_ys(const void* ys, int i) {
    return g_i64 ? (int)((const long long*)ys)[i] : ((const int*)ys)[i];
}
__device__ __forceinline__ unsigned sptr(const void* p) {
    unsigned r;
    asm("{.reg .u64 t; cvta.to.shared.u64 t, %1; cvt.u32.u64 %0, t;}" : "=r"(r) : "l"(p));
    return r;
}
__device__ __forceinline__ void cpa16(unsigned s, const void* g) {
    asm volatile("cp.async.cg.shared.global [%0], [%1], 16;" :: "r"(s), "l"(g));
}
#define CP_COMMIT asm volatile("cp.async.commit_group;")
#define CP_WAIT2  asm volatile("cp.async.wait_group 2;")

__device__ __forceinline__ unsigned pack2(float a, float b) {
    __nv_bfloat162 p = __floats2bfloat162_rn(a, b);
    return *(unsigned*)&p;
}

// ---------------------------------------------------------------- prep
__global__ void k_prep0(const float* __restrict__ bih0, const float* __restrict__ bhh0,
                        const float* __restrict__ bih1, const float* __restrict__ bhh1,
                        const void* __restrict__ ys) {
    int i = blockIdx.x * blockDim.x + threadIdx.x;
    int n = gridDim.x * blockDim.x;
    __nv_bfloat16 z = __float2bfloat16(0.f);
    for (int j = i; j < BB * DD; j += n) {
        g_c0[j] = 0.f; g_c1[j] = 0.f;
        g_z0s[0][j] = z; g_z0s[1][j] = z;
        g_z1s[0][j] = z; g_z1s[1][j] = z;
    }
    for (int j = i; j < 4096; j += n) {
        int u = j >> 2, gate = j & 3;
        int orow = gate * 1024 + u;
        g_bs0r[j] = bih0[orow] + bhh0[orow];
        g_bs1r[j] = bih1[orow] + bhh1[orow];
    }
    if (i < 32) g_cmb[i] = 0u;
    if (i == 0) {
        g_loss = 0.f; g_arrive = 0u; g_release = 0u;
        const int* w = (const int*)ys;
        int f = 1;
        for (int j = 1; j < 64; j += 2) if (w[j] != 0) f = 0;
        g_i64 = f;
    }
}

// fp32 -> bf16, 8 elems/thread-iter (2x float4 in, uint4 out)
__global__ void k_cvt8(const float4* __restrict__ s, uint4* __restrict__ d, long long n8) {
    long long i = (long long)blockIdx.x * blockDim.x + threadIdx.x;
    long long st = (long long)gridDim.x * blockDim.x;
    for (long long j = i; j < n8; j += st) {
        float4 a = s[2 * j], b = s[2 * j + 1];
        d[j] = make_uint4(pack2(a.x, a.y), pack2(a.z, a.w),
                          pack2(b.x, b.y), pack2(b.z, b.w));
    }
}

__global__ void k_reo0(const float* __restrict__ Wih, const float* __restrict__ Whh) {
    long long N4 = 4096LL * 3072 / 4;
    long long i = (long long)blockIdx.x * blockDim.x + threadIdx.x;
    long long st = (long long)gridDim.x * blockDim.x;
    for (long long j4 = i; j4 < N4; j4 += st) {
        long long j = j4 * 4;
        int r = (int)(j / 3072), c = (int)(j % 3072);
        long long orow = (r & 3) * 1024 + (r >> 2);
        float4 v = (c < 2048) ? *(const float4*)(Wih + orow * 2048 + c)
                              : *(const float4*)(Whh + orow * 1024 + (c - 2048));
        *(uint2*)(g_Wc0r + j) = make_uint2(pack2(v.x, v.y), pack2(v.z, v.w));
    }
}
__global__ void k_reo1(const float* __restrict__ Wih, const float* __restrict__ Whh) {
    long long N4 = 4096LL * 2048 / 4;
    long long i = (long long)blockIdx.x * blockDim.x + threadIdx.x;
    long long st = (long long)gridDim.x * blockDim.x;
    for (long long j4 = i; j4 < N4; j4 += st) {
        long long j = j4 * 4;
        int r = (int)(j / 2048), c = (int)(j % 2048);
        long long orow = (r & 3) * 1024 + (r >> 2);
        float4 v = (c < 1024) ? *(const float4*)(Wih + orow * 1024 + c)
                              : *(const float4*)(Whh + orow * 1024 + (c - 1024));
        *(uint2*)(g_Wc1r + j) = make_uint2(pack2(v.x, v.y), pack2(v.z, v.w));
    }
}

__device__ __forceinline__ void mma_bf16(float* d, const unsigned* a, const unsigned* b) {
    asm volatile(
        "mma.sync.aligned.m16n8k16.row.col.f32.bf16.bf16.f32 "
        "{%0,%1,%2,%3}, {%4,%5,%6,%7}, {%8,%9}, {%0,%1,%2,%3};\n"
        : "+f"(d[0]), "+f"(d[1]), "+f"(d[2]), "+f"(d[3])
        : "r"(a[0]), "r"(a[1]), "r"(a[2]), "r"(a[3]), "r"(b[0]), "r"(b[1]));
}

// ---------------------------------------------------------------- big GEMM
template <int EPI>
__global__ __launch_bounds__(256) void mma_big(
    const __nv_bfloat16* __restrict__ A, const __nv_bfloat16* __restrict__ B,
    const float* __restrict__ bias, float* __restrict__ Cf,
    __nv_bfloat16* __restrict__ Cb, int M, int N, int K)
{
    constexpr int BKP = 40;
    __shared__ __nv_bfloat16 As[128][BKP];
    __shared__ __nv_bfloat16 Bs[128][BKP];
    const int tid = threadIdx.x, lane = tid & 31, wid = tid >> 5;
    const int wm = wid >> 1, wn = wid & 1;
    const int m0 = blockIdx.y * 128, n0 = blockIdx.x * 128;
    const int g = lane >> 2, tg = lane & 3;

    float acc[2][8][4];
#pragma unroll
    for (int a = 0; a < 2; a++)
#pragma unroll
        for (int b = 0; b < 8; b++)
#pragma unroll
            for (int c = 0; c < 4; c++) acc[a][b][c] = 0.f;

    int ar[2], ac[2];
#pragma unroll
    for (int t = 0; t < 2; t++) { int s = tid + t * 256; ar[t] = s >> 2; ac[t] = (s & 3) * 8; }

    uint4 pa[2], pb[2];
#pragma unroll
    for (int t = 0; t < 2; t++) {
        int m = m0 + ar[t];
        pa[t] = (m < M) ? *(const uint4*)(A + (long long)m * K + ac[t]) : make_uint4(0, 0, 0, 0);
        int n = n0 + ar[t];
        pb[t] = (n < N) ? *(const uint4*)(B + (long long)n * K + ac[t]) : make_uint4(0, 0, 0, 0);
    }
#pragma unroll
    for (int t = 0; t < 2; t++) {
        *(uint2*)&As[ar[t]][ac[t]]     = make_uint2(pa[t].x, pa[t].y);
        *(uint2*)&As[ar[t]][ac[t] + 4] = make_uint2(pa[t].z, pa[t].w);
        *(uint2*)&Bs[ar[t]][ac[t]]     = make_uint2(pb[t].x, pb[t].y);
        *(uint2*)&Bs[ar[t]][ac[t] + 4] = make_uint2(pb[t].z, pb[t].w);
    }
    __syncthreads();

    const int niter = K >> 5;
    for (int it = 0; it < niter; it++) {
        if (it + 1 < niter) {
            int k0 = (it + 1) << 5;
#pragma unroll
            for (int t = 0; t < 2; t++) {
                int m = m0 + ar[t];
                pa[t] = (m < M) ? *(const uint4*)(A + (long long)m * K + k0 + ac[t]) : make_uint4(0, 0, 0, 0);
                int n = n0 + ar[t];
                pb[t] = (n < N) ? *(const uint4*)(B + (long long)n * K + k0 + ac[t]) : make_uint4(0, 0, 0, 0);
            }
        }
#pragma unroll
        for (int kt = 0; kt < 2; kt++) {
            const int c0 = kt * 16 + tg * 2;
            unsigned af[2][4];
#pragma unroll
            for (int mt = 0; mt < 2; mt++) {
                int r = wm * 32 + mt * 16 + g;
                af[mt][0] = *(const unsigned*)&As[r][c0];
                af[mt][1] = *(const unsigned*)&As[r + 8][c0];
                af[mt][2] = *(const unsigned*)&As[r][c0 + 8];
                af[mt][3] = *(const unsigned*)&As[r + 8][c0 + 8];
            }
#pragma unroll
            for (int nt = 0; nt < 8; nt++) {
                int n = wn * 64 + nt * 8 + g;
                unsigned bf[2];
                bf[0] = *(const unsigned*)&Bs[n][c0];
                bf[1] = *(const unsigned*)&Bs[n][c0 + 8];
                mma_bf16(acc[0][nt], af[0], bf);
                mma_bf16(acc[1][nt], af[1], bf);
            }
        }
        __syncthreads();
        if (it + 1 < niter) {
#pragma unroll
            for (int t = 0; t < 2; t++) {
                *(uint2*)&As[ar[t]][ac[t]]     = make_uint2(pa[t].x, pa[t].y);
                *(uint2*)&As[ar[t]][ac[t] + 4] = make_uint2(pa[t].z, pa[t].w);
                *(uint2*)&Bs[ar[t]][ac[t]]     = make_uint2(pb[t].x, pb[t].y);
                *(uint2*)&Bs[ar[t]][ac[t] + 4] = make_uint2(pb[t].z, pb[t].w);
            }
            __syncthreads();
        }
    }

#pragma unroll
    for (int mt = 0; mt < 2; mt++) {
#pragma unroll
        for (int nt = 0; nt < 8; nt++) {
            int r = m0 + wm * 32 + mt * 16 + g;
            int c = n0 + wn * 64 + nt * 8 + tg * 2;
            float* a = acc[mt][nt];
            if (EPI == 0) {
                float b0 = (c < N) ? bias[c] : 0.f;
                float b1 = (c + 1 < N) ? bias[c + 1] : 0.f;
                if (r < M) {
                    if (c < N)     Cf[(long long)r * N + c]     = a[0] + b0;
                    if (c + 1 < N) Cf[(long long)r * N + c + 1] = a[1] + b1;
                }
                if (r + 8 < M) {
                    if (c < N)     Cf[(long long)(r + 8) * N + c]     = a[2] + b0;
                    if (c + 1 < N) Cf[(long long)(r + 8) * N + c + 1] = a[3] + b1;
                }
            } else {
                float b0 = bias[c], b1 = bias[c + 1];
                __nv_bfloat162 v0 = __floats2bfloat162_rn(tanhf(a[0] + b0), tanhf(a[1] + b1));
                __nv_bfloat162 v1 = __floats2bfloat162_rn(tanhf(a[2] + b0), tanhf(a[3] + b1));
                *(__nv_bfloat162*)(Cb + (long long)r * N + c) = v0;
                *(__nv_bfloat162*)(Cb + (long long)(r + 8) * N + c) = v1;
            }
        }
    }
}

// ---------------------------------------------------------------- barrier
__device__ __forceinline__ void gbar(int e) {
    __syncthreads();
    if (threadIdx.x == 0) {
        __threadfence();
        unsigned old = atomicAdd(&g_arrive, 1u);
        if (old == (unsigned)e * NBLK + (NBLK - 1)) {
            atomicExch(&g_release, (unsigned)(e + 1));
        } else {
            unsigned r;
            do { asm volatile("ld.global.cg.u32 %0, [%1];" : "=r"(r) : "l"(&g_release)); }
            while (r < (unsigned)(e + 1));
        }
        __threadfence();
    }
    __syncthreads();
}

// ---------------------------------------------------------------- tile GEMM
// K-chunk = 256. 4 smem slots, 3 in flight. 8 warps split K (32 K each/chunk).
// AKIND: 0=A0; 1=[emb(stok)|A0|A1]; 2=[A0|A1]. EPI: 0=tanh->outb; 1=LSTM (NT=4).
template <int AKIND, int NT>
__device__ __forceinline__ void issue_chunk(
    char* smraw, int slot, int kc, int K,
    const __nv_bfloat16* A0, const __nv_bfloat16* A1,
    const __nv_bfloat16* B, int n0, const int* stok)
{
    constexpr int ASZ = 32 * 264;
    constexpr int STE = ASZ + NT * 8 * 264;
    __nv_bfloat16* smA = (__nv_bfloat16*)smraw + slot * STE;
    __nv_bfloat16* smB = smA + ASZ;
    const int tid = threadIdx.x;
    const int kbase = kc << 8;
    const int region = kbase >> 10;
    const int koff = kbase & 1023;
#pragma unroll
    for (int j = 0; j < 4; j++) {
        int u = tid + j * 256;
        int r = u >> 5, c = (u & 31) << 3;
        const __nv_bfloat16* src;
        if (AKIND == 0) src = A0 + r * 1024 + kbase + c;
        else if (AKIND == 1) {
            if (region == 0)      src = g_embb + (long long)stok[r] * 1024 + koff + c;
            else if (region == 1) src = A0 + r * 1024 + koff + c;
            else                  src = A1 + r * 1024 + koff + c;
        } else src = (region == 0 ? A0 : A1) + r * 1024 + koff + c;
        cpa16(sptr(smA + r * 264 + c), src);
    }
#pragma unroll
    for (int j = 0; j < NT; j++) {
        int u = tid + j * 256;
        int r = u >> 5, c = (u & 31) << 3;
        cpa16(sptr(smB + r * 264 + c), B + (long long)(n0 + r) * K + kbase + c);
    }
}

template <int AKIND, int EPI, int NT, bool ZALL>
__device__ void gtile(char* smraw, int n0, int K,
                      const __nv_bfloat16* __restrict__ B, const float* __restrict__ bias,
                      const __nv_bfloat16* A0, const __nv_bfloat16* A1,
                      __nv_bfloat16* outb, float* cst, __nv_bfloat16* znew,
                      __nv_bfloat16* zallp, int step, const int* stok)
{
    constexpr int ASZ = 32 * 264;
    constexpr int STE = ASZ + NT * 8 * 264;
    constexpr int NW = 32 * NT * 8;
    const int tid = threadIdx.x, lane = tid & 31, wid = tid >> 5;
    const int g = lane >> 2, tg = lane & 3;
    const int S = K >> 8;

    float acc[2][NT][4];
#pragma unroll
    for (int a = 0; a < 2; a++)
#pragma unroll
        for (int b = 0; b < NT; b++)
#pragma unroll
            for (int c = 0; c < 4; c++) acc[a][b][c] = 0.f;

#pragma unroll
    for (int st = 0; st < 3; st++) {
        if (st < S) issue_chunk<AKIND, NT>(smraw, st, st, K, A0, A1, B, n0, stok);
        CP_COMMIT;
    }

    for (int si = 0; si < S; si++) {
        CP_WAIT2;
        __syncthreads();
        int nx = si + 3;
        if (nx < S) issue_chunk<AKIND, NT>(smraw, nx & 3, nx, K, A0, A1, B, n0, stok);
        CP_COMMIT;
        __nv_bfloat16 (*As)[264] = (__nv_bfloat16(*)[264])((__nv_bfloat16*)smraw + (si & 3) * STE);
        __nv_bfloat16 (*Bs)[264] = (__nv_bfloat16(*)[264])((__nv_bfloat16*)smraw + (si & 3) * STE + ASZ);
#pragma unroll
        for (int ks = 0; ks < 2; ks++) {
            const int c0 = wid * 32 + ks * 16 + tg * 2;
            unsigned af[2][4];
#pragma unroll
            for (int mt = 0; mt < 2; mt++) {
                int r = mt * 16 + g;
                af[mt][0] = *(const unsigned*)&As[r][c0];
                af[mt][1] = *(const unsigned*)&As[r + 8][c0];
                af[mt][2] = *(const unsigned*)&As[r][c0 + 8];
                af[mt][3] = *(const unsigned*)&As[r + 8][c0 + 8];
            }
#pragma unroll
            for (int nt = 0; nt < NT; nt++) {
                int n = nt * 8 + g;
                unsigned bf[2];
                bf[0] = *(const unsigned*)&Bs[n][c0];
                bf[1] = *(const unsigned*)&Bs[n][c0 + 8];
                mma_bf16(acc[0][nt], af[0], bf);
                mma_bf16(acc[1][nt], af[1], bf);
            }
        }
    }
    __syncthreads();

    float* Pred = (float*)smraw;
    {
        int base = wid * NW;
#pragma unroll
        for (int mt = 0; mt < 2; mt++)
#pragma unroll
            for (int nt = 0; nt < NT; nt++) {
                int r = mt * 16 + g, cl = nt * 8 + tg * 2;
                Pred[base + r * (NT * 8) + cl]           = acc[mt][nt][0];
                Pred[base + r * (NT * 8) + cl + 1]       = acc[mt][nt][1];
                Pred[base + (r + 8) * (NT * 8) + cl]     = acc[mt][nt][2];
                Pred[base + (r + 8) * (NT * 8) + cl + 1] = acc[mt][nt][3];
            }
    }
    __syncthreads();

    if (EPI == 0) {
        for (int o = tid; o < NW; o += 256) {
            int r = o / (NT * 8), c = o % (NT * 8);
            float sum = 0.f;
#pragma unroll
            for (int w = 0; w < 8; w++) sum += Pred[w * NW + o];
            outb[r * 1024 + n0 + c] = __float2bfloat16(tanhf(sum + bias[n0 + c]));
        }
    } else {
        int b = tid >> 3, ul = tid & 7;
        float gv[4];
#pragma unroll
        for (int gate = 0; gate < 4; gate++) {
            int col = ul * 4 + gate;
            float sum = 0.f;
#pragma unroll
            for (int w = 0; w < 8; w++) sum += Pred[w * 1024 + b * 32 + col];
            gv[gate] = sum + bias[n0 + col];
        }
        int u = (n0 >> 2) + ul;
        int gid = b * 1024 + u;
        float cv = sigm(gv[1]) * cst[gid] + sigm(gv[0]) * tanhf(gv[2]);
        float h = sigm(gv[3]) * tanhf(cv);
        cst[gid] = cv;
        znew[gid] = __float2bfloat16(h);
        if (ZALL) zallp[(long long)(step * 32 + b) * 2048 + u] = __float2bfloat16(h);
    }
    __syncthreads();
}

// ---------------------------------------------------------------- attention
__device__ void phase_epc(char* smraw, int s, const int* __restrict__ hlens) {
    const int bid = blockIdx.x;
    if (bid >= 128) return;
    const int b = bid >> 2, ch = bid & 3;
    const int t0 = ch * 100;
    const int tid = threadIdx.x, lane = tid & 31, wid = tid >> 5;
    float* dqs = (float*)smraw;
    float* ws  = dqs + 1024;
    float* red = ws + 104;
    float* pcr = red + 256;
    int*   flg = (int*)(pcr + 8192);

    const uint4* dqp = (const uint4*)(g_dqb + b * 1024);
    for (int j = tid; j < 128; j += 256) {
        uint4 v = __ldcg(dqp + j);
        const __nv_bfloat162* h = (const __nv_bfloat162*)&v;
#pragma unroll
        for (int k = 0; k < 4; k++) {
            float2 f = __bfloat1622float2(h[k]);
            dqs[j * 8 + k * 2]     = f.x;
            dqs[j * 8 + k * 2 + 1] = f.y;
        }
    }
    __syncthreads();

    const int hl = hlens[b];
    for (int tl = wid; tl < 100; tl += 8) {
        int t = t0 + tl;
        const __nv_bfloat16* row = g_preb + ((long long)b * 400 + t) * 1024 + lane * 8;
        float sa = 0.f;
#pragma unroll
        for (int q = 0; q < 4; q++) {
            uint4 v = *(const uint4*)(row + q * 256);
            const __nv_bfloat162* h = (const __nv_bfloat162*)&v;
#pragma unroll
            for (int k = 0; k < 4; k++) {
                float2 f = __bfloat1622float2(h[k]);
                sa = fmaf(f.x, dqs[q * 256 + lane * 8 + k * 2], sa);
                sa = fmaf(f.y, dqs[q * 256 + lane * 8 + k * 2 + 1], sa);
            }
        }
#pragma unroll
        for (int off = 16; off; off >>= 1) sa += __shfl_xor_sync(0xffffffffu, sa, off);
        if (lane == 0) ws[tl] = (t < hl) ? 2.f * sa : NEGBIG;
    }
    __syncthreads();

    float lm = NEGBIG;
    for (int i = tid; i < 100; i += 256) lm = fmaxf(lm, ws[i]);
    red[tid] = lm; __syncthreads();
    for (int st = 128; st; st >>= 1) { if (tid < st) red[tid] = fmaxf(red[tid], red[tid + st]); __syncthreads(); }
    const float m = red[0]; __syncthreads();
    float ls = 0.f;
    for (int i = tid; i < 100; i += 256) { float w = expf(ws[i] - m); ws[i] = w; ls += w; }
    red[tid] = ls; __syncthreads();
    for (int st = 128; st; st >>= 1) { if (tid < st) red[tid] += red[tid + st]; __syncthreads(); }
    const float sl = red[0];
    __syncthreads();

    float pacc[32];
#pragma unroll
    for (int i = 0; i < 32; i++) pacc[i] = 0.f;
    for (int tl = wid; tl < 100; tl += 8) {
        float w = ws[tl];
        const __nv_bfloat16* row = g_hsb + ((long long)b * 400 + t0 + tl) * 1024 + lane * 8;
#pragma unroll
        for (int q = 0; q < 4; q++) {
            uint4 v = *(const uint4*)(row + q * 256);
            const __nv_bfloat162* h = (const __nv_bfloat162*)&v;
#pragma unroll
            for (int k = 0; k < 4; k++) {
                float2 f = __bfloat1622float2(h[k]);
                pacc[q * 8 + k * 2]     = fmaf(w, f.x, pacc[q * 8 + k * 2]);
                pacc[q * 8 + k * 2 + 1] = fmaf(w, f.y, pacc[q * 8 + k * 2 + 1]);
            }
        }
    }
#pragma unroll
    for (int q = 0; q < 4; q++)
#pragma unroll
        for (int j = 0; j < 8; j++)
            pcr[wid * 1024 + q * 256 + lane * 8 + j] = pacc[q * 8 + j];
    __syncthreads();
    for (int col = tid; col < 1024; col += 256) {
        float a = 0.f;
#pragma unroll
        for (int w = 0; w < 8; w++) a += pcr[w * 1024 + col];
        g_pc[bid * 1024 + col] = a;
    }
    if (tid == 0) { g_ms[bid * 2] = m; g_ms[bid * 2 + 1] = sl; }
    __syncthreads();

    if (tid == 0) {
        __threadfence();
        unsigned old = atomicAdd(&g_cmb[b], 1u);
        *flg = (old == (unsigned)(s * 4 + 3)) ? 1 : 0;
    }
    __syncthreads();
    if (*flg) {
        float mi[4], si[4];
#pragma unroll
        for (int i = 0; i < 4; i++) {
            mi[i] = __ldcg(&g_ms[(b * 4 + i) * 2]);
            si[i] = __ldcg(&g_ms[(b * 4 + i) * 2 + 1]);
        }
        float M = fmaxf(fmaxf(mi[0], mi[1]), fmaxf(mi[2], mi[3]));
        float sc[4], Ssum = 0.f;
#pragma unroll
        for (int i = 0; i < 4; i++) { sc[i] = expf(mi[i] - M); Ssum += sc[i] * si[i]; }
        float inv = 1.f / Ssum;
        for (int col = tid; col < 1024; col += 256) {
            float a = 0.f;
#pragma unroll
            for (int i = 0; i < 4; i++) a += sc[i] * __ldcg(&g_pc[(b * 4 + i) * 1024 + col]);
            __nv_bfloat16 v = __float2bfloat16(a * inv);
            g_attb[b * 1024 + col] = v;
            g_zallb[((long long)s * 32 + b) * 2048 + 1024 + col] = v;
        }
    }
    __syncthreads();
}

// ---------------------------------------------------------------- main loop
__global__ void __launch_bounds__(256, 1) k_loop(const int* __restrict__ hlens,
                                                 const void* __restrict__ ys,
                                                 const float* __restrict__ bdec) {
    extern __shared__ char sm[];
    const int bid = blockIdx.x;
    int ep = 0;

    for (int s = 0; s <= 101; s++) {
        const int p = s & 1;
        if (bid < 128) {
            if (s >= 1)
                gtile<2, 1, 4, true>(sm, bid * 32, 2048, g_Wc1r, g_bs1r,
                                     g_z0s[p], g_z1s[1 - p],
                                     nullptr, g_c1, g_z1s[p], g_zallb, s - 1, nullptr);
        } else if (bid < 144) {
            if (s <= 100)
                gtile<0, 0, 8, false>(sm, (bid - 128) * 64, 1024, g_Wdecb, bdec,
                                      g_z0s[p], nullptr,
                                      g_dqb, nullptr, nullptr, nullptr, s, nullptr);
        }
        gbar(ep); ep++;
        if (s == 101) break;

        phase_epc(sm, s, hlens);
        gbar(ep); ep++;

        if (bid < 128) {
            int* stok = (int*)(sm + STOK_OFF);
            if (threadIdx.x < 32)
                stok[threadIdx.x] = (s == 0) ? 4999 : read_ys(ys, threadIdx.x * 100 + s - 1);
            __syncthreads();
            gtile<1, 1, 4, false>(sm, bid * 32, 3072, g_Wc0r, g_bs0r,
                                  g_attb, g_z0s[p],
                                  nullptr, g_c0, g_z0s[1 - p], nullptr, s, stok);
        }
        gbar(ep); ep++;
    }
}

// ---------------------------------------------------------------- CE
__global__ void k_ce(const void* __restrict__ ys) {
    int r = blockIdx.x;
    int l = r / BB, b = r % BB;
    const float* y = g_yall + (long long)r * VV;
    __shared__ float red[256];
    int tid = threadIdx.x;
    float lm = NEGBIG;
    for (int v = tid; v < VV; v += 256) lm = fmaxf(lm, y[v]);
    red[tid] = lm; __syncthreads();
    for (int s = 128; s > 0; s >>= 1) { if (tid < s) red[tid] = fmaxf(red[tid], red[tid + s]); __syncthreads(); }
    float m = red[0]; __syncthreads();
    float ls = 0.f;
    for (int v = tid; v < VV; v += 256) ls += expf(y[v] - m);
    red[tid] = ls; __syncthreads();
    for (int s = 128; s > 0; s >>= 1) { if (tid < s) red[tid] += red[tid + s]; __syncthreads(); }
    if (tid == 0) {
        int tgt = (l < LL) ? read_ys(ys, b * LL + l) : 4999;
        atomicAdd(&g_loss, logf(red[0]) + m - y[tgt]);
    }
}

__global__ void k_fin(float* out) {
    out[0] = g_loss * ((float)LL / (float)(L1 * BB));
}

// ---------------------------------------------------------------- launch
extern "C" void kernel_launch(void* const* d_in, const int* in_sizes, int n_in,
                              void* d_out, int out_size) {
    const float* hs    = (const float*)d_in[0];
    const float* embed = (const float*)d_in[1];
    const float* Wenc  = (const float*)d_in[2];
    const float* benc  = (const float*)d_in[3];
    const float* Wdec  = (const float*)d_in[4];
    const float* bdec  = (const float*)d_in[5];
    const float* Wih0  = (const float*)d_in[6];
    const float* Whh0  = (const float*)d_in[7];
    const float* bih0  = (const float*)d_in[8];
    const float* bhh0  = (const float*)d_in[9];
    const float* Wih1  = (const float*)d_in[10];
    const float* Whh1  = (const float*)d_in[11];
    const float* bih1  = (const float*)d_in[12];
    const float* bhh1  = (const float*)d_in[13];
    const float* Wout  = (const float*)d_in[14];
    const float* bout  = (const float*)d_in[15];
    const int*   hlens = (const int*)d_in[16];
    const void*  ys    = (const void*)d_in[17];

    __nv_bfloat16 *hsb, *preb, *embb, *Wencb, *Wdecb, *Woutb, *zallb;
    float *yall;
    cudaGetSymbolAddress((void**)&hsb,   g_hsb);
    cudaGetSymbolAddress((void**)&preb,  g_preb);
    cudaGetSymbolAddress((void**)&embb,  g_embb);
    cudaGetSymbolAddress((void**)&Wencb, g_Wencb);
    cudaGetSymbolAddress((void**)&Wdecb, g_Wdecb);
    cudaGetSymbolAddress((void**)&Woutb, g_Woutb);
    cudaGetSymbolAddress((void**)&zallb, g_zallb);
    cudaGetSymbolAddress((void**)&yall,  g_yall);

    static int smem_set = 0;
    if (!smem_set) {
        cudaFuncSetAttribute(k_loop, cudaFuncAttributeMaxDynamicSharedMemorySize, SMSZ);
        smem_set = 1;
    }

    k_prep0<<<64, 256>>>(bih0, bhh0, bih1, bhh1, ys);
    k_cvt8<<<1184, 256>>>((const float4*)hs, (uint4*)hsb, (long long)BB * TT * DD / 8);
    k_cvt8<<<640, 256>>>((const float4*)embed, (uint4*)embb, 5000LL * DD / 8);
    k_cvt8<<<512, 256>>>((const float4*)Wenc, (uint4*)Wencb, (long long)DD * DD / 8);
    k_cvt8<<<512, 256>>>((const float4*)Wdec, (uint4*)Wdecb, (long long)DD * DD / 8);
    k_cvt8<<<1184, 256>>>((const float4*)Wout, (uint4*)Woutb, (long long)VV * 2048 / 8);
    k_reo0<<<1536, 256>>>(Wih0, Whh0);
    k_reo1<<<1024, 256>>>(Wih1, Whh1);

    mma_big<1><<<dim3(DD / 128, BB * TT / 128), 256>>>(hsb, Wencb, benc, nullptr, preb,
                                                       BB * TT, DD, DD);

    k_loop<<<NBLK, 256, SMSZ>>>(hlens, ys, bdec);

    mma_big<0><<<dim3((VV + 127) / 128, (L1 * BB + 127) / 128), 256>>>(
        zallb, Woutb, bout, yall, nullptr, L1 * BB, VV, 2048);

    k_ce<<<L1 * BB, 256>>>(ys);
    k_fin<<<1, 1>>>((float*)d_out);
}

// round 7
// speedup vs baseline: 10.6937x; 1.2417x over previous
#include <cuda_runtime.h>
#include <cuda_bf16.h>

#define BB 32
#define TT 400
#define DD 1024
#define VV 5000
#define LL 100
#define L1 101
#define NEGBIG -1e30f
#define NBLK 148
#define SMSZ 202752
#define BIG_SMEM 110592

__device__ __align__(16) __nv_bfloat16 g_hsb [BB * TT * DD];
__device__ __align__(16) __nv_bfloat16 g_preb[BB * TT * DD];
__device__ __align__(16) __nv_bfloat16 g_eysb[L1 * BB * DD];
__device__ __align__(16) __nv_bfloat16 g_Wencb[DD * DD];
__device__ __align__(16) __nv_bfloat16 g_Wdecb[DD * DD];
__device__ __align__(16) __nv_bfloat16 g_Woutb[VV * 2048];
__device__ __align__(16) __nv_bfloat16 g_Wc0e[4096 * 1024];
__device__ __align__(16) __nv_bfloat16 g_Wc0x[4096 * 2048];
__device__ __align__(16) __nv_bfloat16 g_Wc1r[4096 * 2048];
__device__ __align__(16) float g_bs0r[4096];
__device__ __align__(16) float g_bs1r[4096];
__device__ __align__(16) float g_emb0[(long long)L1 * BB * 4096];
__device__ __align__(16) __nv_bfloat16 g_dqb[BB * DD];
__device__ __align__(16) __nv_bfloat16 g_attb[BB * DD];
__device__ __align__(16) __nv_bfloat16 g_z0s[2][BB * DD];
__device__ __align__(16) __nv_bfloat16 g_z1s[2][BB * DD];
__device__ __align__(16) float g_c0[BB * DD];
__device__ __align__(16) float g_c1[BB * DD];
__device__ __align__(16) float g_pc[128 * 1024];
__device__ __align__(16) float g_ms[256];
__device__ unsigned g_cmb[32];
__device__ __align__(16) __nv_bfloat16 g_zallb[L1 * BB * 2048];
__device__ __align__(16) float g_yall[(long long)L1 * BB * VV];
__device__ float g_loss;
__device__ int g_i64;
__device__ unsigned g_arrive;
__device__ unsigned g_release;

__device__ __forceinline__ float sigm(float x) { return 1.0f / (1.0f + expf(-x)); }
__device__ __forceinline__ int read_ys(const void* ys, int i) {
    return g_i64 ? (int)((const long long*)ys)[i] : ((const int*)ys)[i];
}
__device__ __forceinline__ unsigned sptr(const void* p) {
    unsigned r;
    asm("{.reg .u64 t; cvta.to.shared.u64 t, %1; cvt.u32.u64 %0, t;}" : "=r"(r) : "l"(p));
    return r;
}
__device__ __forceinline__ void cpa16(unsigned s, const void* g) {
    asm volatile("cp.async.cg.shared.global [%0], [%1], 16;" :: "r"(s), "l"(g));
}
#define CP_COMMIT asm volatile("cp.async.commit_group;")
#define CP_WAIT2  asm volatile("cp.async.wait_group 2;")
#define CP_WAIT1  asm volatile("cp.async.wait_group 1;")

__device__ __forceinline__ unsigned pack2(float a, float b) {
    __nv_bfloat162 p = __floats2bfloat162_rn(a, b);
    return *(unsigned*)&p;
}

// ---------------------------------------------------------------- prep
__global__ void k_prep0(const float* __restrict__ bih0, const float* __restrict__ bhh0,
                        const float* __restrict__ bih1, const float* __restrict__ bhh1,
                        const void* __restrict__ ys) {
    int i = blockIdx.x * blockDim.x + threadIdx.x;
    int n = gridDim.x * blockDim.x;
    __nv_bfloat16 z = __float2bfloat16(0.f);
    for (int j = i; j < BB * DD; j += n) {
        g_c0[j] = 0.f; g_c1[j] = 0.f;
        g_z0s[0][j] = z; g_z0s[1][j] = z;
        g_z1s[0][j] = z; g_z1s[1][j] = z;
    }
    for (int j = i; j < 4096; j += n) {
        int u = j >> 2, gate = j & 3;
        int orow = gate * 1024 + u;
        g_bs0r[j] = bih0[orow] + bhh0[orow];
        g_bs1r[j] = bih1[orow] + bhh1[orow];
    }
    if (i < 32) g_cmb[i] = 0u;
    if (i == 0) {
        g_loss = 0.f; g_arrive = 0u; g_release = 0u;
        const int* w = (const int*)ys;
        int f = 1;
        for (int j = 1; j < 64; j += 2) if (w[j] != 0) f = 0;
        g_i64 = f;
    }
}

__global__ void k_cvt8(const float4* __restrict__ s, uint4* __restrict__ d, long long n8) {
    long long i = (long long)blockIdx.x * blockDim.x + threadIdx.x;
    long long st = (long long)gridDim.x * blockDim.x;
    for (long long j = i; j < n8; j += st) {
        float4 a = s[2 * j], b = s[2 * j + 1];
        d[j] = make_uint4(pack2(a.x, a.y), pack2(a.z, a.w),
                          pack2(b.x, b.y), pack2(b.z, b.w));
    }
}

// gather teacher-forced embeddings -> bf16 rows [l*32+b][1024]
__global__ void k_gath(const float* __restrict__ embed, const void* __restrict__ ys) {
    int row = blockIdx.x;
    int l = row >> 5, b = row & 31;
    int tok = (l == 0) ? 4999 : read_ys(ys, b * LL + l - 1);
    const float4* src = (const float4*)(embed + (long long)tok * 1024);
    uint2* dst = (uint2*)(g_eysb + (long long)row * 1024);
    int j = threadIdx.x;
    float4 v = src[j];
    dst[j] = make_uint2(pack2(v.x, v.y), pack2(v.z, v.w));
}

// gate-interleaved weight reorders
__global__ void k_reo0(const float* __restrict__ Wih, const float* __restrict__ Whh) {
    long long Ne = 4096LL * 1024 / 4, Nx = 4096LL * 2048 / 4;
    long long i = (long long)blockIdx.x * blockDim.x + threadIdx.x;
    long long st = (long long)gridDim.x * blockDim.x;
    for (long long j4 = i; j4 < Ne; j4 += st) {
        long long j = j4 * 4;
        int r = (int)(j >> 10), c = (int)(j & 1023);
        long long orow = (r & 3) * 1024 + (r >> 2);
        float4 v = *(const float4*)(Wih + orow * 2048 + c);
        *(uint2*)(g_Wc0e + j) = make_uint2(pack2(v.x, v.y), pack2(v.z, v.w));
    }
    for (long long j4 = i; j4 < Nx; j4 += st) {
        long long j = j4 * 4;
        int r = (int)(j >> 11), c = (int)(j & 2047);
        long long orow = (r & 3) * 1024 + (r >> 2);
        float4 v = (c < 1024) ? *(const float4*)(Wih + orow * 2048 + 1024 + c)
                              : *(const float4*)(Whh + orow * 1024 + (c - 1024));
        *(uint2*)(g_Wc0x + j) = make_uint2(pack2(v.x, v.y), pack2(v.z, v.w));
    }
}
__global__ void k_reo1(const float* __restrict__ Wih, const float* __restrict__ Whh) {
    long long N4 = 4096LL * 2048 / 4;
    long long i = (long long)blockIdx.x * blockDim.x + threadIdx.x;
    long long st = (long long)gridDim.x * blockDim.x;
    for (long long j4 = i; j4 < N4; j4 += st) {
        long long j = j4 * 4;
        int r = (int)(j >> 11), c = (int)(j & 2047);
        long long orow = (r & 3) * 1024 + (r >> 2);
        float4 v = (c < 1024) ? *(const float4*)(Wih + orow * 1024 + c)
                              : *(const float4*)(Whh + orow * 1024 + (c - 1024));
        *(uint2*)(g_Wc1r + j) = make_uint2(pack2(v.x, v.y), pack2(v.z, v.w));
    }
}

__device__ __forceinline__ void mma_bf16(float* d, const unsigned* a, const unsigned* b) {
    asm volatile(
        "mma.sync.aligned.m16n8k16.row.col.f32.bf16.bf16.f32 "
        "{%0,%1,%2,%3}, {%4,%5,%6,%7}, {%8,%9}, {%0,%1,%2,%3};\n"
        : "+f"(d[0]), "+f"(d[1]), "+f"(d[2]), "+f"(d[3])
        : "r"(a[0]), "r"(a[1]), "r"(a[2]), "r"(a[3]), "r"(b[0]), "r"(b[1]));
}

// ---------------------------------------------------------------- big GEMM
// BM=BN=128, BK=64, 3-stage cp.async. 8 warps (4m x 2n), warp tile 32x64.
// EPI 0: fp32 out + bias. EPI 1: tanh -> bf16 out + bias.
#define BKP 72
__device__ __forceinline__ void issue_big(
    char* smb, int slot, int k0,
    const __nv_bfloat16* A, const __nv_bfloat16* B,
    int M, int N, int K, int m0, int n0)
{
    __nv_bfloat16* smA = (__nv_bfloat16*)smb + slot * (2 * 128 * BKP);
    __nv_bfloat16* smB = smA + 128 * BKP;
    const int tid = threadIdx.x;
#pragma unroll
    for (int j = 0; j < 4; j++) {
        int idx = tid + j * 256;
        int r = idx >> 3, c = (idx & 7) * 8;
        int m = m0 + r; if (m >= M) m = 0;
        cpa16(sptr(smA + r * BKP + c), A + (long long)m * K + k0 + c);
        int n = n0 + r; if (n >= N) n = 0;
        cpa16(sptr(smB + r * BKP + c), B + (long long)n * K + k0 + c);
    }
}

template <int EPI>
__global__ __launch_bounds__(256) void mma_big(
    const __nv_bfloat16* __restrict__ A, const __nv_bfloat16* __restrict__ B,
    const float* __restrict__ bias, float* __restrict__ Cf,
    __nv_bfloat16* __restrict__ Cb, int M, int N, int K)
{
    extern __shared__ char smb[];
    const int tid = threadIdx.x, lane = tid & 31, wid = tid >> 5;
    const int wm = wid >> 1, wn = wid & 1;
    const int m0 = blockIdx.y * 128, n0 = blockIdx.x * 128;
    const int g = lane >> 2, tg = lane & 3;
    const int S = K >> 6;

    float acc[2][8][4];
#pragma unroll
    for (int a = 0; a < 2; a++)
#pragma unroll
        for (int b = 0; b < 8; b++)
#pragma unroll
            for (int c = 0; c < 4; c++) acc[a][b][c] = 0.f;

    issue_big(smb, 0, 0, A, B, M, N, K, m0, n0); CP_COMMIT;
    if (S > 1) issue_big(smb, 1, 64, A, B, M, N, K, m0, n0);
    CP_COMMIT;

    for (int si = 0; si < S; si++) {
        CP_WAIT1;
        __syncthreads();
        if (si + 2 < S) issue_big(smb, (si + 2) % 3, (si + 2) << 6, A, B, M, N, K, m0, n0);
        CP_COMMIT;
        __nv_bfloat16 (*As)[BKP] = (__nv_bfloat16(*)[BKP])((__nv_bfloat16*)smb + (si % 3) * (2 * 128 * BKP));
        __nv_bfloat16 (*Bs)[BKP] = (__nv_bfloat16(*)[BKP])((__nv_bfloat16*)smb + (si % 3) * (2 * 128 * BKP) + 128 * BKP);
#pragma unroll
        for (int kt = 0; kt < 4; kt++) {
            const int c0 = kt * 16 + tg * 2;
            unsigned af[2][4];
#pragma unroll
            for (int mt = 0; mt < 2; mt++) {
                int r = wm * 32 + mt * 16 + g;
                af[mt][0] = *(const unsigned*)&As[r][c0];
                af[mt][1] = *(const unsigned*)&As[r + 8][c0];
                af[mt][2] = *(const unsigned*)&As[r][c0 + 8];
                af[mt][3] = *(const unsigned*)&As[r + 8][c0 + 8];
            }
#pragma unroll
            for (int nt = 0; nt < 8; nt++) {
                int n = wn * 64 + nt * 8 + g;
                unsigned bf[2];
                bf[0] = *(const unsigned*)&Bs[n][c0];
                bf[1] = *(const unsigned*)&Bs[n][c0 + 8];
                mma_bf16(acc[0][nt], af[0], bf);
                mma_bf16(acc[1][nt], af[1], bf);
            }
        }
    }

#pragma unroll
    for (int mt = 0; mt < 2; mt++) {
#pragma unroll
        for (int nt = 0; nt < 8; nt++) {
            int r = m0 + wm * 32 + mt * 16 + g;
            int c = n0 + wn * 64 + nt * 8 + tg * 2;
            float* a = acc[mt][nt];
            if (EPI == 0) {
                float b0 = (c < N) ? bias[c] : 0.f;
                float b1 = (c + 1 < N) ? bias[c + 1] : 0.f;
                if (r < M) {
                    if (c < N)     Cf[(long long)r * N + c]     = a[0] + b0;
                    if (c + 1 < N) Cf[(long long)r * N + c + 1] = a[1] + b1;
                }
                if (r + 8 < M) {
                    if (c < N)     Cf[(long long)(r + 8) * N + c]     = a[2] + b0;
                    if (c + 1 < N) Cf[(long long)(r + 8) * N + c + 1] = a[3] + b1;
                }
            } else {
                float b0 = bias[c], b1 = bias[c + 1];
                __nv_bfloat162 v0 = __floats2bfloat162_rn(tanhf(a[0] + b0), tanhf(a[1] + b1));
                __nv_bfloat162 v1 = __floats2bfloat162_rn(tanhf(a[2] + b0), tanhf(a[3] + b1));
                *(__nv_bfloat162*)(Cb + (long long)r * N + c) = v0;
                *(__nv_bfloat162*)(Cb + (long long)(r + 8) * N + c) = v1;
            }
        }
    }
}

// ---------------------------------------------------------------- barrier
__device__ __forceinline__ void gbar(int e) {
    __syncthreads();
    if (threadIdx.x == 0) {
        __threadfence();
        unsigned old = atomicAdd(&g_arrive, 1u);
        if (old == (unsigned)e * NBLK + (NBLK - 1)) {
            atomicExch(&g_release, (unsigned)(e + 1));
        } else {
            unsigned r;
            do { asm volatile("ld.global.cg.u32 %0, [%1];" : "=r"(r) : "l"(&g_release)); }
            while (r < (unsigned)(e + 1));
        }
        __threadfence();
    }
    __syncthreads();
}

// ---------------------------------------------------------------- tile GEMM
// K-chunk = 256, 4 slots (3 in flight). AKIND: 0=A0[32][1024]; 2=[A0|A1].
// EPI: 0=tanh->outb; 1=LSTM pointwise (NT=4). HASEB: per-row fp32 bias (g0).
template <int AKIND, int NT>
__device__ __forceinline__ void issue_chunk(
    char* smraw, int slot, int kc, int K,
    const __nv_bfloat16* A0, const __nv_bfloat16* A1,
    const __nv_bfloat16* B, int n0)
{
    constexpr int ASZ = 32 * 264;
    constexpr int STE = ASZ + NT * 8 * 264;
    __nv_bfloat16* smA = (__nv_bfloat16*)smraw + slot * STE;
    __nv_bfloat16* smB = smA + ASZ;
    const int tid = threadIdx.x;
    const int kbase = kc << 8;
    const int region = kbase >> 10;
    const int koff = kbase & 1023;
#pragma unroll
    for (int j = 0; j < 4; j++) {
        int u = tid + j * 256;
        int r = u >> 5, c = (u & 31) << 3;
        const __nv_bfloat16* src;
        if (AKIND == 0) src = A0 + r * 1024 + kbase + c;
        else src = (region == 0 ? A0 : A1) + r * 1024 + koff + c;
        cpa16(sptr(smA + r * 264 + c), src);
    }
#pragma unroll
    for (int j = 0; j < NT; j++) {
        int u = tid + j * 256;
        int r = u >> 5, c = (u & 31) << 3;
        cpa16(sptr(smB + r * 264 + c), B + (long long)(n0 + r) * K + kbase + c);
    }
}

template <int AKIND, int EPI, int NT, bool ZALL, bool HASEB>
__device__ void gtile(char* smraw, int n0, int K,
                      const __nv_bfloat16* __restrict__ B, const float* __restrict__ bias,
                      const __nv_bfloat16* A0, const __nv_bfloat16* A1,
                      __nv_bfloat16* outb, float* cst, __nv_bfloat16* znew,
                      __nv_bfloat16* zallp, int step, const float* eb)
{
    constexpr int ASZ = 32 * 264;
    constexpr int STE = ASZ + NT * 8 * 264;
    constexpr int NW = 32 * NT * 8;
    const int tid = threadIdx.x, lane = tid & 31, wid = tid >> 5;
    const int g = lane >> 2, tg = lane & 3;
    const int S = K >> 8;

    float acc[2][NT][4];
#pragma unroll
    for (int a = 0; a < 2; a++)
#pragma unroll
        for (int b = 0; b < NT; b++)
#pragma unroll
            for (int c = 0; c < 4; c++) acc[a][b][c] = 0.f;

#pragma unroll
    for (int st = 0; st < 3; st++) {
        if (st < S) issue_chunk<AKIND, NT>(smraw, st, st, K, A0, A1, B, n0);
        CP_COMMIT;
    }

    for (int si = 0; si < S; si++) {
        CP_WAIT2;
        __syncthreads();
        int nx = si + 3;
        if (nx < S) issue_chunk<AKIND, NT>(smraw, nx & 3, nx, K, A0, A1, B, n0);
        CP_COMMIT;
        __nv_bfloat16 (*As)[264] = (__nv_bfloat16(*)[264])((__nv_bfloat16*)smraw + (si & 3) * STE);
        __nv_bfloat16 (*Bs)[264] = (__nv_bfloat16(*)[264])((__nv_bfloat16*)smraw + (si & 3) * STE + ASZ);
#pragma unroll
        for (int ks = 0; ks < 2; ks++) {
            const int c0 = wid * 32 + ks * 16 + tg * 2;
            unsigned af[2][4];
#pragma unroll
            for (int mt = 0; mt < 2; mt++) {
                int r = mt * 16 + g;
                af[mt][0] = *(const unsigned*)&As[r][c0];
                af[mt][1] = *(const unsigned*)&As[r + 8][c0];
                af[mt][2] = *(const unsigned*)&As[r][c0 + 8];
                af[mt][3] = *(const unsigned*)&As[r + 8][c0 + 8];
            }
#pragma unroll
            for (int nt = 0; nt < NT; nt++) {
                int n = nt * 8 + g;
                unsigned bf[2];
                bf[0] = *(const unsigned*)&Bs[n][c0];
                bf[1] = *(const unsigned*)&Bs[n][c0 + 8];
                mma_bf16(acc[0][nt], af[0], bf);
                mma_bf16(acc[1][nt], af[1], bf);
            }
        }
    }
    __syncthreads();

    float* Pred = (float*)smraw;
    {
        int base = wid * NW;
#pragma unroll
        for (int mt = 0; mt < 2; mt++)
#pragma unroll
            for (int nt = 0; nt < NT; nt++) {
                int r = mt * 16 + g, cl = nt * 8 + tg * 2;
                Pred[base + r * (NT * 8) + cl]           = acc[mt][nt][0];
                Pred[base + r * (NT * 8) + cl + 1]       = acc[mt][nt][1];
                Pred[base + (r + 8) * (NT * 8) + cl]     = acc[mt][nt][2];
                Pred[base + (r + 8) * (NT * 8) + cl + 1] = acc[mt][nt][3];
            }
    }
    __syncthreads();

    if (EPI == 0) {
        for (int o = tid; o < NW; o += 256) {
            int r = o / (NT * 8), c = o % (NT * 8);
            float sum = 0.f;
#pragma unroll
            for (int w = 0; w < 8; w++) sum += Pred[w * NW + o];
            outb[r * 1024 + n0 + c] = __float2bfloat16(tanhf(sum + bias[n0 + c]));
        }
    } else {
        int b = tid >> 3, ul = tid & 7;
        float gv[4];
#pragma unroll
        for (int gate = 0; gate < 4; gate++) {
            int col = ul * 4 + gate;
            float sum = 0.f;
#pragma unroll
            for (int w = 0; w < 8; w++) sum += Pred[w * 1024 + b * 32 + col];
            float bb = HASEB ? eb[b * 4096 + n0 + col] : bias[n0 + col];
            gv[gate] = sum + bb;
        }
        int u = (n0 >> 2) + ul;
        int gid = b * 1024 + u;
        float cv = sigm(gv[1]) * cst[gid] + sigm(gv[0]) * tanhf(gv[2]);
        float h = sigm(gv[3]) * tanhf(cv);
        cst[gid] = cv;
        znew[gid] = __float2bfloat16(h);
        if (ZALL) zallp[(long long)(step * 32 + b) * 2048 + u] = __float2bfloat16(h);
    }
    __syncthreads();
}

// ---------------------------------------------------------------- attention
__device__ void phase_epc(char* smraw, int s, const int* __restrict__ hlens) {
    const int bid = blockIdx.x;
    if (bid >= 128) return;
    const int b = bid >> 2, ch = bid & 3;
    const int t0 = ch * 100;
    const int tid = threadIdx.x, lane = tid & 31, wid = tid >> 5;
    float* dqs = (float*)smraw;
    float* ws  = dqs + 1024;
    float* red = ws + 104;
    float* pcr = red + 256;
    int*   flg = (int*)(pcr + 8192);

    const uint4* dqp = (const uint4*)(g_dqb + b * 1024);
    for (int j = tid; j < 128; j += 256) {
        uint4 v = __ldcg(dqp + j);
        const __nv_bfloat162* h = (const __nv_bfloat162*)&v;
#pragma unroll
        for (int k = 0; k < 4; k++) {
            float2 f = __bfloat1622float2(h[k]);
            dqs[j * 8 + k * 2]     = f.x;
            dqs[j * 8 + k * 2 + 1] = f.y;
        }
    }
    __syncthreads();

    const int hl = hlens[b];
    // e pass: 2 rows per warp iteration
    for (int base = wid * 2; base < 100; base += 16) {
        const __nv_bfloat16* r1 = g_preb + ((long long)b * 400 + t0 + base) * 1024 + lane * 8;
        const __nv_bfloat16* r2 = r1 + 1024;
        float a1 = 0.f, a2 = 0.f, a3 = 0.f, a4 = 0.f;
#pragma unroll
        for (int q = 0; q < 4; q++) {
            uint4 v1 = *(const uint4*)(r1 + q * 256);
            uint4 v2 = *(const uint4*)(r2 + q * 256);
            const __nv_bfloat162* h1 = (const __nv_bfloat162*)&v1;
            const __nv_bfloat162* h2 = (const __nv_bfloat162*)&v2;
#pragma unroll
            for (int k = 0; k < 4; k++) {
                float2 d = *(const float2*)(dqs + q * 256 + lane * 8 + k * 2);
                float2 f1 = __bfloat1622float2(h1[k]);
                float2 f2 = __bfloat1622float2(h2[k]);
                a1 = fmaf(f1.x, d.x, a1); a2 = fmaf(f1.y, d.y, a2);
                a3 = fmaf(f2.x, d.x, a3); a4 = fmaf(f2.y, d.y, a4);
            }
        }
        float s1 = a1 + a2, s2 = a3 + a4;
#pragma unroll
        for (int off = 16; off; off >>= 1) {
            s1 += __shfl_xor_sync(0xffffffffu, s1, off);
            s2 += __shfl_xor_sync(0xffffffffu, s2, off);
        }
        if (lane == 0) {
            int t = t0 + base;
            ws[base]     = (t < hl)     ? 2.f * s1 : NEGBIG;
            ws[base + 1] = (t + 1 < hl) ? 2.f * s2 : NEGBIG;
        }
    }
    __syncthreads();

    float lm = NEGBIG;
    for (int i = tid; i < 100; i += 256) lm = fmaxf(lm, ws[i]);
    red[tid] = lm; __syncthreads();
    for (int st = 128; st; st >>= 1) { if (tid < st) red[tid] = fmaxf(red[tid], red[tid + st]); __syncthreads(); }
    const float m = red[0]; __syncthreads();
    float ls = 0.f;
    for (int i = tid; i < 100; i += 256) { float w = expf(ws[i] - m); ws[i] = w; ls += w; }
    red[tid] = ls; __syncthreads();
    for (int st = 128; st; st >>= 1) { if (tid < st) red[tid] += red[tid + st]; __syncthreads(); }
    const float sl = red[0];
    __syncthreads();

    // context pass: 2 rows per warp iteration
    float pacc[32];
#pragma unroll
    for (int i = 0; i < 32; i++) pacc[i] = 0.f;
    for (int base = wid * 2; base < 100; base += 16) {
        float w1 = ws[base], w2 = ws[base + 1];
        const __nv_bfloat16* r1 = g_hsb + ((long long)b * 400 + t0 + base) * 1024 + lane * 8;
        const __nv_bfloat16* r2 = r1 + 1024;
#pragma unroll
        for (int q = 0; q < 4; q++) {
            uint4 v1 = *(const uint4*)(r1 + q * 256);
            uint4 v2 = *(const uint4*)(r2 + q * 256);
            const __nv_bfloat162* h1 = (const __nv_bfloat162*)&v1;
            const __nv_bfloat162* h2 = (const __nv_bfloat162*)&v2;
#pragma unroll
            for (int k = 0; k < 4; k++) {
                float2 f1 = __bfloat1622float2(h1[k]);
                float2 f2 = __bfloat1622float2(h2[k]);
                int o = q * 8 + k * 2;
                pacc[o]     = fmaf(w1, f1.x, fmaf(w2, f2.x, pacc[o]));
                pacc[o + 1] = fmaf(w1, f1.y, fmaf(w2, f2.y, pacc[o + 1]));
            }
        }
    }
#pragma unroll
    for (int q = 0; q < 4; q++)
#pragma unroll
        for (int j = 0; j < 8; j++)
            pcr[wid * 1024 + q * 256 + lane * 8 + j] = pacc[q * 8 + j];
    __syncthreads();
    for (int col = tid; col < 1024; col += 256) {
        float a = 0.f;
#pragma unroll
        for (int w = 0; w < 8; w++) a += pcr[w * 1024 + col];
        g_pc[bid * 1024 + col] = a;
    }
    if (tid == 0) { g_ms[bid * 2] = m; g_ms[bid * 2 + 1] = sl; }
    __syncthreads();

    if (tid == 0) {
        __threadfence();
        unsigned old = atomicAdd(&g_cmb[b], 1u);
        *flg = (old == (unsigned)(s * 4 + 3)) ? 1 : 0;
    }
    __syncthreads();
    if (*flg) {
        float mi[4], si[4];
#pragma unroll
        for (int i = 0; i < 4; i++) {
            mi[i] = __ldcg(&g_ms[(b * 4 + i) * 2]);
            si[i] = __ldcg(&g_ms[(b * 4 + i) * 2 + 1]);
        }
        float M = fmaxf(fmaxf(mi[0], mi[1]), fmaxf(mi[2], mi[3]));
        float sc[4], Ssum = 0.f;
#pragma unroll
        for (int i = 0; i < 4; i++) { sc[i] = expf(mi[i] - M); Ssum += sc[i] * si[i]; }
        float inv = 1.f / Ssum;
        for (int col = tid; col < 1024; col += 256) {
            float a = 0.f;
#pragma unroll
            for (int i = 0; i < 4; i++) a += sc[i] * __ldcg(&g_pc[(b * 4 + i) * 1024 + col]);
            __nv_bfloat16 v = __float2bfloat16(a * inv);
            g_attb[b * 1024 + col] = v;
            g_zallb[((long long)s * 32 + b) * 2048 + 1024 + col] = v;
        }
    }
    __syncthreads();
}

// ---------------------------------------------------------------- main loop
__global__ void __launch_bounds__(256, 1) k_loop(const int* __restrict__ hlens,
                                                 const float* __restrict__ bdec) {
    extern __shared__ char sm[];
    const int bid = blockIdx.x;
    int ep = 0;

    for (int s = 0; s <= 101; s++) {
        const int p = s & 1;
        if (bid < 128) {
            if (s >= 1)
                gtile<2, 1, 4, true, false>(sm, bid * 32, 2048, g_Wc1r, g_bs1r,
                                            g_z0s[p], g_z1s[1 - p],
                                            nullptr, g_c1, g_z1s[p], g_zallb, s - 1, nullptr);
        } else if (bid < 144) {
            if (s <= 100)
                gtile<0, 0, 8, false, false>(sm, (bid - 128) * 64, 1024, g_Wdecb, bdec,
                                             g_z0s[p], nullptr,
                                             g_dqb, nullptr, nullptr, nullptr, s, nullptr);
        }
        gbar(ep); ep++;
        if (s == 101) break;

        phase_epc(sm, s, hlens);
        gbar(ep); ep++;

        if (bid < 128) {
            gtile<2, 1, 4, false, true>(sm, bid * 32, 2048, g_Wc0x, nullptr,
                                        g_attb, g_z0s[p],
                                        nullptr, g_c0, g_z0s[1 - p], nullptr, s,
                                        g_emb0 + (long long)s * 32 * 4096);
        }
        gbar(ep); ep++;
    }
}

// ---------------------------------------------------------------- CE
__global__ void k_ce(const void* __restrict__ ys) {
    int r = blockIdx.x;
    int l = r / BB, b = r % BB;
    const float* y = g_yall + (long long)r * VV;
    __shared__ float red[256];
    int tid = threadIdx.x;
    float lm = NEGBIG;
    for (int v = tid; v < VV; v += 256) lm = fmaxf(lm, y[v]);
    red[tid] = lm; __syncthreads();
    for (int s = 128; s > 0; s >>= 1) { if (tid < s) red[tid] = fmaxf(red[tid], red[tid + s]); __syncthreads(); }
    float m = red[0]; __syncthreads();
    float ls = 0.f;
    for (int v = tid; v < VV; v += 256) ls += expf(y[v] - m);
    red[tid] = ls; __syncthreads();
    for (int s = 128; s > 0; s >>= 1) { if (tid < s) red[tid] += red[tid + s]; __syncthreads(); }
    if (tid == 0) {
        int tgt = (l < LL) ? read_ys(ys, b * LL + l) : 4999;
        atomicAdd(&g_loss, logf(red[0]) + m - y[tgt]);
    }
}

__global__ void k_fin(float* out) {
    out[0] = g_loss * ((float)LL / (float)(L1 * BB));
}

// ---------------------------------------------------------------- launch
extern "C" void kernel_launch(void* const* d_in, const int* in_sizes, int n_in,
                              void* d_out, int out_size) {
    const float* hs    = (const float*)d_in[0];
    const float* embed = (const float*)d_in[1];
    const float* Wenc  = (const float*)d_in[2];
    const float* benc  = (const float*)d_in[3];
    const float* Wdec  = (const float*)d_in[4];
    const float* bdec  = (const float*)d_in[5];
    const float* Wih0  = (const float*)d_in[6];
    const float* Whh0  = (const float*)d_in[7];
    const float* bih0  = (const float*)d_in[8];
    const float* bhh0  = (const float*)d_in[9];
    const float* Wih1  = (const float*)d_in[10];
    const float* Whh1  = (const float*)d_in[11];
    const float* bih1  = (const float*)d_in[12];
    const float* bhh1  = (const float*)d_in[13];
    const float* Wout  = (const float*)d_in[14];
    const float* bout  = (const float*)d_in[15];
    const int*   hlens = (const int*)d_in[16];
    const void*  ys    = (const void*)d_in[17];

    __nv_bfloat16 *hsb, *preb, *eysb, *Wencb, *Wdecb, *Woutb, *Wc0e, *zallb;
    float *yall, *bs0r, *emb0;
    cudaGetSymbolAddress((void**)&hsb,   g_hsb);
    cudaGetSymbolAddress((void**)&preb,  g_preb);
    cudaGetSymbolAddress((void**)&eysb,  g_eysb);
    cudaGetSymbolAddress((void**)&Wencb, g_Wencb);
    cudaGetSymbolAddress((void**)&Wdecb, g_Wdecb);
    cudaGetSymbolAddress((void**)&Woutb, g_Woutb);
    cudaGetSymbolAddress((void**)&Wc0e,  g_Wc0e);
    cudaGetSymbolAddress((void**)&zallb, g_zallb);
    cudaGetSymbolAddress((void**)&yall,  g_yall);
    cudaGetSymbolAddress((void**)&bs0r,  g_bs0r);
    cudaGetSymbolAddress((void**)&emb0,  g_emb0);

    static int smem_set = 0;
    if (!smem_set) {
        cudaFuncSetAttribute(k_loop, cudaFuncAttributeMaxDynamicSharedMemorySize, SMSZ);
        cudaFuncSetAttribute(mma_big<0>, cudaFuncAttributeMaxDynamicSharedMemorySize, BIG_SMEM);
        cudaFuncSetAttribute(mma_big<1>, cudaFuncAttributeMaxDynamicSharedMemorySize, BIG_SMEM);
        smem_set = 1;
    }

    k_prep0<<<64, 256>>>(bih0, bhh0, bih1, bhh1, ys);
    k_cvt8<<<1184, 256>>>((const float4*)hs, (uint4*)hsb, (long long)BB * TT * DD / 8);
    k_cvt8<<<512, 256>>>((const float4*)Wenc, (uint4*)Wencb, (long long)DD * DD / 8);
    k_cvt8<<<512, 256>>>((const float4*)Wdec, (uint4*)Wdecb, (long long)DD * DD / 8);
    k_cvt8<<<1184, 256>>>((const float4*)Wout, (uint4*)Woutb, (long long)VV * 2048 / 8);
    k_gath<<<L1 * BB, 256>>>(embed, ys);
    k_reo0<<<1536, 256>>>(Wih0, Whh0);
    k_reo1<<<1024, 256>>>(Wih1, Whh1);

    // g_emb0 = eysb @ Wc0e^T + bs0r  (embedding contribution to layer-0 gates)
    mma_big<0><<<dim3(4096 / 128, (L1 * BB + 127) / 128), 256, BIG_SMEM>>>(
        eysb, Wc0e, bs0r, emb0, nullptr, L1 * BB, 4096, 1024);

    // pre_enc = tanh(hs @ Wenc^T + benc) -> bf16
    mma_big<1><<<dim3(DD / 128, BB * TT / 128), 256, BIG_SMEM>>>(
        hsb, Wencb, benc, nullptr, preb, BB * TT, DD, DD);

    k_loop<<<NBLK, 256, SMSZ>>>(hlens, bdec);

    // y_all = zall @ Wout^T + bout
    mma_big<0><<<dim3((VV + 127) / 128, (L1 * BB + 127) / 128), 256, BIG_SMEM>>>(
        zallb, Woutb, bout, yall, nullptr, L1 * BB, VV, 2048);

    k_ce<<<L1 * BB, 256>>>(ys);
    k_fin<<<1, 1>>>((float*)d_out);
}

// round 8
// speedup vs baseline: 11.2637x; 1.0533x over previous
#include <cuda_runtime.h>
#include <cuda_bf16.h>

#define BB 32
#define TT 400
#define DD 1024
#define VV 5000
#define LL 100
#define L1 101
#define NEGBIG -1e30f
#define NBLK 148
#define SMSZ 202752
#define BIG_SMEM 110592

__device__ __align__(16) __nv_bfloat16 g_hsb [BB * TT * DD];
__device__ __align__(16) __nv_bfloat16 g_preb[BB * TT * DD];
__device__ __align__(16) __nv_bfloat16 g_eysb[L1 * BB * DD];
__device__ __align__(16) __nv_bfloat16 g_Wencb[DD * DD];
__device__ __align__(16) __nv_bfloat16 g_Wdecb[DD * DD];
__device__ __align__(16) __nv_bfloat16 g_Woutb[VV * 2048];
__device__ __align__(16) __nv_bfloat16 g_Wc0e[4096 * 1024];
__device__ __align__(16) __nv_bfloat16 g_Wc0x[4096 * 2048];
__device__ __align__(16) __nv_bfloat16 g_Wc1r[4096 * 2048];
__device__ __align__(16) float g_bs0r[4096];
__device__ __align__(16) float g_bs1r[4096];
__device__ __align__(16) float g_emb0[(long long)L1 * BB * 4096];
__device__ __align__(16) __nv_bfloat16 g_dqb[BB * DD];
__device__ __align__(16) __nv_bfloat16 g_attb[BB * DD];
__device__ __align__(16) __nv_bfloat16 g_z0s[2][BB * DD];
__device__ __align__(16) __nv_bfloat16 g_z1s[2][BB * DD];
__device__ __align__(16) float g_c0[BB * DD];
__device__ __align__(16) float g_c1[BB * DD];
__device__ __align__(16) float g_pc[148 * 1024];
__device__ __align__(16) float g_ms[304];
__device__ unsigned g_cmb[32];
__device__ __align__(16) __nv_bfloat16 g_zallb[L1 * BB * 2048];
__device__ __align__(16) float g_yall[(long long)L1 * BB * VV];
__device__ float g_loss;
__device__ int g_i64;
__device__ unsigned g_arrive;
__device__ unsigned g_release;

__device__ __forceinline__ float sigm(float x) { return 1.0f / (1.0f + expf(-x)); }
__device__ __forceinline__ int read_ys(const void* ys, int i) {
    return g_i64 ? (int)((const long long*)ys)[i] : ((const int*)ys)[i];
}
__device__ __forceinline__ unsigned sptr(const void* p) {
    unsigned r;
    asm("{.reg .u64 t; cvta.to.shared.u64 t, %1; cvt.u32.u64 %0, t;}" : "=r"(r) : "l"(p));
    return r;
}
__device__ __forceinline__ void cpa16(unsigned s, const void* g) {
    asm volatile("cp.async.cg.shared.global [%0], [%1], 16;" :: "r"(s), "l"(g));
}
#define CP_COMMIT asm volatile("cp.async.commit_group;")
#define CP_WAIT2  asm volatile("cp.async.wait_group 2;")
#define CP_WAIT1  asm volatile("cp.async.wait_group 1;")

__device__ __forceinline__ unsigned pack2(float a, float b) {
    __nv_bfloat162 p = __floats2bfloat162_rn(a, b);
    return *(unsigned*)&p;
}

// ---------------------------------------------------------------- fused prologue
// All init + converts + gather + weight reorders in one kernel (grid-stride regions).
__global__ void k_prep_all(
    const float* __restrict__ hs, const float* __restrict__ embed,
    const float* __restrict__ Wenc, const float* __restrict__ Wdec,
    const float* __restrict__ Wout,
    const float* __restrict__ Wih0, const float* __restrict__ Whh0,
    const float* __restrict__ Wih1, const float* __restrict__ Whh1,
    const float* __restrict__ bih0, const float* __restrict__ bhh0,
    const float* __restrict__ bih1, const float* __restrict__ bhh1,
    const void* __restrict__ ys)
{
    __shared__ int s_i64;
    const int tid = threadIdx.x;
    if (tid == 0) {
        const int* w = (const int*)ys;
        int f = 1;
        for (int j = 1; j < 64; j += 2) if (w[j] != 0) f = 0;
        s_i64 = f;
    }
    __syncthreads();
    const int i64 = s_i64;
    const long long gi = (long long)blockIdx.x * blockDim.x + tid;
    const long long gn = (long long)gridDim.x * blockDim.x;

    // small state inits
    {
        __nv_bfloat16 z = __float2bfloat16(0.f);
        for (long long j = gi; j < BB * DD; j += gn) {
            g_c0[j] = 0.f; g_c1[j] = 0.f;
            g_z0s[0][j] = z; g_z0s[1][j] = z;
            g_z1s[0][j] = z; g_z1s[1][j] = z;
        }
        for (long long j = gi; j < 4096; j += gn) {
            int u = (int)j >> 2, gate = (int)j & 3;
            int orow = gate * 1024 + u;
            g_bs0r[j] = bih0[orow] + bhh0[orow];
            g_bs1r[j] = bih1[orow] + bhh1[orow];
        }
        if (gi < 32) g_cmb[gi] = 0u;
        if (gi == 0) { g_loss = 0.f; g_arrive = 0u; g_release = 0u; g_i64 = i64; }
    }

    // cvt hs -> g_hsb
    {
        const float4* s = (const float4*)hs;
        uint4* d = (uint4*)g_hsb;
        for (long long j = gi; j < 1638400LL; j += gn) {
            float4 a = s[2 * j], b = s[2 * j + 1];
            d[j] = make_uint4(pack2(a.x, a.y), pack2(a.z, a.w), pack2(b.x, b.y), pack2(b.z, b.w));
        }
    }
    // cvt Wenc
    {
        const float4* s = (const float4*)Wenc;
        uint4* d = (uint4*)g_Wencb;
        for (long long j = gi; j < 131072LL; j += gn) {
            float4 a = s[2 * j], b = s[2 * j + 1];
            d[j] = make_uint4(pack2(a.x, a.y), pack2(a.z, a.w), pack2(b.x, b.y), pack2(b.z, b.w));
        }
    }
    // cvt Wdec
    {
        const float4* s = (const float4*)Wdec;
        uint4* d = (uint4*)g_Wdecb;
        for (long long j = gi; j < 131072LL; j += gn) {
            float4 a = s[2 * j], b = s[2 * j + 1];
            d[j] = make_uint4(pack2(a.x, a.y), pack2(a.z, a.w), pack2(b.x, b.y), pack2(b.z, b.w));
        }
    }
    // cvt Wout
    {
        const float4* s = (const float4*)Wout;
        uint4* d = (uint4*)g_Woutb;
        for (long long j = gi; j < 1280000LL; j += gn) {
            float4 a = s[2 * j], b = s[2 * j + 1];
            d[j] = make_uint4(pack2(a.x, a.y), pack2(a.z, a.w), pack2(b.x, b.y), pack2(b.z, b.w));
        }
    }
    // embedding gather -> g_eysb  (3232 rows x 128 float4 cols)
    {
        for (long long it = gi; it < 413696LL; it += gn) {
            int row = (int)(it >> 7), col = (int)(it & 127);
            int l = row >> 5, b = row & 31;
            int tok = 4999;
            if (l > 0) {
                int idx = b * LL + l - 1;
                tok = i64 ? (int)((const long long*)ys)[idx] : ((const int*)ys)[idx];
            }
            float4 v = ((const float4*)(embed + (long long)tok * 1024))[col];
            ((uint2*)(g_eysb + (long long)row * 1024))[col] = make_uint2(pack2(v.x, v.y), pack2(v.z, v.w));
        }
    }
    // reo0e: Wih0[:, :1024] gate-interleaved
    {
        for (long long j4 = gi; j4 < 1048576LL; j4 += gn) {
            long long j = j4 * 4;
            int r = (int)(j >> 10), c = (int)(j & 1023);
            long long orow = (r & 3) * 1024 + (r >> 2);
            float4 v = *(const float4*)(Wih0 + orow * 2048 + c);
            *(uint2*)(g_Wc0e + j) = make_uint2(pack2(v.x, v.y), pack2(v.z, v.w));
        }
    }
    // reo0x: [Wih0[:,1024:] | Whh0] gate-interleaved
    {
        for (long long j4 = gi; j4 < 2097152LL; j4 += gn) {
            long long j = j4 * 4;
            int r = (int)(j >> 11), c = (int)(j & 2047);
            long long orow = (r & 3) * 1024 + (r >> 2);
            float4 v = (c < 1024) ? *(const float4*)(Wih0 + orow * 2048 + 1024 + c)
                                  : *(const float4*)(Whh0 + orow * 1024 + (c - 1024));
            *(uint2*)(g_Wc0x + j) = make_uint2(pack2(v.x, v.y), pack2(v.z, v.w));
        }
    }
    // reo1: [Wih1 | Whh1] gate-interleaved
    {
        for (long long j4 = gi; j4 < 2097152LL; j4 += gn) {
            long long j = j4 * 4;
            int r = (int)(j >> 11), c = (int)(j & 2047);
            long long orow = (r & 3) * 1024 + (r >> 2);
            float4 v = (c < 1024) ? *(const float4*)(Wih1 + orow * 1024 + c)
                                  : *(const float4*)(Whh1 + orow * 1024 + (c - 1024));
            *(uint2*)(g_Wc1r + j) = make_uint2(pack2(v.x, v.y), pack2(v.z, v.w));
        }
    }
}

__device__ __forceinline__ void mma_bf16(float* d, const unsigned* a, const unsigned* b) {
    asm volatile(
        "mma.sync.aligned.m16n8k16.row.col.f32.bf16.bf16.f32 "
        "{%0,%1,%2,%3}, {%4,%5,%6,%7}, {%8,%9}, {%0,%1,%2,%3};\n"
        : "+f"(d[0]), "+f"(d[1]), "+f"(d[2]), "+f"(d[3])
        : "r"(a[0]), "r"(a[1]), "r"(a[2]), "r"(a[3]), "r"(b[0]), "r"(b[1]));
}

// ---------------------------------------------------------------- big GEMM
#define BKP 72
__device__ __forceinline__ void issue_big(
    char* smb, int slot, int k0,
    const __nv_bfloat16* A, const __nv_bfloat16* B,
    int M, int N, int K, int m0, int n0)
{
    __nv_bfloat16* smA = (__nv_bfloat16*)smb + slot * (2 * 128 * BKP);
    __nv_bfloat16* smB = smA + 128 * BKP;
    const int tid = threadIdx.x;
#pragma unroll
    for (int j = 0; j < 4; j++) {
        int idx = tid + j * 256;
        int r = idx >> 3, c = (idx & 7) * 8;
        int m = m0 + r; if (m >= M) m = 0;
        cpa16(sptr(smA + r * BKP + c), A + (long long)m * K + k0 + c);
        int n = n0 + r; if (n >= N) n = 0;
        cpa16(sptr(smB + r * BKP + c), B + (long long)n * K + k0 + c);
    }
}

template <int EPI>
__global__ __launch_bounds__(256) void mma_big(
    const __nv_bfloat16* __restrict__ A, const __nv_bfloat16* __restrict__ B,
    const float* __restrict__ bias, float* __restrict__ Cf,
    __nv_bfloat16* __restrict__ Cb, int M, int N, int K)
{
    extern __shared__ char smb[];
    const int tid = threadIdx.x, lane = tid & 31, wid = tid >> 5;
    const int wm = wid >> 1, wn = wid & 1;
    const int m0 = blockIdx.y * 128, n0 = blockIdx.x * 128;
    const int g = lane >> 2, tg = lane & 3;
    const int S = K >> 6;

    float acc[2][8][4];
#pragma unroll
    for (int a = 0; a < 2; a++)
#pragma unroll
        for (int b = 0; b < 8; b++)
#pragma unroll
            for (int c = 0; c < 4; c++) acc[a][b][c] = 0.f;

    issue_big(smb, 0, 0, A, B, M, N, K, m0, n0); CP_COMMIT;
    if (S > 1) issue_big(smb, 1, 64, A, B, M, N, K, m0, n0);
    CP_COMMIT;

    for (int si = 0; si < S; si++) {
        CP_WAIT1;
        __syncthreads();
        if (si + 2 < S) issue_big(smb, (si + 2) % 3, (si + 2) << 6, A, B, M, N, K, m0, n0);
        CP_COMMIT;
        __nv_bfloat16 (*As)[BKP] = (__nv_bfloat16(*)[BKP])((__nv_bfloat16*)smb + (si % 3) * (2 * 128 * BKP));
        __nv_bfloat16 (*Bs)[BKP] = (__nv_bfloat16(*)[BKP])((__nv_bfloat16*)smb + (si % 3) * (2 * 128 * BKP) + 128 * BKP);
#pragma unroll
        for (int kt = 0; kt < 4; kt++) {
            const int c0 = kt * 16 + tg * 2;
            unsigned af[2][4];
#pragma unroll
            for (int mt = 0; mt < 2; mt++) {
                int r = wm * 32 + mt * 16 + g;
                af[mt][0] = *(const unsigned*)&As[r][c0];
                af[mt][1] = *(const unsigned*)&As[r + 8][c0];
                af[mt][2] = *(const unsigned*)&As[r][c0 + 8];
                af[mt][3] = *(const unsigned*)&As[r + 8][c0 + 8];
            }
#pragma unroll
            for (int nt = 0; nt < 8; nt++) {
                int n = wn * 64 + nt * 8 + g;
                unsigned bf[2];
                bf[0] = *(const unsigned*)&Bs[n][c0];
                bf[1] = *(const unsigned*)&Bs[n][c0 + 8];
                mma_bf16(acc[0][nt], af[0], bf);
                mma_bf16(acc[1][nt], af[1], bf);
            }
        }
    }

#pragma unroll
    for (int mt = 0; mt < 2; mt++) {
#pragma unroll
        for (int nt = 0; nt < 8; nt++) {
            int r = m0 + wm * 32 + mt * 16 + g;
            int c = n0 + wn * 64 + nt * 8 + tg * 2;
            float* a = acc[mt][nt];
            if (EPI == 0) {
                float b0 = (c < N) ? bias[c] : 0.f;
                float b1 = (c + 1 < N) ? bias[c + 1] : 0.f;
                if (r < M) {
                    if (c < N)     Cf[(long long)r * N + c]     = a[0] + b0;
                    if (c + 1 < N) Cf[(long long)r * N + c + 1] = a[1] + b1;
                }
                if (r + 8 < M) {
                    if (c < N)     Cf[(long long)(r + 8) * N + c]     = a[2] + b0;
                    if (c + 1 < N) Cf[(long long)(r + 8) * N + c + 1] = a[3] + b1;
                }
            } else {
                float b0 = bias[c], b1 = bias[c + 1];
                __nv_bfloat162 v0 = __floats2bfloat162_rn(tanhf(a[0] + b0), tanhf(a[1] + b1));
                __nv_bfloat162 v1 = __floats2bfloat162_rn(tanhf(a[2] + b0), tanhf(a[3] + b1));
                *(__nv_bfloat162*)(Cb + (long long)r * N + c) = v0;
                *(__nv_bfloat162*)(Cb + (long long)(r + 8) * N + c) = v1;
            }
        }
    }
}

// ---------------------------------------------------------------- barrier
__device__ __forceinline__ void gbar(int e) {
    __syncthreads();
    if (threadIdx.x == 0) {
        __threadfence();
        unsigned old = atomicAdd(&g_arrive, 1u);
        if (old == (unsigned)e * NBLK + (NBLK - 1)) {
            atomicExch(&g_release, (unsigned)(e + 1));
        } else {
            unsigned r;
            do { asm volatile("ld.global.cg.u32 %0, [%1];" : "=r"(r) : "l"(&g_release)); }
            while (r < (unsigned)(e + 1));
        }
        __threadfence();
    }
    __syncthreads();
}

// ---------------------------------------------------------------- tile GEMM
template <int AKIND, int NT>
__device__ __forceinline__ void issue_chunk(
    char* smraw, int slot, int kc, int K,
    const __nv_bfloat16* A0, const __nv_bfloat16* A1,
    const __nv_bfloat16* B, int n0)
{
    constexpr int ASZ = 32 * 264;
    constexpr int STE = ASZ + NT * 8 * 264;
    __nv_bfloat16* smA = (__nv_bfloat16*)smraw + slot * STE;
    __nv_bfloat16* smB = smA + ASZ;
    const int tid = threadIdx.x;
    const int kbase = kc << 8;
    const int region = kbase >> 10;
    const int koff = kbase & 1023;
#pragma unroll
    for (int j = 0; j < 4; j++) {
        int u = tid + j * 256;
        int r = u >> 5, c = (u & 31) << 3;
        const __nv_bfloat16* src;
        if (AKIND == 0) src = A0 + r * 1024 + kbase + c;
        else src = (region == 0 ? A0 : A1) + r * 1024 + koff + c;
        cpa16(sptr(smA + r * 264 + c), src);
    }
#pragma unroll
    for (int j = 0; j < NT; j++) {
        int u = tid + j * 256;
        int r = u >> 5, c = (u & 31) << 3;
        cpa16(sptr(smB + r * 264 + c), B + (long long)(n0 + r) * K + kbase + c);
    }
}

template <int AKIND, int EPI, int NT, bool ZALL, bool HASEB>
__device__ void gtile(char* smraw, int n0, int K,
                      const __nv_bfloat16* __restrict__ B, const float* __restrict__ bias,
                      const __nv_bfloat16* A0, const __nv_bfloat16* A1,
                      __nv_bfloat16* outb, float* cst, __nv_bfloat16* znew,
                      __nv_bfloat16* zallp, int step, const float* eb)
{
    constexpr int ASZ = 32 * 264;
    constexpr int STE = ASZ + NT * 8 * 264;
    constexpr int NW = 32 * NT * 8;
    const int tid = threadIdx.x, lane = tid & 31, wid = tid >> 5;
    const int g = lane >> 2, tg = lane & 3;
    const int S = K >> 8;

    float acc[2][NT][4];
#pragma unroll
    for (int a = 0; a < 2; a++)
#pragma unroll
        for (int b = 0; b < NT; b++)
#pragma unroll
            for (int c = 0; c < 4; c++) acc[a][b][c] = 0.f;

#pragma unroll
    for (int st = 0; st < 3; st++) {
        if (st < S) issue_chunk<AKIND, NT>(smraw, st, st, K, A0, A1, B, n0);
        CP_COMMIT;
    }

    for (int si = 0; si < S; si++) {
        CP_WAIT2;
        __syncthreads();
        int nx = si + 3;
        if (nx < S) issue_chunk<AKIND, NT>(smraw, nx & 3, nx, K, A0, A1, B, n0);
        CP_COMMIT;
        __nv_bfloat16 (*As)[264] = (__nv_bfloat16(*)[264])((__nv_bfloat16*)smraw + (si & 3) * STE);
        __nv_bfloat16 (*Bs)[264] = (__nv_bfloat16(*)[264])((__nv_bfloat16*)smraw + (si & 3) * STE + ASZ);
#pragma unroll
        for (int ks = 0; ks < 2; ks++) {
            const int c0 = wid * 32 + ks * 16 + tg * 2;
            unsigned af[2][4];
#pragma unroll
            for (int mt = 0; mt < 2; mt++) {
                int r = mt * 16 + g;
                af[mt][0] = *(const unsigned*)&As[r][c0];
                af[mt][1] = *(const unsigned*)&As[r + 8][c0];
                af[mt][2] = *(const unsigned*)&As[r][c0 + 8];
                af[mt][3] = *(const unsigned*)&As[r + 8][c0 + 8];
            }
#pragma unroll
            for (int nt = 0; nt < NT; nt++) {
                int n = nt * 8 + g;
                unsigned bf[2];
                bf[0] = *(const unsigned*)&Bs[n][c0];
                bf[1] = *(const unsigned*)&Bs[n][c0 + 8];
                mma_bf16(acc[0][nt], af[0], bf);
                mma_bf16(acc[1][nt], af[1], bf);
            }
        }
    }
    __syncthreads();

    float* Pred = (float*)smraw;
    {
        int base = wid * NW;
#pragma unroll
        for (int mt = 0; mt < 2; mt++)
#pragma unroll
            for (int nt = 0; nt < NT; nt++) {
                int r = mt * 16 + g, cl = nt * 8 + tg * 2;
                Pred[base + r * (NT * 8) + cl]           = acc[mt][nt][0];
                Pred[base + r * (NT * 8) + cl + 1]       = acc[mt][nt][1];
                Pred[base + (r + 8) * (NT * 8) + cl]     = acc[mt][nt][2];
                Pred[base + (r + 8) * (NT * 8) + cl + 1] = acc[mt][nt][3];
            }
    }
    __syncthreads();

    if (EPI == 0) {
        for (int o = tid; o < NW; o += 256) {
            int r = o / (NT * 8), c = o % (NT * 8);
            float sum = 0.f;
#pragma unroll
            for (int w = 0; w < 8; w++) sum += Pred[w * NW + o];
            outb[r * 1024 + n0 + c] = __float2bfloat16(tanhf(sum + bias[n0 + c]));
        }
    } else {
        int b = tid >> 3, ul = tid & 7;
        float gv[4];
#pragma unroll
        for (int gate = 0; gate < 4; gate++) {
            int col = ul * 4 + gate;
            float sum = 0.f;
#pragma unroll
            for (int w = 0; w < 8; w++) sum += Pred[w * 1024 + b * 32 + col];
            float bb = HASEB ? eb[b * 4096 + n0 + col] : bias[n0 + col];
            gv[gate] = sum + bb;
        }
        int u = (n0 >> 2) + ul;
        int gid = b * 1024 + u;
        float cv = sigm(gv[1]) * cst[gid] + sigm(gv[0]) * tanhf(gv[2]);
        float h = sigm(gv[3]) * tanhf(cv);
        cst[gid] = cv;
        znew[gid] = __float2bfloat16(h);
        if (ZALL) zallp[(long long)(step * 32 + b) * 2048 + u] = __float2bfloat16(h);
    }
    __syncthreads();
}

// ---------------------------------------------------------------- attention
// 148 blocks: b<20 -> 5 chunks of 80 t; b>=20 -> 4 chunks of 100 t.
__device__ void phase_epc(char* smraw, int s, const int* __restrict__ hlens) {
    const int bid = blockIdx.x;
    int b, t0, tlen, ncs, base;
    if (bid < 100) { b = bid / 5; t0 = (bid % 5) * 80; tlen = 80; ncs = 5; base = b * 5; }
    else { int u = bid - 100; b = 20 + (u >> 2); t0 = (u & 3) * 100; tlen = 100; ncs = 4; base = 100 + (b - 20) * 4; }

    const int tid = threadIdx.x, lane = tid & 31, wid = tid >> 5;
    float* dqs = (float*)smraw;
    float* ws  = dqs + 1024;
    float* red = ws + 104;
    float* pcr = red + 256;
    int*   flg = (int*)(pcr + 8192);

    const uint4* dqp = (const uint4*)(g_dqb + b * 1024);
    for (int j = tid; j < 128; j += 256) {
        uint4 v = __ldcg(dqp + j);
        const __nv_bfloat162* h = (const __nv_bfloat162*)&v;
#pragma unroll
        for (int k = 0; k < 4; k++) {
            float2 f = __bfloat1622float2(h[k]);
            dqs[j * 8 + k * 2]     = f.x;
            dqs[j * 8 + k * 2 + 1] = f.y;
        }
    }
    __syncthreads();

    const int hl = hlens[b];
    for (int bs = wid * 2; bs < tlen; bs += 16) {
        const __nv_bfloat16* r1 = g_preb + ((long long)b * 400 + t0 + bs) * 1024 + lane * 8;
        const __nv_bfloat16* r2 = r1 + 1024;
        float a1 = 0.f, a2 = 0.f, a3 = 0.f, a4 = 0.f;
#pragma unroll
        for (int q = 0; q < 4; q++) {
            uint4 v1 = *(const uint4*)(r1 + q * 256);
            uint4 v2 = *(const uint4*)(r2 + q * 256);
            const __nv_bfloat162* h1 = (const __nv_bfloat162*)&v1;
            const __nv_bfloat162* h2 = (const __nv_bfloat162*)&v2;
#pragma unroll
            for (int k = 0; k < 4; k++) {
                float2 d = *(const float2*)(dqs + q * 256 + lane * 8 + k * 2);
                float2 f1 = __bfloat1622float2(h1[k]);
                float2 f2 = __bfloat1622float2(h2[k]);
                a1 = fmaf(f1.x, d.x, a1); a2 = fmaf(f1.y, d.y, a2);
                a3 = fmaf(f2.x, d.x, a3); a4 = fmaf(f2.y, d.y, a4);
            }
        }
        float s1 = a1 + a2, s2 = a3 + a4;
#pragma unroll
        for (int off = 16; off; off >>= 1) {
            s1 += __shfl_xor_sync(0xffffffffu, s1, off);
            s2 += __shfl_xor_sync(0xffffffffu, s2, off);
        }
        if (lane == 0) {
            int t = t0 + bs;
            ws[bs]     = (t < hl)     ? 2.f * s1 : NEGBIG;
            ws[bs + 1] = (t + 1 < hl) ? 2.f * s2 : NEGBIG;
        }
    }
    __syncthreads();

    float lm = NEGBIG;
    for (int i = tid; i < tlen; i += 256) lm = fmaxf(lm, ws[i]);
    red[tid] = lm; __syncthreads();
    for (int st = 128; st; st >>= 1) { if (tid < st) red[tid] = fmaxf(red[tid], red[tid + st]); __syncthreads(); }
    const float m = red[0]; __syncthreads();
    float ls = 0.f;
    for (int i = tid; i < tlen; i += 256) { float w = expf(ws[i] - m); ws[i] = w; ls += w; }
    red[tid] = ls; __syncthreads();
    for (int st = 128; st; st >>= 1) { if (tid < st) red[tid] += red[tid + st]; __syncthreads(); }
    const float sl = red[0];
    __syncthreads();

    float pacc[32];
#pragma unroll
    for (int i = 0; i < 32; i++) pacc[i] = 0.f;
    for (int bs = wid * 2; bs < tlen; bs += 16) {
        float w1 = ws[bs], w2 = ws[bs + 1];
        const __nv_bfloat16* r1 = g_hsb + ((long long)b * 400 + t0 + bs) * 1024 + lane * 8;
        const __nv_bfloat16* r2 = r1 + 1024;
#pragma unroll
        for (int q = 0; q < 4; q++) {
            uint4 v1 = *(const uint4*)(r1 + q * 256);
            uint4 v2 = *(const uint4*)(r2 + q * 256);
            const __nv_bfloat162* h1 = (const __nv_bfloat162*)&v1;
            const __nv_bfloat162* h2 = (const __nv_bfloat162*)&v2;
#pragma unroll
            for (int k = 0; k < 4; k++) {
                float2 f1 = __bfloat1622float2(h1[k]);
                float2 f2 = __bfloat1622float2(h2[k]);
                int o = q * 8 + k * 2;
                pacc[o]     = fmaf(w1, f1.x, fmaf(w2, f2.x, pacc[o]));
                pacc[o + 1] = fmaf(w1, f1.y, fmaf(w2, f2.y, pacc[o + 1]));
            }
        }
    }
#pragma unroll
    for (int q = 0; q < 4; q++)
#pragma unroll
        for (int j = 0; j < 8; j++)
            pcr[wid * 1024 + q * 256 + lane * 8 + j] = pacc[q * 8 + j];
    __syncthreads();
    for (int col = tid; col < 1024; col += 256) {
        float a = 0.f;
#pragma unroll
        for (int w = 0; w < 8; w++) a += pcr[w * 1024 + col];
        g_pc[bid * 1024 + col] = a;
    }
    if (tid == 0) { g_ms[bid * 2] = m; g_ms[bid * 2 + 1] = sl; }
    __syncthreads();

    if (tid == 0) {
        __threadfence();
        unsigned old = atomicAdd(&g_cmb[b], 1u);
        *flg = (old == (unsigned)(s * ncs + ncs - 1)) ? 1 : 0;
    }
    __syncthreads();
    if (*flg) {
        float mi[5], si[5];
        for (int i = 0; i < ncs; i++) {
            mi[i] = __ldcg(&g_ms[(base + i) * 2]);
            si[i] = __ldcg(&g_ms[(base + i) * 2 + 1]);
        }
        float M = NEGBIG;
        for (int i = 0; i < ncs; i++) M = fmaxf(M, mi[i]);
        float sc[5], Ssum = 0.f;
        for (int i = 0; i < ncs; i++) { sc[i] = expf(mi[i] - M); Ssum += sc[i] * si[i]; }
        float inv = 1.f / Ssum;
        for (int col = tid; col < 1024; col += 256) {
            float a = 0.f;
            for (int i = 0; i < ncs; i++) a += sc[i] * __ldcg(&g_pc[(base + i) * 1024 + col]);
            __nv_bfloat16 v = __float2bfloat16(a * inv);
            g_attb[b * 1024 + col] = v;
            g_zallb[((long long)s * 32 + b) * 2048 + 1024 + col] = v;
        }
    }
    __syncthreads();
}

// ---------------------------------------------------------------- main loop
__global__ void __launch_bounds__(256, 1) k_loop(const int* __restrict__ hlens,
                                                 const float* __restrict__ bdec) {
    extern __shared__ char sm[];
    const int bid = blockIdx.x;
    int ep = 0;

    for (int s = 0; s <= 101; s++) {
        const int p = s & 1;
        if (bid < 128) {
            if (s >= 1)
                gtile<2, 1, 4, true, false>(sm, bid * 32, 2048, g_Wc1r, g_bs1r,
                                            g_z0s[p], g_z1s[1 - p],
                                            nullptr, g_c1, g_z1s[p], g_zallb, s - 1, nullptr);
        } else if (bid < 144) {
            if (s <= 100)
                gtile<0, 0, 8, false, false>(sm, (bid - 128) * 64, 1024, g_Wdecb, bdec,
                                             g_z0s[p], nullptr,
                                             g_dqb, nullptr, nullptr, nullptr, s, nullptr);
        }
        gbar(ep); ep++;
        if (s == 101) break;

        phase_epc(sm, s, hlens);
        gbar(ep); ep++;

        if (bid < 128) {
            gtile<2, 1, 4, false, true>(sm, bid * 32, 2048, g_Wc0x, nullptr,
                                        g_attb, g_z0s[p],
                                        nullptr, g_c0, g_z0s[1 - p], nullptr, s,
                                        g_emb0 + (long long)s * 32 * 4096);
        }
        gbar(ep); ep++;
    }
}

// ---------------------------------------------------------------- CE
__global__ void k_ce(const void* __restrict__ ys) {
    int r = blockIdx.x;
    int l = r / BB, b = r % BB;
    const float* y = g_yall + (long long)r * VV;
    __shared__ float red[256];
    int tid = threadIdx.x;
    float lm = NEGBIG;
    for (int v = tid; v < VV; v += 256) lm = fmaxf(lm, y[v]);
    red[tid] = lm; __syncthreads();
    for (int s = 128; s > 0; s >>= 1) { if (tid < s) red[tid] = fmaxf(red[tid], red[tid + s]); __syncthreads(); }
    float m = red[0]; __syncthreads();
    float ls = 0.f;
    for (int v = tid; v < VV; v += 256) ls += expf(y[v] - m);
    red[tid] = ls; __syncthreads();
    for (int s = 128; s > 0; s >>= 1) { if (tid < s) red[tid] += red[tid + s]; __syncthreads(); }
    if (tid == 0) {
        int tgt = (l < LL) ? read_ys(ys, b * LL + l) : 4999;
        atomicAdd(&g_loss, logf(red[0]) + m - y[tgt]);
    }
}

__global__ void k_fin(float* out) {
    out[0] = g_loss * ((float)LL / (float)(L1 * BB));
}

// ---------------------------------------------------------------- launch
extern "C" void kernel_launch(void* const* d_in, const int* in_sizes, int n_in,
                              void* d_out, int out_size) {
    const float* hs    = (const float*)d_in[0];
    const float* embed = (const float*)d_in[1];
    const float* Wenc  = (const float*)d_in[2];
    const float* benc  = (const float*)d_in[3];
    const float* Wdec  = (const float*)d_in[4];
    const float* bdec  = (const float*)d_in[5];
    const float* Wih0  = (const float*)d_in[6];
    const float* Whh0  = (const float*)d_in[7];
    const float* bih0  = (const float*)d_in[8];
    const float* bhh0  = (const float*)d_in[9];
    const float* Wih1  = (const float*)d_in[10];
    const float* Whh1  = (const float*)d_in[11];
    const float* bih1  = (const float*)d_in[12];
    const float* bhh1  = (const float*)d_in[13];
    const float* Wout  = (const float*)d_in[14];
    const float* bout  = (const float*)d_in[15];
    const int*   hlens = (const int*)d_in[16];
    const void*  ys    = (const void*)d_in[17];

    __nv_bfloat16 *hsb, *preb, *eysb, *Wencb, *Woutb, *Wc0e, *zallb;
    float *yall, *bs0r, *emb0;
    cudaGetSymbolAddress((void**)&hsb,   g_hsb);
    cudaGetSymbolAddress((void**)&preb,  g_preb);
    cudaGetSymbolAddress((void**)&eysb,  g_eysb);
    cudaGetSymbolAddress((void**)&Wencb, g_Wencb);
    cudaGetSymbolAddress((void**)&Woutb, g_Woutb);
    cudaGetSymbolAddress((void**)&Wc0e,  g_Wc0e);
    cudaGetSymbolAddress((void**)&zallb, g_zallb);
    cudaGetSymbolAddress((void**)&yall,  g_yall);
    cudaGetSymbolAddress((void**)&bs0r,  g_bs0r);
    cudaGetSymbolAddress((void**)&emb0,  g_emb0);

    static int smem_set = 0;
    if (!smem_set) {
        cudaFuncSetAttribute(k_loop, cudaFuncAttributeMaxDynamicSharedMemorySize, SMSZ);
        cudaFuncSetAttribute(mma_big<0>, cudaFuncAttributeMaxDynamicSharedMemorySize, BIG_SMEM);
        cudaFuncSetAttribute(mma_big<1>, cudaFuncAttributeMaxDynamicSharedMemorySize, BIG_SMEM);
        smem_set = 1;
    }

    // 1: fused prologue
    k_prep_all<<<296, 256>>>(hs, embed, Wenc, Wdec, Wout,
                             Wih0, Whh0, Wih1, Whh1,
                             bih0, bhh0, bih1, bhh1, ys);

    // 2: g_emb0 = eysb @ Wc0e^T + bs0r
    mma_big<0><<<dim3(4096 / 128, (L1 * BB + 127) / 128), 256, BIG_SMEM>>>(
        eysb, Wc0e, bs0r, emb0, nullptr, L1 * BB, 4096, 1024);

    // 3: pre_enc = tanh(hs @ Wenc^T + benc) -> bf16
    mma_big<1><<<dim3(DD / 128, BB * TT / 128), 256, BIG_SMEM>>>(
        hsb, Wencb, benc, nullptr, preb, BB * TT, DD, DD);

    // 4: persistent recurrent loop
    k_loop<<<NBLK, 256, SMSZ>>>(hlens, bdec);

    // 5: y_all = zall @ Wout^T + bout
    mma_big<0><<<dim3((VV + 127) / 128, (L1 * BB + 127) / 128), 256, BIG_SMEM>>>(
        zallb, Woutb, bout, yall, nullptr, L1 * BB, VV, 2048);

    // 6-7: CE + finalize
    k_ce<<<L1 * BB, 256>>>(ys);
    k_fin<<<1, 1>>>((float*)d_out);
}